// round 9
// baseline (speedup 1.0000x reference)
#include <cuda_runtime.h>
#include <cuda_bf16.h>
#include <math.h>
#include <cstdint>

// Problem dims (fixed by the dataset)
#define BB 8
#define SS 1024
#define DD 1024
#define FF 4096
#define MTOK (BB*SS)       // 8192
#define CMOD_N (6*DD)      // 6144

#define QSCALE 0.022542110013890053f   // log2(e) / 64

// -------- scratch (device globals; no allocation allowed) --------
__device__ float g_x1 [MTOK * DD];

__device__ __nv_bfloat16 g_qb  [MTOK * DD];
__device__ __nv_bfloat16 g_kb  [MTOK * DD];
__device__ __nv_bfloat16 g_vb  [MTOK * DD];
__device__ __nv_bfloat16 g_xmod_b[MTOK * DD];
__device__ __nv_bfloat16 g_xm2_b [MTOK * DD];
__device__ __nv_bfloat16 g_y_b   [MTOK * DD];
__device__ __nv_bfloat16 g_h_b   [(size_t)MTOK * FF];
__device__ __nv_bfloat16 g_wqkvt[3 * DD * DD];
__device__ __nv_bfloat16 g_wat  [DD * DD];
__device__ __nv_bfloat16 g_wfc1t[(size_t)FF * DD];
__device__ __nv_bfloat16 g_wfc2t[(size_t)DD * FF];

// ===================== PTX helpers (baseline ISA only — no tcgen05) =====================
__device__ __forceinline__ uint32_t smem_u32(const void* p) {
    uint32_t a;
    asm("{ .reg .u64 t; cvta.to.shared.u64 t, %1; cvt.u32.u64 %0, t; }" : "=r"(a) : "l"(p));
    return a;
}
__device__ __forceinline__ void cp_async16(uint32_t dst, const void* src) {
    asm volatile("cp.async.cg.shared.global [%0], [%1], 16;" :: "r"(dst), "l"(src));
}
#define CP_COMMIT() asm volatile("cp.async.commit_group;" ::: "memory")
#define CP_WAIT(n)  asm volatile("cp.async.wait_group %0;" :: "n"(n) : "memory")

__device__ __forceinline__ void ldm4(uint32_t* r, uint32_t addr) {
    asm volatile("ldmatrix.sync.aligned.m8n8.x4.shared.b16 {%0,%1,%2,%3}, [%4];"
        : "=r"(r[0]), "=r"(r[1]), "=r"(r[2]), "=r"(r[3]) : "r"(addr));
}
__device__ __forceinline__ void ldm4t(uint32_t* r, uint32_t addr) {
    asm volatile("ldmatrix.sync.aligned.m8n8.x4.trans.shared.b16 {%0,%1,%2,%3}, [%4];"
        : "=r"(r[0]), "=r"(r[1]), "=r"(r[2]), "=r"(r[3]) : "r"(addr));
}
__device__ __forceinline__ void mma16816(float* c, const uint32_t* a, const uint32_t* b) {
    asm volatile(
        "mma.sync.aligned.m16n8k16.row.col.f32.bf16.bf16.f32 "
        "{%0,%1,%2,%3}, {%4,%5,%6,%7}, {%8,%9}, {%0,%1,%2,%3};"
        : "+f"(c[0]), "+f"(c[1]), "+f"(c[2]), "+f"(c[3])
        : "r"(a[0]), "r"(a[1]), "r"(a[2]), "r"(a[3]), "r"(b[0]), "r"(b[1]));
}
__device__ __forceinline__ uint32_t pack_bf16x2(float lo, float hi) {
    uint32_t r;
    asm("cvt.rn.bf16x2.f32 %0, %1, %2;" : "=r"(r) : "f"(hi), "f"(lo));  // first operand -> upper half
    return r;
}
__device__ __forceinline__ float fast_exp2(float x) {
    float r;
    asm("ex2.approx.ftz.f32 %0, %1;" : "=f"(r) : "f"(x));
    return r;
}
__device__ __forceinline__ void stcs_f2(float* p, float2 v) {
    asm volatile("st.global.cs.v2.f32 [%0], {%1, %2};" :: "l"(p), "f"(v.x), "f"(v.y));
}
__device__ __forceinline__ void stcs_f4(float* p, float4 v) {
    asm volatile("st.global.cs.v4.f32 [%0], {%1, %2, %3, %4};"
        :: "l"(p), "f"(v.x), "f"(v.y), "f"(v.z), "f"(v.w));
}

// ===================== mma.sync GEMM: C[M x N] = A[M x K](bf16) @ Wt[N x K]^T =====================
// BM=128, BN=128. 128 threads: 2x2 warps, warp tile 64x64 (fragment traffic 16KB/ks vs 24
// for the 8-warp 32x64 layout -> smem crossbar no longer co-critical with tensor).
// 6-stage cp.async (3 pairs of BK=32 chunks); one barrier per 64 K-elems.
enum { EPI_QKV3 = 0, EPI_GATE = 1, EPI_GELU = 2 };

#define CHUNK_BYTES 16384       // A 8KB + B 8KB per BK=32 chunk
#define PAIR_BYTES  32768
#define B_OFF 8192
#define GEMM_SMEM (3 * PAIR_BYTES)   // 96 KB

template <int EPI>
__global__ void __launch_bounds__(128) mma_gemm(
    const __nv_bfloat16* __restrict__ A, const __nv_bfloat16* __restrict__ Wt,
    const float* __restrict__ bias,
    float* __restrict__ outf, __nv_bfloat16* __restrict__ outb,
    int K, int N, float scale,
    const float* __restrict__ add_src, const float* __restrict__ cmod, int gate_off,
    __nv_bfloat16* __restrict__ outb2, __nv_bfloat16* __restrict__ outb3,
    const float* __restrict__ bias2, const float* __restrict__ bias3)
{
    extern __shared__ __align__(128) char smbuf[];   // 96 KB
    const uint32_t smb = smem_u32(smbuf);

    const int tid = threadIdx.x;
    const int lane = tid & 31, wid = tid >> 5;
    const int wm = wid & 1, wn = wid >> 1;      // 2 warps M x 2 warps N
    const int m0 = blockIdx.y * 128;
    const int n0 = blockIdx.x * 128;

    // loads: 512 16B units per operand per chunk, 4 per thread
    uint32_t ud[4];
    const __nv_bfloat16* srcA[4];
    const __nv_bfloat16* srcB[4];
    #pragma unroll
    for (int i = 0; i < 4; i++) {
        int u = tid + i * 128;
        int r = u >> 2, g = u & 3;
        ud[i] = (uint32_t)r * 64u + (uint32_t)((g ^ ((r >> 1) & 3)) << 4);
        srcA[i] = A + (size_t)(m0 + r) * K + g * 8;
        srcB[i] = Wt + (size_t)(n0 + r) * K + g * 8;
    }

    const int npair = K >> 6;   // K / 64

    uint32_t aoff[4][2];
    #pragma unroll
    for (int mt = 0; mt < 4; mt++) {
        int r = wm * 64 + mt * 16 + (lane & 15);
        int sw = (r >> 1) & 3;
        #pragma unroll
        for (int ks = 0; ks < 2; ks++)
            aoff[mt][ks] = (uint32_t)r * 64u +
                           (uint32_t)(((ks * 2 + (lane >> 4)) ^ sw) << 4);
    }
    uint32_t boff[4][2];
    {
        int n = wn * 64 + ((lane >> 4) & 1) * 8 + (lane & 7);
        int gpar = (lane >> 3) & 1;
        #pragma unroll
        for (int np = 0; np < 4; np++) {
            int nn = n + np * 16;
            int sw = (nn >> 1) & 3;
            #pragma unroll
            for (int ks = 0; ks < 2; ks++)
                boff[np][ks] = (uint32_t)B_OFF + (uint32_t)nn * 64u +
                               (uint32_t)(((ks * 2 + gpar) ^ sw) << 4);
        }
    }

    // prologue: pairs 0,1 (chunks 0..3), one commit group per pair
    #pragma unroll
    for (int s = 0; s < 2; s++) {
        uint32_t base = smb + (uint32_t)s * PAIR_BYTES;
        #pragma unroll
        for (int h = 0; h < 2; h++) {
            uint32_t cb = base + (uint32_t)h * CHUNK_BYTES;
            int ch = 2 * s + h;
            #pragma unroll
            for (int i = 0; i < 4; i++) {
                cp_async16(cb + ud[i],         srcA[i] + ch * 32);
                cp_async16(cb + B_OFF + ud[i], srcB[i] + ch * 32);
            }
        }
        CP_COMMIT();
    }

    float c[4][8][4];
    #pragma unroll
    for (int mt = 0; mt < 4; mt++)
        #pragma unroll
        for (int nt = 0; nt < 8; nt++)
            #pragma unroll
            for (int e = 0; e < 4; e++) c[mt][nt][e] = 0.f;

    for (int p = 0; p < npair; p++) {
        CP_WAIT(1);
        __syncthreads();
        if (p + 2 < npair) {
            uint32_t base = smb + (uint32_t)((p + 2) % 3) * PAIR_BYTES;
            #pragma unroll
            for (int h = 0; h < 2; h++) {
                uint32_t cb = base + (uint32_t)h * CHUNK_BYTES;
                int ch = 2 * (p + 2) + h;
                #pragma unroll
                for (int i = 0; i < 4; i++) {
                    cp_async16(cb + ud[i],         srcA[i] + ch * 32);
                    cp_async16(cb + B_OFF + ud[i], srcB[i] + ch * 32);
                }
            }
        }
        CP_COMMIT();

        const uint32_t sp = smb + (uint32_t)(p % 3) * PAIR_BYTES;
        #pragma unroll
        for (int h = 0; h < 2; h++) {
            const uint32_t st = sp + (uint32_t)h * CHUNK_BYTES;
            #pragma unroll
            for (int ks = 0; ks < 2; ks++) {
                uint32_t a[4][4];
                #pragma unroll
                for (int mt = 0; mt < 4; mt++)
                    ldm4(a[mt], st + aoff[mt][ks]);
                uint32_t b[8][2];
                #pragma unroll
                for (int np = 0; np < 4; np++) {
                    uint32_t r[4];
                    ldm4(r, st + boff[np][ks]);
                    b[2 * np][0] = r[0]; b[2 * np][1] = r[1];
                    b[2 * np + 1][0] = r[2]; b[2 * np + 1][1] = r[3];
                }
                #pragma unroll
                for (int mt = 0; mt < 4; mt++)
                    #pragma unroll
                    for (int nt = 0; nt < 8; nt++)
                        mma16816(c[mt][nt], a[mt], b[nt]);
            }
        }
    }

    // ---- epilogue ----
    __nv_bfloat16* qdst = nullptr;
    const float* bsel = bias;
    float scl = scale;
    if (EPI == EPI_QKV3) {
        int buf = n0 >> 10;
        qdst = (buf == 0) ? outb : (buf == 1) ? outb2 : outb3;
        bsel = (buf == 0) ? bias : (buf == 1) ? bias2 : bias3;
        scl  = (buf == 0) ? scale : 1.f;
    }
    const int lcol0 = n0 & 1023;

    #pragma unroll
    for (int mt = 0; mt < 4; mt++) {
        #pragma unroll
        for (int half = 0; half < 2; half++) {
            const int grow = m0 + wm * 64 + mt * 16 + (lane >> 2) + half * 8;
            const int b = grow >> 10;
            #pragma unroll
            for (int nt = 0; nt < 8; nt++) {
                const int coff = wn * 64 + nt * 8 + (lane & 3) * 2;
                if (EPI == EPI_QKV3) {
                    const int lcol = lcol0 + coff;
                    float v0 = (c[mt][nt][half * 2 + 0] + bsel[lcol]) * scl;
                    float v1 = (c[mt][nt][half * 2 + 1] + bsel[lcol + 1]) * scl;
                    __nv_bfloat162 pr;
                    pr.x = __float2bfloat16(v0);
                    pr.y = __float2bfloat16(v1);
                    *(__nv_bfloat162*)&qdst[(size_t)grow * DD + lcol] = pr;
                } else if (EPI == EPI_GATE) {
                    const int gcol = n0 + coff;
                    float v0 = c[mt][nt][half * 2 + 0] + bias[gcol];
                    float v1 = c[mt][nt][half * 2 + 1] + bias[gcol + 1];
                    const float* gp = cmod + b * CMOD_N + gate_off + gcol;
                    const float* ap = add_src + (size_t)grow * N + gcol;
                    float2 o = { ap[0] + gp[0] * v0, ap[1] + gp[1] * v1 };
                    if (gate_off == 5120)   // final x_out: write-only -> streaming store
                        stcs_f2(&outf[(size_t)grow * N + gcol], o);
                    else
                        *(float2*)&outf[(size_t)grow * N + gcol] = o;
                } else {   // EPI_GELU -> bf16
                    const int gcol = n0 + coff;
                    float v0 = c[mt][nt][half * 2 + 0] + bias[gcol];
                    float v1 = c[mt][nt][half * 2 + 1] + bias[gcol + 1];
                    float g0 = 0.5f * v0 * (1.f + erff(v0 * 0.70710678118654752f));
                    float g1 = 0.5f * v1 * (1.f + erff(v1 * 0.70710678118654752f));
                    __nv_bfloat162 pr;
                    pr.x = __float2bfloat16(g0);
                    pr.y = __float2bfloat16(g1);
                    *(__nv_bfloat162*)&outb[(size_t)grow * N + gcol] = pr;
                }
            }
        }
    }
}

// ===================== Flash attention on mma.sync (bf16 in/out, fixed-base exp2 softmax) =====================
// Br=64, Bc=64, Dh=64. 64 threads = 2 warps, each owning 32 q-rows: K/V fragments are
// loaded ONCE per warp and reused for both 16-row blocks (halves smem crossbar traffic).
// Fixed-base softmax (scores O(0.5) by construction), l-reduction deferred to epilogue.
__global__ void __launch_bounds__(64) flash_mma(
    const __nv_bfloat16* __restrict__ Q, const __nv_bfloat16* __restrict__ K,
    const __nv_bfloat16* __restrict__ V, __nv_bfloat16* __restrict__ Y)
{
    extern __shared__ __align__(128) char smbuf[];   // Q 8KB + 3 x (K 8KB + V 8KB) = 56KB
    const uint32_t Qb  = smem_u32(smbuf);
    const uint32_t KVb = Qb + 8192;

    const int tid = threadIdx.x, lane = tid & 31, w = tid >> 5;
    const int qt = blockIdx.x, h = blockIdx.y, b = blockIdx.z;
    const size_t gbase = ((size_t)b * SS) * DD + h * 64;
    const int t0q = qt * 64;

    // --- Q load (8KB = 512 x 16B units, 8/thread) ---
    #pragma unroll
    for (int i = 0; i < 8; i++) {
        int u = tid + i * 64;
        int r = u >> 3, g = u & 7;
        cp_async16(Qb + r * 128 + ((g ^ (r & 7)) << 4),
                   Q + gbase + (size_t)(t0q + r) * DD + g * 8);
    }
    // --- KV tile loader: per operand 512 units, 8/thread ---
    int kvr[8], kvg[8];
    uint32_t kvd[8];
    #pragma unroll
    for (int i = 0; i < 8; i++) {
        int u = tid + i * 64;
        kvr[i] = u >> 3; kvg[i] = u & 7;
        kvd[i] = (uint32_t)kvr[i] * 128u + (uint32_t)((kvg[i] ^ (kvr[i] & 7)) << 4);
    }

    #pragma unroll
    for (int s = 0; s < 2; s++) {   // tiles 0,1 -> stages 0,1 (tile 0 shares group with Q)
        uint32_t base = KVb + (uint32_t)s * 16384u;
        #pragma unroll
        for (int i = 0; i < 8; i++) {
            cp_async16(base + kvd[i],        K + gbase + (size_t)(s * 64 + kvr[i]) * DD + kvg[i] * 8);
            cp_async16(base + 8192 + kvd[i], V + gbase + (size_t)(s * 64 + kvr[i]) * DD + kvg[i] * 8);
        }
        CP_COMMIT();
    }

    uint32_t qa[2][4][4];
    float O[2][8][4];
    #pragma unroll
    for (int mq = 0; mq < 2; mq++)
        #pragma unroll
        for (int nb = 0; nb < 8; nb++)
            #pragma unroll
            for (int e = 0; e < 4; e++) O[mq][nb][e] = 0.f;
    float lp[2][2] = { {0.f, 0.f}, {0.f, 0.f} };

    for (int t = 0; t < 16; t++) {
        CP_WAIT(1);
        __syncthreads();   // data visibility for tile t AND orders compute(t-1) before prefetch below
        if (t + 2 < 16) {
            uint32_t base = KVb + (uint32_t)((t + 2) % 3) * 16384u;
            const int t0k = (t + 2) * 64;
            #pragma unroll
            for (int i = 0; i < 8; i++) {
                cp_async16(base + kvd[i],        K + gbase + (size_t)(t0k + kvr[i]) * DD + kvg[i] * 8);
                cp_async16(base + 8192 + kvd[i], V + gbase + (size_t)(t0k + kvr[i]) * DD + kvg[i] * 8);
            }
        }
        CP_COMMIT();

        if (t == 0) {
            #pragma unroll
            for (int mq = 0; mq < 2; mq++)
                #pragma unroll
                for (int kc = 0; kc < 4; kc++) {
                    int r = w * 32 + mq * 16 + (lane & 15);
                    int g = (kc * 2 + (lane >> 4)) ^ (r & 7);
                    ldm4(qa[mq][kc], Qb + r * 128 + (g << 4));
                }
        }
        const uint32_t Kb = KVb + (uint32_t)(t % 3) * 16384u;
        const uint32_t Vb = Kb + 8192u;

        // ---- S = Q @ K^T (K fragments shared across both q-row blocks) ----
        float sc[2][8][4];
        #pragma unroll
        for (int mq = 0; mq < 2; mq++)
            #pragma unroll
            for (int nb = 0; nb < 8; nb++)
                #pragma unroll
                for (int e = 0; e < 4; e++) sc[mq][nb][e] = 0.f;
        #pragma unroll
        for (int kc = 0; kc < 4; kc++) {
            #pragma unroll
            for (int ng = 0; ng < 4; ng++) {
                int n = ng * 16 + ((lane >> 4) & 1) * 8 + (lane & 7);
                int g = (kc * 2 + ((lane >> 3) & 1)) ^ (n & 7);
                uint32_t kb[4];
                ldm4(kb, Kb + n * 128 + (g << 4));
                #pragma unroll
                for (int mq = 0; mq < 2; mq++) {
                    mma16816(sc[mq][2 * ng],     qa[mq][kc], &kb[0]);
                    mma16816(sc[mq][2 * ng + 1], qa[mq][kc], &kb[2]);
                }
            }
        }

        // ---- fixed-base softmax: P = exp2(S), partial row sums only ----
        uint32_t pa[2][4][4];
        #pragma unroll
        for (int mq = 0; mq < 2; mq++)
            #pragma unroll
            for (int ng = 0; ng < 4; ng++) {
                float e00 = fast_exp2(sc[mq][2 * ng][0]),     e01 = fast_exp2(sc[mq][2 * ng][1]);
                float e02 = fast_exp2(sc[mq][2 * ng][2]),     e03 = fast_exp2(sc[mq][2 * ng][3]);
                float e10 = fast_exp2(sc[mq][2 * ng + 1][0]), e11 = fast_exp2(sc[mq][2 * ng + 1][1]);
                float e12 = fast_exp2(sc[mq][2 * ng + 1][2]), e13 = fast_exp2(sc[mq][2 * ng + 1][3]);
                lp[mq][0] += e00 + e01 + e10 + e11;
                lp[mq][1] += e02 + e03 + e12 + e13;
                pa[mq][ng][0] = pack_bf16x2(e00, e01);
                pa[mq][ng][1] = pack_bf16x2(e02, e03);
                pa[mq][ng][2] = pack_bf16x2(e10, e11);
                pa[mq][ng][3] = pack_bf16x2(e12, e13);
            }

        // ---- O += P @ V (V fragments shared across both q-row blocks) ----
        #pragma unroll
        for (int kc = 0; kc < 4; kc++) {
            #pragma unroll
            for (int ng = 0; ng < 4; ng++) {
                int r = kc * 16 + (lane & 15);
                int g = (ng * 2 + (lane >> 4)) ^ (r & 7);
                uint32_t vb[4];
                ldm4t(vb, Vb + r * 128 + (g << 4));
                #pragma unroll
                for (int mq = 0; mq < 2; mq++) {
                    mma16816(O[mq][2 * ng],     pa[mq][kc], &vb[0]);
                    mma16816(O[mq][2 * ng + 1], pa[mq][kc], &vb[2]);
                }
            }
        }
        // no trailing barrier: next iteration's top barrier orders compute(t) vs prefetch(t+3)
    }

    // ---- single end-of-loop l reduction + store ----
    #pragma unroll
    for (int mq = 0; mq < 2; mq++) {
        float l0 = lp[mq][0], l1 = lp[mq][1];
        l0 += __shfl_xor_sync(0xffffffffu, l0, 1);
        l0 += __shfl_xor_sync(0xffffffffu, l0, 2);
        l1 += __shfl_xor_sync(0xffffffffu, l1, 1);
        l1 += __shfl_xor_sync(0xffffffffu, l1, 2);
        float inv0 = 1.f / l0, inv1 = 1.f / l1;
        const int r0 = t0q + w * 32 + mq * 16 + (lane >> 2);
        #pragma unroll
        for (int nb = 0; nb < 8; nb++) {
            const int d = nb * 8 + (lane & 3) * 2;
            __nv_bfloat162 p0, p1;
            p0.x = __float2bfloat16(O[mq][nb][0] * inv0);
            p0.y = __float2bfloat16(O[mq][nb][1] * inv0);
            p1.x = __float2bfloat16(O[mq][nb][2] * inv1);
            p1.y = __float2bfloat16(O[mq][nb][3] * inv1);
            *(__nv_bfloat162*)&Y[gbase + (size_t)r0 * DD + d]       = p0;
            *(__nv_bfloat162*)&Y[gbase + (size_t)(r0 + 8) * DD + d] = p1;
        }
    }
}

// ---------------- merged transpose + fp32->bf16 of all weights ----------------
// tiles: [0,3072) qkv | [3072,4096) w_attn | [4096,8192) fc1 | [8192,12288) fc2
__global__ void __launch_bounds__(256) transpose_all(
    const float* __restrict__ wq, const float* __restrict__ wk, const float* __restrict__ wv,
    const float* __restrict__ wattn, const float* __restrict__ wfc1, const float* __restrict__ wfc2,
    __nv_bfloat16* __restrict__ qkvt, __nv_bfloat16* __restrict__ wat,
    __nv_bfloat16* __restrict__ f1t, __nv_bfloat16* __restrict__ f2t)
{
    __shared__ float t[32][33];
    int id = blockIdx.x;
    const float* W; __nv_bfloat16* Wt;
    int n0, k0, Nsrc, Kdst;
    if (id < 3072) {               // qkv: 96 n-tiles x 32 k-tiles
        int tx = id % 96, ty = id / 96;
        n0 = tx * 32; k0 = ty * 32;
        int buf = n0 >> 10;
        W = (buf == 0) ? wq : (buf == 1) ? wk : wv;
        Wt = qkvt;  Nsrc = DD; Kdst = DD;
        int nl0 = n0 & 1023;
        int txi = threadIdx.x & 31, tyi = threadIdx.x >> 5;
        #pragma unroll
        for (int r = tyi; r < 32; r += 8)
            t[r][txi] = W[(size_t)(k0 + r) * Nsrc + nl0 + txi];
        __syncthreads();
        #pragma unroll
        for (int r = tyi; r < 32; r += 8)
            Wt[(size_t)(n0 + r) * Kdst + k0 + txi] = __float2bfloat16(t[txi][r]);
        return;
    } else if (id < 4096) {        // w_attn: 32 x 32
        int lid2 = id - 3072;
        n0 = (lid2 % 32) * 32; k0 = (lid2 / 32) * 32;
        W = wattn; Wt = wat; Nsrc = DD; Kdst = DD;
    } else if (id < 8192) {        // fc1: [K=1024, N=4096] -> f1t[4096,1024]: 128 x 32
        int lid2 = id - 4096;
        n0 = (lid2 % 128) * 32; k0 = (lid2 / 128) * 32;
        W = wfc1; Wt = f1t; Nsrc = FF; Kdst = DD;
    } else {                       // fc2: [K=4096, N=1024] -> f2t[1024,4096]: 32 x 128
        int lid2 = id - 8192;
        n0 = (lid2 % 32) * 32; k0 = (lid2 / 32) * 32;
        W = wfc2; Wt = f2t; Nsrc = DD; Kdst = FF;
    }
    int txi = threadIdx.x & 31, tyi = threadIdx.x >> 5;
    #pragma unroll
    for (int r = tyi; r < 32; r += 8)
        t[r][txi] = W[(size_t)(k0 + r) * Nsrc + n0 + txi];
    __syncthreads();
    #pragma unroll
    for (int r = tyi; r < 32; r += 8)
        Wt[(size_t)(n0 + r) * Kdst + k0 + txi] = __float2bfloat16(t[txi][r]);
}

// ---------------- cmod = silu(c) @ w_mod + b_mod (fp32; silu fused; 192 CTAs) ----------------
__global__ void __launch_bounds__(256) mod_gemm2(
    const float* __restrict__ c, const float* __restrict__ w_mod,
    const float* __restrict__ b_mod, float* __restrict__ cmod,
    float* __restrict__ o_shift, float* __restrict__ o_scale, float* __restrict__ o_cact)
{
    __shared__ float sc[BB * DD];        // 32 KB
    __shared__ float red[8][32][8];      // 8 KB  [ks][jl][b]
    int tid = threadIdx.x;
    for (int i = tid; i < BB * DD; i += 256) {
        float v = c[i];
        float sv = v / (1.f + expf(-v));
        sc[i] = sv;
        if (blockIdx.x == 0) o_cact[i] = sv;
    }
    __syncthreads();

    int jl = tid & 31, ks = tid >> 5;
    int j = blockIdx.x * 32 + jl;
    float acc[BB];
    #pragma unroll
    for (int b = 0; b < BB; b++) acc[b] = 0.f;

    int d0 = ks * 128;
    #pragma unroll 4
    for (int dd = 0; dd < 128; dd++) {
        int d = d0 + dd;
        float w = w_mod[(size_t)d * CMOD_N + j];
        #pragma unroll
        for (int b = 0; b < BB; b++) acc[b] = fmaf(sc[b * DD + d], w, acc[b]);
    }
    #pragma unroll
    for (int b = 0; b < BB; b++) red[ks][jl][b] = acc[b];
    __syncthreads();

    int b = ks;
    float s = 0.f;
    #pragma unroll
    for (int kk = 0; kk < 8; kk++) s += red[kk][jl][b];
    float v = s + b_mod[j];
    cmod[b * CMOD_N + j] = v;
    if (j < 1024)            o_shift[b * DD + j] = v;
    else if (j < 2048)       o_scale[b * DD + (j - 1024)] = v;
}

// ---------------- LayerNorm + modulate (warp-per-row; no block barriers, no smem) ----------------
__global__ void __launch_bounds__(256) ln_mod_kernel(
    const float* __restrict__ x, const float* __restrict__ cmod,
    float* __restrict__ xnorm, float* __restrict__ xmod, __nv_bfloat16* __restrict__ xmod_b,
    int shift_off, int scale_off)
{
    const int row = blockIdx.x * 8 + (threadIdx.x >> 5);
    const int lane = threadIdx.x & 31;
    const int b = row >> 10;
    const float4* xr = (const float4*)(x + (size_t)row * DD);

    float4 v[8];
    float s = 0.f;
    #pragma unroll
    for (int i = 0; i < 8; i++) {
        v[i] = xr[lane + i * 32];
        s += v[i].x + v[i].y + v[i].z + v[i].w;
    }
    #pragma unroll
    for (int o = 16; o > 0; o >>= 1) s += __shfl_xor_sync(0xffffffffu, s, o);
    const float mu = s * (1.f / DD);

    float s2 = 0.f;
    #pragma unroll
    for (int i = 0; i < 8; i++) {
        float d0 = v[i].x - mu, d1 = v[i].y - mu, d2 = v[i].z - mu, d3 = v[i].w - mu;
        s2 += d0 * d0 + d1 * d1 + d2 * d2 + d3 * d3;
    }
    #pragma unroll
    for (int o = 16; o > 0; o >>= 1) s2 += __shfl_xor_sync(0xffffffffu, s2, o);
    const float rstd = rsqrtf(s2 * (1.f / DD) + 1e-6f);

    const float4* shp = (const float4*)(cmod + b * CMOD_N + shift_off);
    const float4* slp = (const float4*)(cmod + b * CMOD_N + scale_off);
    #pragma unroll
    for (int i = 0; i < 8; i++) {
        const int idx = lane + i * 32;
        const float4 sh = shp[idx], sl = slp[idx];
        float4 xn = { (v[i].x - mu) * rstd, (v[i].y - mu) * rstd,
                      (v[i].z - mu) * rstd, (v[i].w - mu) * rstd };
        float4 xm = { xn.x * (1.f + sl.x) + sh.x, xn.y * (1.f + sl.y) + sh.y,
                      xn.z * (1.f + sl.z) + sh.z, xn.w * (1.f + sl.w) + sh.w };
        if (xnorm) stcs_f4(xnorm + (size_t)row * DD + idx * 4, xn);
        if (xmod)  stcs_f4(xmod  + (size_t)row * DD + idx * 4, xm);
        uint2 p = { pack_bf16x2(xm.x, xm.y), pack_bf16x2(xm.z, xm.w) };
        ((uint2*)(xmod_b + (size_t)row * DD))[idx] = p;
    }
}

// ---------------- launch ----------------
extern "C" void kernel_launch(void* const* d_in, const int* in_sizes, int n_in,
                              void* d_out, int out_size)
{
    const float* x      = (const float*)d_in[0];
    const float* c      = (const float*)d_in[1];
    const float* w_mod  = (const float*)d_in[2];
    const float* b_mod  = (const float*)d_in[3];
    const float* w_q    = (const float*)d_in[4];
    const float* b_q    = (const float*)d_in[5];
    const float* w_k    = (const float*)d_in[6];
    const float* b_k    = (const float*)d_in[7];
    const float* w_v    = (const float*)d_in[8];
    const float* b_v    = (const float*)d_in[9];
    const float* w_attn = (const float*)d_in[10];
    const float* b_attn = (const float*)d_in[11];
    const float* w_fc1  = (const float*)d_in[12];
    const float* b_fc1  = (const float*)d_in[13];
    const float* w_fc2  = (const float*)d_in[14];
    const float* b_fc2  = (const float*)d_in[15];

    float* out = (float*)d_out;
    float* o_xout  = out;                    // [8,1024,1024]
    float* o_xnorm = out + 8388608;          // [8,1024,1024]
    float* o_xmod  = out + 16777216;         // [8,1024,1024]
    float* o_shift = out + 25165824;         // [8,1024]
    float* o_scale = out + 25174016;         // [8,1024]
    float* o_cmod  = out + 25182208;         // [8,6144]
    float* o_cact  = out + 25231360;         // [8,1024]

    float *p_x1;
    __nv_bfloat16 *p_qb, *p_kb, *p_vb, *p_xmb, *p_xm2b, *p_yb, *p_hb;
    __nv_bfloat16 *p_wqkvt, *p_wat, *p_f1t, *p_f2t;
    cudaGetSymbolAddress((void**)&p_x1,    g_x1);
    cudaGetSymbolAddress((void**)&p_qb,    g_qb);
    cudaGetSymbolAddress((void**)&p_kb,    g_kb);
    cudaGetSymbolAddress((void**)&p_vb,    g_vb);
    cudaGetSymbolAddress((void**)&p_xmb,   g_xmod_b);
    cudaGetSymbolAddress((void**)&p_xm2b,  g_xm2_b);
    cudaGetSymbolAddress((void**)&p_yb,    g_y_b);
    cudaGetSymbolAddress((void**)&p_hb,    g_h_b);
    cudaGetSymbolAddress((void**)&p_wqkvt, g_wqkvt);
    cudaGetSymbolAddress((void**)&p_wat,   g_wat);
    cudaGetSymbolAddress((void**)&p_f1t,   g_wfc1t);
    cudaGetSymbolAddress((void**)&p_f2t,   g_wfc2t);

    cudaFuncSetAttribute(flash_mma, cudaFuncAttributeMaxDynamicSharedMemorySize, 57344);
    cudaFuncSetAttribute(mma_gemm<EPI_QKV3>, cudaFuncAttributeMaxDynamicSharedMemorySize, GEMM_SMEM);
    cudaFuncSetAttribute(mma_gemm<EPI_GATE>, cudaFuncAttributeMaxDynamicSharedMemorySize, GEMM_SMEM);
    cudaFuncSetAttribute(mma_gemm<EPI_GELU>, cudaFuncAttributeMaxDynamicSharedMemorySize, GEMM_SMEM);

    // 0) all weight transposes in one launch
    transpose_all<<<12288, 256>>>(w_q, w_k, w_v, w_attn, w_fc1, w_fc2,
                                  p_wqkvt, p_wat, p_f1t, p_f2t);

    // 1) conditioning path (fp32, silu fused)
    mod_gemm2<<<CMOD_N / 32, 256>>>(c, w_mod, b_mod, o_cmod, o_shift, o_scale, o_cact);

    // 2) LN1 + modulate
    ln_mod_kernel<<<MTOK / 8, 256>>>(x, o_cmod, o_xnorm, o_xmod, p_xmb, 0, 1024);

    // 3) fused QKV projection -> bf16 (q scaled by log2(e)/64 for exp2 softmax)
    dim3 gQKV(3 * DD / 128, MTOK / 128);   // (24, 64)
    mma_gemm<EPI_QKV3><<<gQKV, 128, GEMM_SMEM>>>(p_xmb, p_wqkvt, b_q, nullptr, p_qb, DD, DD, QSCALE,
                                      nullptr, nullptr, 0, p_kb, p_vb, b_k, b_v);

    // 4) attention on tensor cores (2-warp CTAs, shared K/V fragments)
    flash_mma<<<dim3(SS / 64, 16, BB), 64, 57344>>>(p_qb, p_kb, p_vb, p_yb);

    // 5) attn projection + residual with gate_msa
    dim3 gD(DD / 128, MTOK / 128);     // (8, 64)
    mma_gemm<EPI_GATE><<<gD, 128, GEMM_SMEM>>>(p_yb, p_wat, b_attn, p_x1, nullptr, DD, DD, 1.f,
                                    x, o_cmod, 2048, nullptr, nullptr, nullptr, nullptr);

    // 6) LN2 + modulate (bf16 only)
    ln_mod_kernel<<<MTOK / 8, 256>>>(p_x1, o_cmod, nullptr, nullptr, p_xm2b, 3072, 4096);

    // 7) MLP on tensor cores
    dim3 gF(FF / 128, MTOK / 128);     // (32, 64)
    mma_gemm<EPI_GELU><<<gF, 128, GEMM_SMEM>>>(p_xm2b, p_f1t, b_fc1, nullptr, p_hb, DD, FF, 1.f,
                                    nullptr, nullptr, 0, nullptr, nullptr, nullptr, nullptr);
    mma_gemm<EPI_GATE><<<gD, 128, GEMM_SMEM>>>(p_hb, p_f2t, b_fc2, o_xout, nullptr, FF, DD, 1.f,
                                    p_x1, o_cmod, 5120, nullptr, nullptr, nullptr, nullptr);
}

// round 10
// speedup vs baseline: 1.0976x; 1.0976x over previous
#include <cuda_runtime.h>
#include <cuda_bf16.h>
#include <math.h>
#include <cstdint>

// Problem dims (fixed by the dataset)
#define BB 8
#define SS 1024
#define DD 1024
#define FF 4096
#define MTOK (BB*SS)       // 8192
#define CMOD_N (6*DD)      // 6144

#define QSCALE 0.022542110013890053f   // log2(e) / 64

// -------- scratch (device globals; no allocation allowed) --------
__device__ float g_x1 [MTOK * DD];

__device__ __nv_bfloat16 g_qb  [MTOK * DD];
__device__ __nv_bfloat16 g_kb  [MTOK * DD];
__device__ __nv_bfloat16 g_vb  [MTOK * DD];
__device__ __nv_bfloat16 g_xmod_b[MTOK * DD];
__device__ __nv_bfloat16 g_xm2_b [MTOK * DD];
__device__ __nv_bfloat16 g_y_b   [MTOK * DD];
__device__ __nv_bfloat16 g_h_b   [(size_t)MTOK * FF];
__device__ __nv_bfloat16 g_wqkvt[3 * DD * DD];
__device__ __nv_bfloat16 g_wat  [DD * DD];
__device__ __nv_bfloat16 g_wfc1t[(size_t)FF * DD];
__device__ __nv_bfloat16 g_wfc2t[(size_t)DD * FF];

// ===================== PTX helpers (baseline ISA only — no tcgen05) =====================
__device__ __forceinline__ uint32_t smem_u32(const void* p) {
    uint32_t a;
    asm("{ .reg .u64 t; cvta.to.shared.u64 t, %1; cvt.u32.u64 %0, t; }" : "=r"(a) : "l"(p));
    return a;
}
__device__ __forceinline__ void cp_async16(uint32_t dst, const void* src) {
    asm volatile("cp.async.cg.shared.global [%0], [%1], 16;" :: "r"(dst), "l"(src));
}
#define CP_COMMIT() asm volatile("cp.async.commit_group;" ::: "memory")
#define CP_WAIT(n)  asm volatile("cp.async.wait_group %0;" :: "n"(n) : "memory")

__device__ __forceinline__ void ldm4(uint32_t* r, uint32_t addr) {
    asm volatile("ldmatrix.sync.aligned.m8n8.x4.shared.b16 {%0,%1,%2,%3}, [%4];"
        : "=r"(r[0]), "=r"(r[1]), "=r"(r[2]), "=r"(r[3]) : "r"(addr));
}
__device__ __forceinline__ void ldm4t(uint32_t* r, uint32_t addr) {
    asm volatile("ldmatrix.sync.aligned.m8n8.x4.trans.shared.b16 {%0,%1,%2,%3}, [%4];"
        : "=r"(r[0]), "=r"(r[1]), "=r"(r[2]), "=r"(r[3]) : "r"(addr));
}
__device__ __forceinline__ void mma16816(float* c, const uint32_t* a, const uint32_t* b) {
    asm volatile(
        "mma.sync.aligned.m16n8k16.row.col.f32.bf16.bf16.f32 "
        "{%0,%1,%2,%3}, {%4,%5,%6,%7}, {%8,%9}, {%0,%1,%2,%3};"
        : "+f"(c[0]), "+f"(c[1]), "+f"(c[2]), "+f"(c[3])
        : "r"(a[0]), "r"(a[1]), "r"(a[2]), "r"(a[3]), "r"(b[0]), "r"(b[1]));
}
__device__ __forceinline__ uint32_t pack_bf16x2(float lo, float hi) {
    uint32_t r;
    asm("cvt.rn.bf16x2.f32 %0, %1, %2;" : "=r"(r) : "f"(hi), "f"(lo));  // first operand -> upper half
    return r;
}
__device__ __forceinline__ float fast_exp2(float x) {
    float r;
    asm("ex2.approx.ftz.f32 %0, %1;" : "=f"(r) : "f"(x));
    return r;
}
__device__ __forceinline__ void stcs_f2(float* p, float2 v) {
    asm volatile("st.global.cs.v2.f32 [%0], {%1, %2};" :: "l"(p), "f"(v.x), "f"(v.y));
}
__device__ __forceinline__ void stcs_f4(float* p, float4 v) {
    asm volatile("st.global.cs.v4.f32 [%0], {%1, %2, %3, %4};"
        :: "l"(p), "f"(v.x), "f"(v.y), "f"(v.z), "f"(v.w));
}

// ===================== mma.sync GEMM: C[M x N] = A[M x K](bf16) @ Wt[N x K]^T =====================
// BM=128, BN=128. 256 threads (8 warps, warp tile 32x64) — the measured-best config (R8).
// 6-stage cp.async (3 pairs of BK=32 chunks); one barrier per 64 K-elems.
enum { EPI_QKV3 = 0, EPI_GATE = 1, EPI_GELU = 2 };

#define CHUNK_BYTES 16384       // A 8KB + B 8KB per BK=32 chunk
#define PAIR_BYTES  32768
#define B_OFF 8192
#define GEMM_SMEM (3 * PAIR_BYTES)   // 96 KB

template <int EPI>
__global__ void __launch_bounds__(256) mma_gemm(
    const __nv_bfloat16* __restrict__ A, const __nv_bfloat16* __restrict__ Wt,
    const float* __restrict__ bias,
    float* __restrict__ outf, __nv_bfloat16* __restrict__ outb,
    int K, int N, float scale,
    const float* __restrict__ add_src, const float* __restrict__ cmod, int gate_off,
    __nv_bfloat16* __restrict__ outb2, __nv_bfloat16* __restrict__ outb3,
    const float* __restrict__ bias2, const float* __restrict__ bias3)
{
    extern __shared__ __align__(128) char smbuf[];   // 96 KB
    const uint32_t smb = smem_u32(smbuf);

    const int tid = threadIdx.x;
    const int lane = tid & 31, wid = tid >> 5;
    const int wm = wid & 3, wn = wid >> 2;      // 4 warps M x 2 warps N
    const int m0 = blockIdx.y * 128;
    const int n0 = blockIdx.x * 128;

    const int uA0 = tid, uA1 = tid + 256;
    const int rA0u = uA0 >> 2, gA0u = uA0 & 3;
    const int rA1u = uA1 >> 2, gA1u = uA1 & 3;
    const uint32_t dstA0 = (uint32_t)rA0u * 64u + (uint32_t)((gA0u ^ ((rA0u >> 1) & 3)) << 4);
    const uint32_t dstA1 = (uint32_t)rA1u * 64u + (uint32_t)((gA1u ^ ((rA1u >> 1) & 3)) << 4);
    const __nv_bfloat16* srcA0 = A + (size_t)(m0 + rA0u) * K + gA0u * 8;
    const __nv_bfloat16* srcA1 = A + (size_t)(m0 + rA1u) * K + gA1u * 8;
    const __nv_bfloat16* srcB0 = Wt + (size_t)(n0 + rA0u) * K + gA0u * 8;
    const __nv_bfloat16* srcB1 = Wt + (size_t)(n0 + rA1u) * K + gA1u * 8;

    const int npair = K >> 6;   // K / 64

    uint32_t aoff[2][2];
    {
        int r = wm * 32 + (lane & 15);
        int sw = (r >> 1) & 3;
        #pragma unroll
        for (int mt = 0; mt < 2; mt++)
            #pragma unroll
            for (int ks = 0; ks < 2; ks++)
                aoff[mt][ks] = (uint32_t)(r + mt * 16) * 64u +
                               (uint32_t)(((ks * 2 + (lane >> 4)) ^ sw) << 4);
    }
    uint32_t boff[4][2];
    {
        int n = wn * 64 + ((lane >> 4) & 1) * 8 + (lane & 7);
        int gpar = (lane >> 3) & 1;
        int sw = (n >> 1) & 3;
        #pragma unroll
        for (int np = 0; np < 4; np++)
            #pragma unroll
            for (int ks = 0; ks < 2; ks++)
                boff[np][ks] = (uint32_t)B_OFF + (uint32_t)(n + np * 16) * 64u +
                               (uint32_t)(((ks * 2 + gpar) ^ sw) << 4);
    }

    // prologue: pairs 0,1 (chunks 0..3), one commit group per pair
    #pragma unroll
    for (int s = 0; s < 2; s++) {
        uint32_t base = smb + (uint32_t)s * PAIR_BYTES;
        #pragma unroll
        for (int h = 0; h < 2; h++) {
            uint32_t cb = base + (uint32_t)h * CHUNK_BYTES;
            int ch = 2 * s + h;
            cp_async16(cb + dstA0,         srcA0 + ch * 32);
            cp_async16(cb + dstA1,         srcA1 + ch * 32);
            cp_async16(cb + B_OFF + dstA0, srcB0 + ch * 32);
            cp_async16(cb + B_OFF + dstA1, srcB1 + ch * 32);
        }
        CP_COMMIT();
    }

    float c[2][8][4];
    #pragma unroll
    for (int mt = 0; mt < 2; mt++)
        #pragma unroll
        for (int nt = 0; nt < 8; nt++)
            #pragma unroll
            for (int e = 0; e < 4; e++) c[mt][nt][e] = 0.f;

    for (int p = 0; p < npair; p++) {
        CP_WAIT(1);
        __syncthreads();
        if (p + 2 < npair) {
            uint32_t base = smb + (uint32_t)((p + 2) % 3) * PAIR_BYTES;
            #pragma unroll
            for (int h = 0; h < 2; h++) {
                uint32_t cb = base + (uint32_t)h * CHUNK_BYTES;
                int ch = 2 * (p + 2) + h;
                cp_async16(cb + dstA0,         srcA0 + ch * 32);
                cp_async16(cb + dstA1,         srcA1 + ch * 32);
                cp_async16(cb + B_OFF + dstA0, srcB0 + ch * 32);
                cp_async16(cb + B_OFF + dstA1, srcB1 + ch * 32);
            }
        }
        CP_COMMIT();

        const uint32_t sp = smb + (uint32_t)(p % 3) * PAIR_BYTES;
        #pragma unroll
        for (int h = 0; h < 2; h++) {
            const uint32_t st = sp + (uint32_t)h * CHUNK_BYTES;
            #pragma unroll
            for (int ks = 0; ks < 2; ks++) {
                uint32_t a[2][4];
                ldm4(a[0], st + aoff[0][ks]);
                ldm4(a[1], st + aoff[1][ks]);
                uint32_t b[8][2];
                #pragma unroll
                for (int np = 0; np < 4; np++) {
                    uint32_t r[4];
                    ldm4(r, st + boff[np][ks]);
                    b[2 * np][0] = r[0]; b[2 * np][1] = r[1];
                    b[2 * np + 1][0] = r[2]; b[2 * np + 1][1] = r[3];
                }
                #pragma unroll
                for (int mt = 0; mt < 2; mt++)
                    #pragma unroll
                    for (int nt = 0; nt < 8; nt++)
                        mma16816(c[mt][nt], a[mt], b[nt]);
            }
        }
    }

    // ---- epilogue ----
    __nv_bfloat16* qdst = nullptr;
    const float* bsel = bias;
    float scl = scale;
    if (EPI == EPI_QKV3) {
        int buf = n0 >> 10;
        qdst = (buf == 0) ? outb : (buf == 1) ? outb2 : outb3;
        bsel = (buf == 0) ? bias : (buf == 1) ? bias2 : bias3;
        scl  = (buf == 0) ? scale : 1.f;
    }
    const int lcol0 = n0 & 1023;

    #pragma unroll
    for (int mt = 0; mt < 2; mt++) {
        #pragma unroll
        for (int half = 0; half < 2; half++) {
            const int grow = m0 + wm * 32 + mt * 16 + (lane >> 2) + half * 8;
            const int b = grow >> 10;
            #pragma unroll
            for (int nt = 0; nt < 8; nt++) {
                const int coff = wn * 64 + nt * 8 + (lane & 3) * 2;
                if (EPI == EPI_QKV3) {
                    const int lcol = lcol0 + coff;
                    float v0 = (c[mt][nt][half * 2 + 0] + bsel[lcol]) * scl;
                    float v1 = (c[mt][nt][half * 2 + 1] + bsel[lcol + 1]) * scl;
                    __nv_bfloat162 pr;
                    pr.x = __float2bfloat16(v0);
                    pr.y = __float2bfloat16(v1);
                    *(__nv_bfloat162*)&qdst[(size_t)grow * DD + lcol] = pr;
                } else if (EPI == EPI_GATE) {
                    const int gcol = n0 + coff;
                    float v0 = c[mt][nt][half * 2 + 0] + bias[gcol];
                    float v1 = c[mt][nt][half * 2 + 1] + bias[gcol + 1];
                    const float* gp = cmod + b * CMOD_N + gate_off + gcol;
                    const float* ap = add_src + (size_t)grow * N + gcol;
                    float2 o = { ap[0] + gp[0] * v0, ap[1] + gp[1] * v1 };
                    if (gate_off == 5120)   // final x_out: write-only -> streaming store
                        stcs_f2(&outf[(size_t)grow * N + gcol], o);
                    else
                        *(float2*)&outf[(size_t)grow * N + gcol] = o;
                } else {   // EPI_GELU -> bf16
                    const int gcol = n0 + coff;
                    float v0 = c[mt][nt][half * 2 + 0] + bias[gcol];
                    float v1 = c[mt][nt][half * 2 + 1] + bias[gcol + 1];
                    float g0 = 0.5f * v0 * (1.f + erff(v0 * 0.70710678118654752f));
                    float g1 = 0.5f * v1 * (1.f + erff(v1 * 0.70710678118654752f));
                    __nv_bfloat162 pr;
                    pr.x = __float2bfloat16(g0);
                    pr.y = __float2bfloat16(g1);
                    *(__nv_bfloat162*)&outb[(size_t)grow * N + gcol] = pr;
                }
            }
        }
    }
}

// ===================== Flash attention on mma.sync (bf16 in/out, fixed-base exp2 softmax) =====================
// Br=128, Bc=64, Dh=64. 128 threads = 4 warps, each owning 32 q-rows (mq=2): K/V fragments
// loaded once per warp serve 2x the tensor work -> crossbar ratio 0.63 (was 1.25 at Br=64/mq=1),
// while keeping the same threads/warps as the measured-best R8 flash.
// Fixed-base softmax (scores O(0.5) by construction), l-reduction deferred to epilogue.
__global__ void __launch_bounds__(128) flash_mma(
    const __nv_bfloat16* __restrict__ Q, const __nv_bfloat16* __restrict__ K,
    const __nv_bfloat16* __restrict__ V, __nv_bfloat16* __restrict__ Y)
{
    extern __shared__ __align__(128) char smbuf[];   // Q 16KB + 3 x (K 8KB + V 8KB) = 64KB
    const uint32_t Qb  = smem_u32(smbuf);
    const uint32_t KVb = Qb + 16384;

    const int tid = threadIdx.x, lane = tid & 31, w = tid >> 5;
    const int qt = blockIdx.x, h = blockIdx.y, b = blockIdx.z;
    const size_t gbase = ((size_t)b * SS) * DD + h * 64;
    const int t0q = qt * 128;

    // --- Q load (16KB = 1024 x 16B units, 8/thread) ---
    #pragma unroll
    for (int i = 0; i < 8; i++) {
        int u = tid + i * 128;
        int r = u >> 3, g = u & 7;
        cp_async16(Qb + r * 128 + ((g ^ (r & 7)) << 4),
                   Q + gbase + (size_t)(t0q + r) * DD + g * 8);
    }
    // --- KV tile loader: per operand 512 units, 4/thread ---
    int kvr[4], kvg[4];
    uint32_t kvd[4];
    #pragma unroll
    for (int i = 0; i < 4; i++) {
        int u = tid + i * 128;
        kvr[i] = u >> 3; kvg[i] = u & 7;
        kvd[i] = (uint32_t)kvr[i] * 128u + (uint32_t)((kvg[i] ^ (kvr[i] & 7)) << 4);
    }

    #pragma unroll
    for (int s = 0; s < 2; s++) {   // tiles 0,1 -> stages 0,1 (tile 0 shares group with Q)
        uint32_t base = KVb + (uint32_t)s * 16384u;
        #pragma unroll
        for (int i = 0; i < 4; i++) {
            cp_async16(base + kvd[i],        K + gbase + (size_t)(s * 64 + kvr[i]) * DD + kvg[i] * 8);
            cp_async16(base + 8192 + kvd[i], V + gbase + (size_t)(s * 64 + kvr[i]) * DD + kvg[i] * 8);
        }
        CP_COMMIT();
    }

    uint32_t qa[2][4][4];
    float O[2][8][4];
    #pragma unroll
    for (int mq = 0; mq < 2; mq++)
        #pragma unroll
        for (int nb = 0; nb < 8; nb++)
            #pragma unroll
            for (int e = 0; e < 4; e++) O[mq][nb][e] = 0.f;
    float lp[2][2] = { {0.f, 0.f}, {0.f, 0.f} };

    for (int t = 0; t < 16; t++) {
        CP_WAIT(1);
        __syncthreads();   // data visibility for tile t AND orders compute(t-1) before prefetch below
        if (t + 2 < 16) {
            uint32_t base = KVb + (uint32_t)((t + 2) % 3) * 16384u;
            const int t0k = (t + 2) * 64;
            #pragma unroll
            for (int i = 0; i < 4; i++) {
                cp_async16(base + kvd[i],        K + gbase + (size_t)(t0k + kvr[i]) * DD + kvg[i] * 8);
                cp_async16(base + 8192 + kvd[i], V + gbase + (size_t)(t0k + kvr[i]) * DD + kvg[i] * 8);
            }
        }
        CP_COMMIT();

        if (t == 0) {
            #pragma unroll
            for (int mq = 0; mq < 2; mq++)
                #pragma unroll
                for (int kc = 0; kc < 4; kc++) {
                    int r = w * 32 + mq * 16 + (lane & 15);
                    int g = (kc * 2 + (lane >> 4)) ^ (r & 7);
                    ldm4(qa[mq][kc], Qb + r * 128 + (g << 4));
                }
        }
        const uint32_t Kb = KVb + (uint32_t)(t % 3) * 16384u;
        const uint32_t Vb = Kb + 8192u;

        // ---- S = Q @ K^T (K fragments shared across both q-row blocks) ----
        float sc[2][8][4];
        #pragma unroll
        for (int mq = 0; mq < 2; mq++)
            #pragma unroll
            for (int nb = 0; nb < 8; nb++)
                #pragma unroll
                for (int e = 0; e < 4; e++) sc[mq][nb][e] = 0.f;
        #pragma unroll
        for (int kc = 0; kc < 4; kc++) {
            #pragma unroll
            for (int ng = 0; ng < 4; ng++) {
                int n = ng * 16 + ((lane >> 4) & 1) * 8 + (lane & 7);
                int g = (kc * 2 + ((lane >> 3) & 1)) ^ (n & 7);
                uint32_t kb[4];
                ldm4(kb, Kb + n * 128 + (g << 4));
                #pragma unroll
                for (int mq = 0; mq < 2; mq++) {
                    mma16816(sc[mq][2 * ng],     qa[mq][kc], &kb[0]);
                    mma16816(sc[mq][2 * ng + 1], qa[mq][kc], &kb[2]);
                }
            }
        }

        // ---- fixed-base softmax: P = exp2(S), partial row sums only ----
        uint32_t pa[2][4][4];
        #pragma unroll
        for (int mq = 0; mq < 2; mq++)
            #pragma unroll
            for (int ng = 0; ng < 4; ng++) {
                float e00 = fast_exp2(sc[mq][2 * ng][0]),     e01 = fast_exp2(sc[mq][2 * ng][1]);
                float e02 = fast_exp2(sc[mq][2 * ng][2]),     e03 = fast_exp2(sc[mq][2 * ng][3]);
                float e10 = fast_exp2(sc[mq][2 * ng + 1][0]), e11 = fast_exp2(sc[mq][2 * ng + 1][1]);
                float e12 = fast_exp2(sc[mq][2 * ng + 1][2]), e13 = fast_exp2(sc[mq][2 * ng + 1][3]);
                lp[mq][0] += e00 + e01 + e10 + e11;
                lp[mq][1] += e02 + e03 + e12 + e13;
                pa[mq][ng][0] = pack_bf16x2(e00, e01);
                pa[mq][ng][1] = pack_bf16x2(e02, e03);
                pa[mq][ng][2] = pack_bf16x2(e10, e11);
                pa[mq][ng][3] = pack_bf16x2(e12, e13);
            }

        // ---- O += P @ V (V fragments shared across both q-row blocks) ----
        #pragma unroll
        for (int kc = 0; kc < 4; kc++) {
            #pragma unroll
            for (int ng = 0; ng < 4; ng++) {
                int r = kc * 16 + (lane & 15);
                int g = (ng * 2 + (lane >> 4)) ^ (r & 7);
                uint32_t vb[4];
                ldm4t(vb, Vb + r * 128 + (g << 4));
                #pragma unroll
                for (int mq = 0; mq < 2; mq++) {
                    mma16816(O[mq][2 * ng],     pa[mq][kc], &vb[0]);
                    mma16816(O[mq][2 * ng + 1], pa[mq][kc], &vb[2]);
                }
            }
        }
        // no trailing barrier: next iteration's top barrier orders compute(t) vs prefetch(t+3)
    }

    // ---- single end-of-loop l reduction + store ----
    #pragma unroll
    for (int mq = 0; mq < 2; mq++) {
        float l0 = lp[mq][0], l1 = lp[mq][1];
        l0 += __shfl_xor_sync(0xffffffffu, l0, 1);
        l0 += __shfl_xor_sync(0xffffffffu, l0, 2);
        l1 += __shfl_xor_sync(0xffffffffu, l1, 1);
        l1 += __shfl_xor_sync(0xffffffffu, l1, 2);
        float inv0 = 1.f / l0, inv1 = 1.f / l1;
        const int r0 = t0q + w * 32 + mq * 16 + (lane >> 2);
        #pragma unroll
        for (int nb = 0; nb < 8; nb++) {
            const int d = nb * 8 + (lane & 3) * 2;
            __nv_bfloat162 p0, p1;
            p0.x = __float2bfloat16(O[mq][nb][0] * inv0);
            p0.y = __float2bfloat16(O[mq][nb][1] * inv0);
            p1.x = __float2bfloat16(O[mq][nb][2] * inv1);
            p1.y = __float2bfloat16(O[mq][nb][3] * inv1);
            *(__nv_bfloat162*)&Y[gbase + (size_t)r0 * DD + d]       = p0;
            *(__nv_bfloat162*)&Y[gbase + (size_t)(r0 + 8) * DD + d] = p1;
        }
    }
}

// ---------------- merged transpose + fp32->bf16 of all weights ----------------
// tiles: [0,3072) qkv | [3072,4096) w_attn | [4096,8192) fc1 | [8192,12288) fc2
__global__ void __launch_bounds__(256) transpose_all(
    const float* __restrict__ wq, const float* __restrict__ wk, const float* __restrict__ wv,
    const float* __restrict__ wattn, const float* __restrict__ wfc1, const float* __restrict__ wfc2,
    __nv_bfloat16* __restrict__ qkvt, __nv_bfloat16* __restrict__ wat,
    __nv_bfloat16* __restrict__ f1t, __nv_bfloat16* __restrict__ f2t)
{
    __shared__ float t[32][33];
    int id = blockIdx.x;
    const float* W; __nv_bfloat16* Wt;
    int n0, k0, Nsrc, Kdst;
    if (id < 3072) {               // qkv: 96 n-tiles x 32 k-tiles
        int tx = id % 96, ty = id / 96;
        n0 = tx * 32; k0 = ty * 32;
        int buf = n0 >> 10;
        W = (buf == 0) ? wq : (buf == 1) ? wk : wv;
        Wt = qkvt;  Nsrc = DD; Kdst = DD;
        int nl0 = n0 & 1023;
        int txi = threadIdx.x & 31, tyi = threadIdx.x >> 5;
        #pragma unroll
        for (int r = tyi; r < 32; r += 8)
            t[r][txi] = W[(size_t)(k0 + r) * Nsrc + nl0 + txi];
        __syncthreads();
        #pragma unroll
        for (int r = tyi; r < 32; r += 8)
            Wt[(size_t)(n0 + r) * Kdst + k0 + txi] = __float2bfloat16(t[txi][r]);
        return;
    } else if (id < 4096) {        // w_attn: 32 x 32
        int lid2 = id - 3072;
        n0 = (lid2 % 32) * 32; k0 = (lid2 / 32) * 32;
        W = wattn; Wt = wat; Nsrc = DD; Kdst = DD;
    } else if (id < 8192) {        // fc1: [K=1024, N=4096] -> f1t[4096,1024]: 128 x 32
        int lid2 = id - 4096;
        n0 = (lid2 % 128) * 32; k0 = (lid2 / 128) * 32;
        W = wfc1; Wt = f1t; Nsrc = FF; Kdst = DD;
    } else {                       // fc2: [K=4096, N=1024] -> f2t[1024,4096]: 32 x 128
        int lid2 = id - 8192;
        n0 = (lid2 % 32) * 32; k0 = (lid2 / 32) * 32;
        W = wfc2; Wt = f2t; Nsrc = DD; Kdst = FF;
    }
    int txi = threadIdx.x & 31, tyi = threadIdx.x >> 5;
    #pragma unroll
    for (int r = tyi; r < 32; r += 8)
        t[r][txi] = W[(size_t)(k0 + r) * Nsrc + n0 + txi];
    __syncthreads();
    #pragma unroll
    for (int r = tyi; r < 32; r += 8)
        Wt[(size_t)(n0 + r) * Kdst + k0 + txi] = __float2bfloat16(t[txi][r]);
}

// ---------------- cmod = silu(c) @ w_mod + b_mod (fp32; silu fused; 192 CTAs) ----------------
__global__ void __launch_bounds__(256) mod_gemm2(
    const float* __restrict__ c, const float* __restrict__ w_mod,
    const float* __restrict__ b_mod, float* __restrict__ cmod,
    float* __restrict__ o_shift, float* __restrict__ o_scale, float* __restrict__ o_cact)
{
    __shared__ float sc[BB * DD];        // 32 KB
    __shared__ float red[8][32][8];      // 8 KB  [ks][jl][b]
    int tid = threadIdx.x;
    for (int i = tid; i < BB * DD; i += 256) {
        float v = c[i];
        float sv = v / (1.f + expf(-v));
        sc[i] = sv;
        if (blockIdx.x == 0) o_cact[i] = sv;
    }
    __syncthreads();

    int jl = tid & 31, ks = tid >> 5;
    int j = blockIdx.x * 32 + jl;
    float acc[BB];
    #pragma unroll
    for (int b = 0; b < BB; b++) acc[b] = 0.f;

    int d0 = ks * 128;
    #pragma unroll 4
    for (int dd = 0; dd < 128; dd++) {
        int d = d0 + dd;
        float w = w_mod[(size_t)d * CMOD_N + j];
        #pragma unroll
        for (int b = 0; b < BB; b++) acc[b] = fmaf(sc[b * DD + d], w, acc[b]);
    }
    #pragma unroll
    for (int b = 0; b < BB; b++) red[ks][jl][b] = acc[b];
    __syncthreads();

    int b = ks;
    float s = 0.f;
    #pragma unroll
    for (int kk = 0; kk < 8; kk++) s += red[kk][jl][b];
    float v = s + b_mod[j];
    cmod[b * CMOD_N + j] = v;
    if (j < 1024)            o_shift[b * DD + j] = v;
    else if (j < 2048)       o_scale[b * DD + (j - 1024)] = v;
}

// ---------------- LayerNorm + modulate (warp-per-row; no block barriers, no smem) ----------------
__global__ void __launch_bounds__(256) ln_mod_kernel(
    const float* __restrict__ x, const float* __restrict__ cmod,
    float* __restrict__ xnorm, float* __restrict__ xmod, __nv_bfloat16* __restrict__ xmod_b,
    int shift_off, int scale_off)
{
    const int row = blockIdx.x * 8 + (threadIdx.x >> 5);
    const int lane = threadIdx.x & 31;
    const int b = row >> 10;
    const float4* xr = (const float4*)(x + (size_t)row * DD);

    float4 v[8];
    float s = 0.f;
    #pragma unroll
    for (int i = 0; i < 8; i++) {
        v[i] = xr[lane + i * 32];
        s += v[i].x + v[i].y + v[i].z + v[i].w;
    }
    #pragma unroll
    for (int o = 16; o > 0; o >>= 1) s += __shfl_xor_sync(0xffffffffu, s, o);
    const float mu = s * (1.f / DD);

    float s2 = 0.f;
    #pragma unroll
    for (int i = 0; i < 8; i++) {
        float d0 = v[i].x - mu, d1 = v[i].y - mu, d2 = v[i].z - mu, d3 = v[i].w - mu;
        s2 += d0 * d0 + d1 * d1 + d2 * d2 + d3 * d3;
    }
    #pragma unroll
    for (int o = 16; o > 0; o >>= 1) s2 += __shfl_xor_sync(0xffffffffu, s2, o);
    const float rstd = rsqrtf(s2 * (1.f / DD) + 1e-6f);

    const float4* shp = (const float4*)(cmod + b * CMOD_N + shift_off);
    const float4* slp = (const float4*)(cmod + b * CMOD_N + scale_off);
    #pragma unroll
    for (int i = 0; i < 8; i++) {
        const int idx = lane + i * 32;
        const float4 sh = shp[idx], sl = slp[idx];
        float4 xn = { (v[i].x - mu) * rstd, (v[i].y - mu) * rstd,
                      (v[i].z - mu) * rstd, (v[i].w - mu) * rstd };
        float4 xm = { xn.x * (1.f + sl.x) + sh.x, xn.y * (1.f + sl.y) + sh.y,
                      xn.z * (1.f + sl.z) + sh.z, xn.w * (1.f + sl.w) + sh.w };
        if (xnorm) stcs_f4(xnorm + (size_t)row * DD + idx * 4, xn);
        if (xmod)  stcs_f4(xmod  + (size_t)row * DD + idx * 4, xm);
        uint2 p = { pack_bf16x2(xm.x, xm.y), pack_bf16x2(xm.z, xm.w) };
        ((uint2*)(xmod_b + (size_t)row * DD))[idx] = p;
    }
}

// ---------------- launch ----------------
extern "C" void kernel_launch(void* const* d_in, const int* in_sizes, int n_in,
                              void* d_out, int out_size)
{
    const float* x      = (const float*)d_in[0];
    const float* c      = (const float*)d_in[1];
    const float* w_mod  = (const float*)d_in[2];
    const float* b_mod  = (const float*)d_in[3];
    const float* w_q    = (const float*)d_in[4];
    const float* b_q    = (const float*)d_in[5];
    const float* w_k    = (const float*)d_in[6];
    const float* b_k    = (const float*)d_in[7];
    const float* w_v    = (const float*)d_in[8];
    const float* b_v    = (const float*)d_in[9];
    const float* w_attn = (const float*)d_in[10];
    const float* b_attn = (const float*)d_in[11];
    const float* w_fc1  = (const float*)d_in[12];
    const float* b_fc1  = (const float*)d_in[13];
    const float* w_fc2  = (const float*)d_in[14];
    const float* b_fc2  = (const float*)d_in[15];

    float* out = (float*)d_out;
    float* o_xout  = out;                    // [8,1024,1024]
    float* o_xnorm = out + 8388608;          // [8,1024,1024]
    float* o_xmod  = out + 16777216;         // [8,1024,1024]
    float* o_shift = out + 25165824;         // [8,1024]
    float* o_scale = out + 25174016;         // [8,1024]
    float* o_cmod  = out + 25182208;         // [8,6144]
    float* o_cact  = out + 25231360;         // [8,1024]

    float *p_x1;
    __nv_bfloat16 *p_qb, *p_kb, *p_vb, *p_xmb, *p_xm2b, *p_yb, *p_hb;
    __nv_bfloat16 *p_wqkvt, *p_wat, *p_f1t, *p_f2t;
    cudaGetSymbolAddress((void**)&p_x1,    g_x1);
    cudaGetSymbolAddress((void**)&p_qb,    g_qb);
    cudaGetSymbolAddress((void**)&p_kb,    g_kb);
    cudaGetSymbolAddress((void**)&p_vb,    g_vb);
    cudaGetSymbolAddress((void**)&p_xmb,   g_xmod_b);
    cudaGetSymbolAddress((void**)&p_xm2b,  g_xm2_b);
    cudaGetSymbolAddress((void**)&p_yb,    g_y_b);
    cudaGetSymbolAddress((void**)&p_hb,    g_h_b);
    cudaGetSymbolAddress((void**)&p_wqkvt, g_wqkvt);
    cudaGetSymbolAddress((void**)&p_wat,   g_wat);
    cudaGetSymbolAddress((void**)&p_f1t,   g_wfc1t);
    cudaGetSymbolAddress((void**)&p_f2t,   g_wfc2t);

    cudaFuncSetAttribute(flash_mma, cudaFuncAttributeMaxDynamicSharedMemorySize, 65536);
    cudaFuncSetAttribute(mma_gemm<EPI_QKV3>, cudaFuncAttributeMaxDynamicSharedMemorySize, GEMM_SMEM);
    cudaFuncSetAttribute(mma_gemm<EPI_GATE>, cudaFuncAttributeMaxDynamicSharedMemorySize, GEMM_SMEM);
    cudaFuncSetAttribute(mma_gemm<EPI_GELU>, cudaFuncAttributeMaxDynamicSharedMemorySize, GEMM_SMEM);

    // 0) all weight transposes in one launch
    transpose_all<<<12288, 256>>>(w_q, w_k, w_v, w_attn, w_fc1, w_fc2,
                                  p_wqkvt, p_wat, p_f1t, p_f2t);

    // 1) conditioning path (fp32, silu fused)
    mod_gemm2<<<CMOD_N / 32, 256>>>(c, w_mod, b_mod, o_cmod, o_shift, o_scale, o_cact);

    // 2) LN1 + modulate
    ln_mod_kernel<<<MTOK / 8, 256>>>(x, o_cmod, o_xnorm, o_xmod, p_xmb, 0, 1024);

    // 3) fused QKV projection -> bf16 (q scaled by log2(e)/64 for exp2 softmax)
    dim3 gQKV(3 * DD / 128, MTOK / 128);   // (24, 64)
    mma_gemm<EPI_QKV3><<<gQKV, 256, GEMM_SMEM>>>(p_xmb, p_wqkvt, b_q, nullptr, p_qb, DD, DD, QSCALE,
                                      nullptr, nullptr, 0, p_kb, p_vb, b_k, b_v);

    // 4) attention on tensor cores (Br=128, mq=2: amortized K/V fragments)
    flash_mma<<<dim3(SS / 128, 16, BB), 128, 65536>>>(p_qb, p_kb, p_vb, p_yb);

    // 5) attn projection + residual with gate_msa
    dim3 gD(DD / 128, MTOK / 128);     // (8, 64)
    mma_gemm<EPI_GATE><<<gD, 256, GEMM_SMEM>>>(p_yb, p_wat, b_attn, p_x1, nullptr, DD, DD, 1.f,
                                    x, o_cmod, 2048, nullptr, nullptr, nullptr, nullptr);

    // 6) LN2 + modulate (bf16 only)
    ln_mod_kernel<<<MTOK / 8, 256>>>(p_x1, o_cmod, nullptr, nullptr, p_xm2b, 3072, 4096);

    // 7) MLP on tensor cores
    dim3 gF(FF / 128, MTOK / 128);     // (32, 64)
    mma_gemm<EPI_GELU><<<gF, 256, GEMM_SMEM>>>(p_xm2b, p_f1t, b_fc1, nullptr, p_hb, DD, FF, 1.f,
                                    nullptr, nullptr, 0, nullptr, nullptr, nullptr, nullptr);
    mma_gemm<EPI_GATE><<<gD, 256, GEMM_SMEM>>>(p_hb, p_f2t, b_fc2, o_xout, nullptr, FF, DD, 1.f,
                                    p_x1, o_cmod, 5120, nullptr, nullptr, nullptr, nullptr);
}

// round 11
// speedup vs baseline: 1.1128x; 1.0139x over previous
#include <cuda_runtime.h>
#include <cuda_bf16.h>
#include <math.h>
#include <cstdint>

// Problem dims (fixed by the dataset)
#define BB 8
#define SS 1024
#define DD 1024
#define FF 4096
#define MTOK (BB*SS)       // 8192
#define CMOD_N (6*DD)      // 6144

#define QSCALE 0.022542110013890053f   // log2(e) / 64

// -------- scratch (device globals; no allocation allowed) --------
__device__ float g_x1 [MTOK * DD];

__device__ __nv_bfloat16 g_qb  [MTOK * DD];
__device__ __nv_bfloat16 g_kb  [MTOK * DD];
__device__ __nv_bfloat16 g_vb  [MTOK * DD];
__device__ __nv_bfloat16 g_xmod_b[MTOK * DD];
__device__ __nv_bfloat16 g_xm2_b [MTOK * DD];
__device__ __nv_bfloat16 g_y_b   [MTOK * DD];
__device__ __nv_bfloat16 g_h_b   [(size_t)MTOK * FF];
__device__ __nv_bfloat16 g_wqkvt[3 * DD * DD];
__device__ __nv_bfloat16 g_wat  [DD * DD];
__device__ __nv_bfloat16 g_wfc1t[(size_t)FF * DD];
__device__ __nv_bfloat16 g_wfc2t[(size_t)DD * FF];

// ===================== PTX helpers (baseline ISA only — no tcgen05) =====================
__device__ __forceinline__ uint32_t smem_u32(const void* p) {
    uint32_t a;
    asm("{ .reg .u64 t; cvta.to.shared.u64 t, %1; cvt.u32.u64 %0, t; }" : "=r"(a) : "l"(p));
    return a;
}
__device__ __forceinline__ void cp_async16(uint32_t dst, const void* src) {
    asm volatile("cp.async.cg.shared.global [%0], [%1], 16;" :: "r"(dst), "l"(src));
}
#define CP_COMMIT() asm volatile("cp.async.commit_group;" ::: "memory")
#define CP_WAIT(n)  asm volatile("cp.async.wait_group %0;" :: "n"(n) : "memory")

__device__ __forceinline__ void ldm4(uint32_t* r, uint32_t addr) {
    asm volatile("ldmatrix.sync.aligned.m8n8.x4.shared.b16 {%0,%1,%2,%3}, [%4];"
        : "=r"(r[0]), "=r"(r[1]), "=r"(r[2]), "=r"(r[3]) : "r"(addr));
}
__device__ __forceinline__ void ldm4t(uint32_t* r, uint32_t addr) {
    asm volatile("ldmatrix.sync.aligned.m8n8.x4.trans.shared.b16 {%0,%1,%2,%3}, [%4];"
        : "=r"(r[0]), "=r"(r[1]), "=r"(r[2]), "=r"(r[3]) : "r"(addr));
}
__device__ __forceinline__ void mma16816(float* c, const uint32_t* a, const uint32_t* b) {
    asm volatile(
        "mma.sync.aligned.m16n8k16.row.col.f32.bf16.bf16.f32 "
        "{%0,%1,%2,%3}, {%4,%5,%6,%7}, {%8,%9}, {%0,%1,%2,%3};"
        : "+f"(c[0]), "+f"(c[1]), "+f"(c[2]), "+f"(c[3])
        : "r"(a[0]), "r"(a[1]), "r"(a[2]), "r"(a[3]), "r"(b[0]), "r"(b[1]));
}
__device__ __forceinline__ uint32_t pack_bf16x2(float lo, float hi) {
    uint32_t r;
    asm("cvt.rn.bf16x2.f32 %0, %1, %2;" : "=r"(r) : "f"(hi), "f"(lo));  // first operand -> upper half
    return r;
}
__device__ __forceinline__ float fast_exp2(float x) {
    float r;
    asm("ex2.approx.ftz.f32 %0, %1;" : "=f"(r) : "f"(x));
    return r;
}
__device__ __forceinline__ void stcs_f2(float* p, float2 v) {
    asm volatile("st.global.cs.v2.f32 [%0], {%1, %2};" :: "l"(p), "f"(v.x), "f"(v.y));
}
__device__ __forceinline__ void stcs_f4(float* p, float4 v) {
    asm volatile("st.global.cs.v4.f32 [%0], {%1, %2, %3, %4};"
        :: "l"(p), "f"(v.x), "f"(v.y), "f"(v.z), "f"(v.w));
}

// ===================== mma.sync GEMM: C[M x N] = A[M x K](bf16) @ Wt[N x K]^T =====================
// BM=128, BN=128. 256 threads (8 warps, warp tile 32x64) — the measured-best config.
// 6-stage cp.async (3 pairs of BK=32 chunks); one barrier per 64 K-elems.
enum { EPI_QKV3 = 0, EPI_GATE = 1, EPI_GELU = 2 };

#define CHUNK_BYTES 16384       // A 8KB + B 8KB per BK=32 chunk
#define PAIR_BYTES  32768
#define B_OFF 8192
#define GEMM_SMEM (3 * PAIR_BYTES)   // 96 KB

template <int EPI>
__global__ void __launch_bounds__(256) mma_gemm(
    const __nv_bfloat16* __restrict__ A, const __nv_bfloat16* __restrict__ Wt,
    const float* __restrict__ bias,
    float* __restrict__ outf, __nv_bfloat16* __restrict__ outb,
    int K, int N, float scale,
    const float* __restrict__ add_src, const float* __restrict__ cmod, int gate_off,
    __nv_bfloat16* __restrict__ outb2, __nv_bfloat16* __restrict__ outb3,
    const float* __restrict__ bias2, const float* __restrict__ bias3)
{
    extern __shared__ __align__(128) char smbuf[];   // 96 KB
    const uint32_t smb = smem_u32(smbuf);

    const int tid = threadIdx.x;
    const int lane = tid & 31, wid = tid >> 5;
    const int wm = wid & 3, wn = wid >> 2;      // 4 warps M x 2 warps N
    const int m0 = blockIdx.y * 128;
    const int n0 = blockIdx.x * 128;

    const int uA0 = tid, uA1 = tid + 256;
    const int rA0u = uA0 >> 2, gA0u = uA0 & 3;
    const int rA1u = uA1 >> 2, gA1u = uA1 & 3;
    const uint32_t dstA0 = (uint32_t)rA0u * 64u + (uint32_t)((gA0u ^ ((rA0u >> 1) & 3)) << 4);
    const uint32_t dstA1 = (uint32_t)rA1u * 64u + (uint32_t)((gA1u ^ ((rA1u >> 1) & 3)) << 4);
    const __nv_bfloat16* srcA0 = A + (size_t)(m0 + rA0u) * K + gA0u * 8;
    const __nv_bfloat16* srcA1 = A + (size_t)(m0 + rA1u) * K + gA1u * 8;
    const __nv_bfloat16* srcB0 = Wt + (size_t)(n0 + rA0u) * K + gA0u * 8;
    const __nv_bfloat16* srcB1 = Wt + (size_t)(n0 + rA1u) * K + gA1u * 8;

    const int npair = K >> 6;   // K / 64

    uint32_t aoff[2][2];
    {
        int r = wm * 32 + (lane & 15);
        int sw = (r >> 1) & 3;
        #pragma unroll
        for (int mt = 0; mt < 2; mt++)
            #pragma unroll
            for (int ks = 0; ks < 2; ks++)
                aoff[mt][ks] = (uint32_t)(r + mt * 16) * 64u +
                               (uint32_t)(((ks * 2 + (lane >> 4)) ^ sw) << 4);
    }
    uint32_t boff[4][2];
    {
        int n = wn * 64 + ((lane >> 4) & 1) * 8 + (lane & 7);
        int gpar = (lane >> 3) & 1;
        int sw = (n >> 1) & 3;
        #pragma unroll
        for (int np = 0; np < 4; np++)
            #pragma unroll
            for (int ks = 0; ks < 2; ks++)
                boff[np][ks] = (uint32_t)B_OFF + (uint32_t)(n + np * 16) * 64u +
                               (uint32_t)(((ks * 2 + gpar) ^ sw) << 4);
    }

    // prologue: pairs 0,1 (chunks 0..3), one commit group per pair
    #pragma unroll
    for (int s = 0; s < 2; s++) {
        uint32_t base = smb + (uint32_t)s * PAIR_BYTES;
        #pragma unroll
        for (int h = 0; h < 2; h++) {
            uint32_t cb = base + (uint32_t)h * CHUNK_BYTES;
            int ch = 2 * s + h;
            cp_async16(cb + dstA0,         srcA0 + ch * 32);
            cp_async16(cb + dstA1,         srcA1 + ch * 32);
            cp_async16(cb + B_OFF + dstA0, srcB0 + ch * 32);
            cp_async16(cb + B_OFF + dstA1, srcB1 + ch * 32);
        }
        CP_COMMIT();
    }

    float c[2][8][4];
    #pragma unroll
    for (int mt = 0; mt < 2; mt++)
        #pragma unroll
        for (int nt = 0; nt < 8; nt++)
            #pragma unroll
            for (int e = 0; e < 4; e++) c[mt][nt][e] = 0.f;

    for (int p = 0; p < npair; p++) {
        CP_WAIT(1);
        __syncthreads();
        if (p + 2 < npair) {
            uint32_t base = smb + (uint32_t)((p + 2) % 3) * PAIR_BYTES;
            #pragma unroll
            for (int h = 0; h < 2; h++) {
                uint32_t cb = base + (uint32_t)h * CHUNK_BYTES;
                int ch = 2 * (p + 2) + h;
                cp_async16(cb + dstA0,         srcA0 + ch * 32);
                cp_async16(cb + dstA1,         srcA1 + ch * 32);
                cp_async16(cb + B_OFF + dstA0, srcB0 + ch * 32);
                cp_async16(cb + B_OFF + dstA1, srcB1 + ch * 32);
            }
        }
        CP_COMMIT();

        const uint32_t sp = smb + (uint32_t)(p % 3) * PAIR_BYTES;
        #pragma unroll
        for (int h = 0; h < 2; h++) {
            const uint32_t st = sp + (uint32_t)h * CHUNK_BYTES;
            #pragma unroll
            for (int ks = 0; ks < 2; ks++) {
                uint32_t a[2][4];
                ldm4(a[0], st + aoff[0][ks]);
                ldm4(a[1], st + aoff[1][ks]);
                uint32_t b[8][2];
                #pragma unroll
                for (int np = 0; np < 4; np++) {
                    uint32_t r[4];
                    ldm4(r, st + boff[np][ks]);
                    b[2 * np][0] = r[0]; b[2 * np][1] = r[1];
                    b[2 * np + 1][0] = r[2]; b[2 * np + 1][1] = r[3];
                }
                #pragma unroll
                for (int mt = 0; mt < 2; mt++)
                    #pragma unroll
                    for (int nt = 0; nt < 8; nt++)
                        mma16816(c[mt][nt], a[mt], b[nt]);
            }
        }
    }

    // ---- epilogue ----
    __nv_bfloat16* qdst = nullptr;
    const float* bsel = bias;
    float scl = scale;
    if (EPI == EPI_QKV3) {
        int buf = n0 >> 10;
        qdst = (buf == 0) ? outb : (buf == 1) ? outb2 : outb3;
        bsel = (buf == 0) ? bias : (buf == 1) ? bias2 : bias3;
        scl  = (buf == 0) ? scale : 1.f;
    }
    const int lcol0 = n0 & 1023;

    #pragma unroll
    for (int mt = 0; mt < 2; mt++) {
        #pragma unroll
        for (int half = 0; half < 2; half++) {
            const int grow = m0 + wm * 32 + mt * 16 + (lane >> 2) + half * 8;
            const int b = grow >> 10;
            #pragma unroll
            for (int nt = 0; nt < 8; nt++) {
                const int coff = wn * 64 + nt * 8 + (lane & 3) * 2;
                if (EPI == EPI_QKV3) {
                    const int lcol = lcol0 + coff;
                    float v0 = (c[mt][nt][half * 2 + 0] + bsel[lcol]) * scl;
                    float v1 = (c[mt][nt][half * 2 + 1] + bsel[lcol + 1]) * scl;
                    __nv_bfloat162 pr;
                    pr.x = __float2bfloat16(v0);
                    pr.y = __float2bfloat16(v1);
                    *(__nv_bfloat162*)&qdst[(size_t)grow * DD + lcol] = pr;
                } else if (EPI == EPI_GATE) {
                    const int gcol = n0 + coff;
                    float v0 = c[mt][nt][half * 2 + 0] + bias[gcol];
                    float v1 = c[mt][nt][half * 2 + 1] + bias[gcol + 1];
                    const float* gp = cmod + b * CMOD_N + gate_off + gcol;
                    const float* ap = add_src + (size_t)grow * N + gcol;
                    float2 o = { ap[0] + gp[0] * v0, ap[1] + gp[1] * v1 };
                    if (gate_off == 5120)   // final x_out: write-only -> streaming store
                        stcs_f2(&outf[(size_t)grow * N + gcol], o);
                    else
                        *(float2*)&outf[(size_t)grow * N + gcol] = o;
                } else {   // EPI_GELU -> bf16
                    const int gcol = n0 + coff;
                    float v0 = c[mt][nt][half * 2 + 0] + bias[gcol];
                    float v1 = c[mt][nt][half * 2 + 1] + bias[gcol + 1];
                    float g0 = 0.5f * v0 * (1.f + erff(v0 * 0.70710678118654752f));
                    float g1 = 0.5f * v1 * (1.f + erff(v1 * 0.70710678118654752f));
                    __nv_bfloat162 pr;
                    pr.x = __float2bfloat16(g0);
                    pr.y = __float2bfloat16(g1);
                    *(__nv_bfloat162*)&outb[(size_t)grow * N + gcol] = pr;
                }
            }
        }
    }
}

// ===================== Flash attention on mma.sync (bf16 in/out, fixed-base exp2 softmax) =====================
// Br=128, Bc=64, Dh=64. 128 threads = 4 warps, each owning 32 q-rows (mq=2): K/V fragments
// loaded once per warp serve 2x the tensor work.
// Fixed-base softmax (scores O(0.5) by construction), l-reduction deferred to epilogue.
__global__ void __launch_bounds__(128) flash_mma(
    const __nv_bfloat16* __restrict__ Q, const __nv_bfloat16* __restrict__ K,
    const __nv_bfloat16* __restrict__ V, __nv_bfloat16* __restrict__ Y)
{
    extern __shared__ __align__(128) char smbuf[];   // Q 16KB + 3 x (K 8KB + V 8KB) = 64KB
    const uint32_t Qb  = smem_u32(smbuf);
    const uint32_t KVb = Qb + 16384;

    const int tid = threadIdx.x, lane = tid & 31, w = tid >> 5;
    const int qt = blockIdx.x, h = blockIdx.y, b = blockIdx.z;
    const size_t gbase = ((size_t)b * SS) * DD + h * 64;
    const int t0q = qt * 128;

    // --- Q load (16KB = 1024 x 16B units, 8/thread) ---
    #pragma unroll
    for (int i = 0; i < 8; i++) {
        int u = tid + i * 128;
        int r = u >> 3, g = u & 7;
        cp_async16(Qb + r * 128 + ((g ^ (r & 7)) << 4),
                   Q + gbase + (size_t)(t0q + r) * DD + g * 8);
    }
    // --- KV tile loader: per operand 512 units, 4/thread ---
    int kvr[4], kvg[4];
    uint32_t kvd[4];
    #pragma unroll
    for (int i = 0; i < 4; i++) {
        int u = tid + i * 128;
        kvr[i] = u >> 3; kvg[i] = u & 7;
        kvd[i] = (uint32_t)kvr[i] * 128u + (uint32_t)((kvg[i] ^ (kvr[i] & 7)) << 4);
    }

    #pragma unroll
    for (int s = 0; s < 2; s++) {   // tiles 0,1 -> stages 0,1 (tile 0 shares group with Q)
        uint32_t base = KVb + (uint32_t)s * 16384u;
        #pragma unroll
        for (int i = 0; i < 4; i++) {
            cp_async16(base + kvd[i],        K + gbase + (size_t)(s * 64 + kvr[i]) * DD + kvg[i] * 8);
            cp_async16(base + 8192 + kvd[i], V + gbase + (size_t)(s * 64 + kvr[i]) * DD + kvg[i] * 8);
        }
        CP_COMMIT();
    }

    uint32_t qa[2][4][4];
    float O[2][8][4];
    #pragma unroll
    for (int mq = 0; mq < 2; mq++)
        #pragma unroll
        for (int nb = 0; nb < 8; nb++)
            #pragma unroll
            for (int e = 0; e < 4; e++) O[mq][nb][e] = 0.f;
    float lp[2][2] = { {0.f, 0.f}, {0.f, 0.f} };

    for (int t = 0; t < 16; t++) {
        CP_WAIT(1);
        __syncthreads();   // data visibility for tile t AND orders compute(t-1) before prefetch below
        if (t + 2 < 16) {
            uint32_t base = KVb + (uint32_t)((t + 2) % 3) * 16384u;
            const int t0k = (t + 2) * 64;
            #pragma unroll
            for (int i = 0; i < 4; i++) {
                cp_async16(base + kvd[i],        K + gbase + (size_t)(t0k + kvr[i]) * DD + kvg[i] * 8);
                cp_async16(base + 8192 + kvd[i], V + gbase + (size_t)(t0k + kvr[i]) * DD + kvg[i] * 8);
            }
        }
        CP_COMMIT();

        if (t == 0) {
            #pragma unroll
            for (int mq = 0; mq < 2; mq++)
                #pragma unroll
                for (int kc = 0; kc < 4; kc++) {
                    int r = w * 32 + mq * 16 + (lane & 15);
                    int g = (kc * 2 + (lane >> 4)) ^ (r & 7);
                    ldm4(qa[mq][kc], Qb + r * 128 + (g << 4));
                }
        }
        const uint32_t Kb = KVb + (uint32_t)(t % 3) * 16384u;
        const uint32_t Vb = Kb + 8192u;

        // ---- S = Q @ K^T (K fragments shared across both q-row blocks) ----
        float sc[2][8][4];
        #pragma unroll
        for (int mq = 0; mq < 2; mq++)
            #pragma unroll
            for (int nb = 0; nb < 8; nb++)
                #pragma unroll
                for (int e = 0; e < 4; e++) sc[mq][nb][e] = 0.f;
        #pragma unroll
        for (int kc = 0; kc < 4; kc++) {
            #pragma unroll
            for (int ng = 0; ng < 4; ng++) {
                int n = ng * 16 + ((lane >> 4) & 1) * 8 + (lane & 7);
                int g = (kc * 2 + ((lane >> 3) & 1)) ^ (n & 7);
                uint32_t kb[4];
                ldm4(kb, Kb + n * 128 + (g << 4));
                #pragma unroll
                for (int mq = 0; mq < 2; mq++) {
                    mma16816(sc[mq][2 * ng],     qa[mq][kc], &kb[0]);
                    mma16816(sc[mq][2 * ng + 1], qa[mq][kc], &kb[2]);
                }
            }
        }

        // ---- fixed-base softmax: P = exp2(S), partial row sums only ----
        uint32_t pa[2][4][4];
        #pragma unroll
        for (int mq = 0; mq < 2; mq++)
            #pragma unroll
            for (int ng = 0; ng < 4; ng++) {
                float e00 = fast_exp2(sc[mq][2 * ng][0]),     e01 = fast_exp2(sc[mq][2 * ng][1]);
                float e02 = fast_exp2(sc[mq][2 * ng][2]),     e03 = fast_exp2(sc[mq][2 * ng][3]);
                float e10 = fast_exp2(sc[mq][2 * ng + 1][0]), e11 = fast_exp2(sc[mq][2 * ng + 1][1]);
                float e12 = fast_exp2(sc[mq][2 * ng + 1][2]), e13 = fast_exp2(sc[mq][2 * ng + 1][3]);
                lp[mq][0] += e00 + e01 + e10 + e11;
                lp[mq][1] += e02 + e03 + e12 + e13;
                pa[mq][ng][0] = pack_bf16x2(e00, e01);
                pa[mq][ng][1] = pack_bf16x2(e02, e03);
                pa[mq][ng][2] = pack_bf16x2(e10, e11);
                pa[mq][ng][3] = pack_bf16x2(e12, e13);
            }

        // ---- O += P @ V (V fragments shared across both q-row blocks) ----
        #pragma unroll
        for (int kc = 0; kc < 4; kc++) {
            #pragma unroll
            for (int ng = 0; ng < 4; ng++) {
                int r = kc * 16 + (lane & 15);
                int g = (ng * 2 + (lane >> 4)) ^ (r & 7);
                uint32_t vb[4];
                ldm4t(vb, Vb + r * 128 + (g << 4));
                #pragma unroll
                for (int mq = 0; mq < 2; mq++) {
                    mma16816(O[mq][2 * ng],     pa[mq][kc], &vb[0]);
                    mma16816(O[mq][2 * ng + 1], pa[mq][kc], &vb[2]);
                }
            }
        }
        // no trailing barrier: next iteration's top barrier orders compute(t) vs prefetch(t+3)
    }

    // ---- single end-of-loop l reduction + store ----
    #pragma unroll
    for (int mq = 0; mq < 2; mq++) {
        float l0 = lp[mq][0], l1 = lp[mq][1];
        l0 += __shfl_xor_sync(0xffffffffu, l0, 1);
        l0 += __shfl_xor_sync(0xffffffffu, l0, 2);
        l1 += __shfl_xor_sync(0xffffffffu, l1, 1);
        l1 += __shfl_xor_sync(0xffffffffu, l1, 2);
        float inv0 = 1.f / l0, inv1 = 1.f / l1;
        const int r0 = t0q + w * 32 + mq * 16 + (lane >> 2);
        #pragma unroll
        for (int nb = 0; nb < 8; nb++) {
            const int d = nb * 8 + (lane & 3) * 2;
            __nv_bfloat162 p0, p1;
            p0.x = __float2bfloat16(O[mq][nb][0] * inv0);
            p0.y = __float2bfloat16(O[mq][nb][1] * inv0);
            p1.x = __float2bfloat16(O[mq][nb][2] * inv1);
            p1.y = __float2bfloat16(O[mq][nb][3] * inv1);
            *(__nv_bfloat162*)&Y[gbase + (size_t)r0 * DD + d]       = p0;
            *(__nv_bfloat162*)&Y[gbase + (size_t)(r0 + 8) * DD + d] = p1;
        }
    }
}

// ===================== merged prologue: mod-GEMM (blocks 0..191) + all transposes (192..12479) =====================
// The two pieces touch disjoint data and are both DRAM-latency-bound -> run them concurrently
// in one launch instead of back-to-back.
__global__ void __launch_bounds__(256) prologue_kernel(
    const float* __restrict__ c, const float* __restrict__ w_mod,
    const float* __restrict__ b_mod, float* __restrict__ cmod,
    float* __restrict__ o_shift, float* __restrict__ o_scale, float* __restrict__ o_cact,
    const float* __restrict__ wq, const float* __restrict__ wk, const float* __restrict__ wv,
    const float* __restrict__ wattn, const float* __restrict__ wfc1, const float* __restrict__ wfc2,
    __nv_bfloat16* __restrict__ qkvt, __nv_bfloat16* __restrict__ wat,
    __nv_bfloat16* __restrict__ f1t, __nv_bfloat16* __restrict__ f2t)
{
    __shared__ __align__(16) char smu[40960];    // union: mod 40KB | transpose 4.2KB
    const int bid = blockIdx.x;
    const int tid = threadIdx.x;

    if (bid < 192) {
        // ---- cmod = silu(c) @ w_mod + b_mod ----
        float* sc = (float*)smu;                               // 32 KB
        float (*red)[32][8] = (float(*)[32][8])(smu + 32768);  // 8 KB
        for (int i = tid; i < BB * DD; i += 256) {
            float v = c[i];
            float sv = v / (1.f + expf(-v));
            sc[i] = sv;
            if (bid == 0) o_cact[i] = sv;
        }
        __syncthreads();

        int jl = tid & 31, ks = tid >> 5;
        int j = bid * 32 + jl;
        float acc[BB];
        #pragma unroll
        for (int b = 0; b < BB; b++) acc[b] = 0.f;

        int d0 = ks * 128;
        #pragma unroll 4
        for (int dd = 0; dd < 128; dd++) {
            int d = d0 + dd;
            float w = w_mod[(size_t)d * CMOD_N + j];
            #pragma unroll
            for (int b = 0; b < BB; b++) acc[b] = fmaf(sc[b * DD + d], w, acc[b]);
        }
        #pragma unroll
        for (int b = 0; b < BB; b++) red[ks][jl][b] = acc[b];
        __syncthreads();

        int b = ks;
        float s = 0.f;
        #pragma unroll
        for (int kk = 0; kk < 8; kk++) s += red[kk][jl][b];
        float v = s + b_mod[j];
        cmod[b * CMOD_N + j] = v;
        if (j < 1024)            o_shift[b * DD + j] = v;
        else if (j < 2048)       o_scale[b * DD + (j - 1024)] = v;
        return;
    }

    // ---- weight transposes ----
    float (*t)[33] = (float(*)[33])smu;
    int id = bid - 192;
    const float* W; __nv_bfloat16* Wt;
    int n0, k0, Nsrc, Kdst;
    if (id < 3072) {               // qkv: 96 n-tiles x 32 k-tiles
        int tx2 = id % 96, ty2 = id / 96;
        n0 = tx2 * 32; k0 = ty2 * 32;
        int buf = n0 >> 10;
        W = (buf == 0) ? wq : (buf == 1) ? wk : wv;
        Wt = qkvt;  Nsrc = DD; Kdst = DD;
        int nl0 = n0 & 1023;
        int txi = tid & 31, tyi = tid >> 5;
        #pragma unroll
        for (int r = tyi; r < 32; r += 8)
            t[r][txi] = W[(size_t)(k0 + r) * Nsrc + nl0 + txi];
        __syncthreads();
        #pragma unroll
        for (int r = tyi; r < 32; r += 8)
            Wt[(size_t)(n0 + r) * Kdst + k0 + txi] = __float2bfloat16(t[txi][r]);
        return;
    } else if (id < 4096) {        // w_attn: 32 x 32
        int lid2 = id - 3072;
        n0 = (lid2 % 32) * 32; k0 = (lid2 / 32) * 32;
        W = wattn; Wt = wat; Nsrc = DD; Kdst = DD;
    } else if (id < 8192) {        // fc1: [K=1024, N=4096] -> f1t[4096,1024]: 128 x 32
        int lid2 = id - 4096;
        n0 = (lid2 % 128) * 32; k0 = (lid2 / 128) * 32;
        W = wfc1; Wt = f1t; Nsrc = FF; Kdst = DD;
    } else {                       // fc2: [K=4096, N=1024] -> f2t[1024,4096]: 32 x 128
        int lid2 = id - 8192;
        n0 = (lid2 % 32) * 32; k0 = (lid2 / 32) * 32;
        W = wfc2; Wt = f2t; Nsrc = DD; Kdst = FF;
    }
    int txi = tid & 31, tyi = tid >> 5;
    #pragma unroll
    for (int r = tyi; r < 32; r += 8)
        t[r][txi] = W[(size_t)(k0 + r) * Nsrc + n0 + txi];
    __syncthreads();
    #pragma unroll
    for (int r = tyi; r < 32; r += 8)
        Wt[(size_t)(n0 + r) * Kdst + k0 + txi] = __float2bfloat16(t[txi][r]);
}

// ---------------- LayerNorm + modulate (warp-per-row; no block barriers, no smem) ----------------
__global__ void __launch_bounds__(256) ln_mod_kernel(
    const float* __restrict__ x, const float* __restrict__ cmod,
    float* __restrict__ xnorm, float* __restrict__ xmod, __nv_bfloat16* __restrict__ xmod_b,
    int shift_off, int scale_off)
{
    const int row = blockIdx.x * 8 + (threadIdx.x >> 5);
    const int lane = threadIdx.x & 31;
    const int b = row >> 10;
    const float4* xr = (const float4*)(x + (size_t)row * DD);

    float4 v[8];
    float s = 0.f;
    #pragma unroll
    for (int i = 0; i < 8; i++) {
        v[i] = xr[lane + i * 32];
        s += v[i].x + v[i].y + v[i].z + v[i].w;
    }
    #pragma unroll
    for (int o = 16; o > 0; o >>= 1) s += __shfl_xor_sync(0xffffffffu, s, o);
    const float mu = s * (1.f / DD);

    float s2 = 0.f;
    #pragma unroll
    for (int i = 0; i < 8; i++) {
        float d0 = v[i].x - mu, d1 = v[i].y - mu, d2 = v[i].z - mu, d3 = v[i].w - mu;
        s2 += d0 * d0 + d1 * d1 + d2 * d2 + d3 * d3;
    }
    #pragma unroll
    for (int o = 16; o > 0; o >>= 1) s2 += __shfl_xor_sync(0xffffffffu, s2, o);
    const float rstd = rsqrtf(s2 * (1.f / DD) + 1e-6f);

    const float4* shp = (const float4*)(cmod + b * CMOD_N + shift_off);
    const float4* slp = (const float4*)(cmod + b * CMOD_N + scale_off);
    #pragma unroll
    for (int i = 0; i < 8; i++) {
        const int idx = lane + i * 32;
        const float4 sh = shp[idx], sl = slp[idx];
        float4 xn = { (v[i].x - mu) * rstd, (v[i].y - mu) * rstd,
                      (v[i].z - mu) * rstd, (v[i].w - mu) * rstd };
        float4 xm = { xn.x * (1.f + sl.x) + sh.x, xn.y * (1.f + sl.y) + sh.y,
                      xn.z * (1.f + sl.z) + sh.z, xn.w * (1.f + sl.w) + sh.w };
        if (xnorm) stcs_f4(xnorm + (size_t)row * DD + idx * 4, xn);
        if (xmod)  stcs_f4(xmod  + (size_t)row * DD + idx * 4, xm);
        uint2 p = { pack_bf16x2(xm.x, xm.y), pack_bf16x2(xm.z, xm.w) };
        ((uint2*)(xmod_b + (size_t)row * DD))[idx] = p;
    }
}

// ---------------- launch ----------------
extern "C" void kernel_launch(void* const* d_in, const int* in_sizes, int n_in,
                              void* d_out, int out_size)
{
    const float* x      = (const float*)d_in[0];
    const float* c      = (const float*)d_in[1];
    const float* w_mod  = (const float*)d_in[2];
    const float* b_mod  = (const float*)d_in[3];
    const float* w_q    = (const float*)d_in[4];
    const float* b_q    = (const float*)d_in[5];
    const float* w_k    = (const float*)d_in[6];
    const float* b_k    = (const float*)d_in[7];
    const float* w_v    = (const float*)d_in[8];
    const float* b_v    = (const float*)d_in[9];
    const float* w_attn = (const float*)d_in[10];
    const float* b_attn = (const float*)d_in[11];
    const float* w_fc1  = (const float*)d_in[12];
    const float* b_fc1  = (const float*)d_in[13];
    const float* w_fc2  = (const float*)d_in[14];
    const float* b_fc2  = (const float*)d_in[15];

    float* out = (float*)d_out;
    float* o_xout  = out;                    // [8,1024,1024]
    float* o_xnorm = out + 8388608;          // [8,1024,1024]
    float* o_xmod  = out + 16777216;         // [8,1024,1024]
    float* o_shift = out + 25165824;         // [8,1024]
    float* o_scale = out + 25174016;         // [8,1024]
    float* o_cmod  = out + 25182208;         // [8,6144]
    float* o_cact  = out + 25231360;         // [8,1024]

    float *p_x1;
    __nv_bfloat16 *p_qb, *p_kb, *p_vb, *p_xmb, *p_xm2b, *p_yb, *p_hb;
    __nv_bfloat16 *p_wqkvt, *p_wat, *p_f1t, *p_f2t;
    cudaGetSymbolAddress((void**)&p_x1,    g_x1);
    cudaGetSymbolAddress((void**)&p_qb,    g_qb);
    cudaGetSymbolAddress((void**)&p_kb,    g_kb);
    cudaGetSymbolAddress((void**)&p_vb,    g_vb);
    cudaGetSymbolAddress((void**)&p_xmb,   g_xmod_b);
    cudaGetSymbolAddress((void**)&p_xm2b,  g_xm2_b);
    cudaGetSymbolAddress((void**)&p_yb,    g_y_b);
    cudaGetSymbolAddress((void**)&p_hb,    g_h_b);
    cudaGetSymbolAddress((void**)&p_wqkvt, g_wqkvt);
    cudaGetSymbolAddress((void**)&p_wat,   g_wat);
    cudaGetSymbolAddress((void**)&p_f1t,   g_wfc1t);
    cudaGetSymbolAddress((void**)&p_f2t,   g_wfc2t);

    cudaFuncSetAttribute(flash_mma, cudaFuncAttributeMaxDynamicSharedMemorySize, 65536);
    cudaFuncSetAttribute(mma_gemm<EPI_QKV3>, cudaFuncAttributeMaxDynamicSharedMemorySize, GEMM_SMEM);
    cudaFuncSetAttribute(mma_gemm<EPI_GATE>, cudaFuncAttributeMaxDynamicSharedMemorySize, GEMM_SMEM);
    cudaFuncSetAttribute(mma_gemm<EPI_GELU>, cudaFuncAttributeMaxDynamicSharedMemorySize, GEMM_SMEM);

    // 0) merged prologue: mod-GEMM + all weight transposes, concurrent
    prologue_kernel<<<192 + 12288, 256>>>(
        c, w_mod, b_mod, o_cmod, o_shift, o_scale, o_cact,
        w_q, w_k, w_v, w_attn, w_fc1, w_fc2,
        p_wqkvt, p_wat, p_f1t, p_f2t);

    // 1) LN1 + modulate
    ln_mod_kernel<<<MTOK / 8, 256>>>(x, o_cmod, o_xnorm, o_xmod, p_xmb, 0, 1024);

    // 2) fused QKV projection -> bf16 (q scaled by log2(e)/64 for exp2 softmax)
    dim3 gQKV(3 * DD / 128, MTOK / 128);   // (24, 64)
    mma_gemm<EPI_QKV3><<<gQKV, 256, GEMM_SMEM>>>(p_xmb, p_wqkvt, b_q, nullptr, p_qb, DD, DD, QSCALE,
                                      nullptr, nullptr, 0, p_kb, p_vb, b_k, b_v);

    // 3) attention on tensor cores (Br=128, mq=2: amortized K/V fragments)
    flash_mma<<<dim3(SS / 128, 16, BB), 128, 65536>>>(p_qb, p_kb, p_vb, p_yb);

    // 4) attn projection + residual with gate_msa
    dim3 gD(DD / 128, MTOK / 128);     // (8, 64)
    mma_gemm<EPI_GATE><<<gD, 256, GEMM_SMEM>>>(p_yb, p_wat, b_attn, p_x1, nullptr, DD, DD, 1.f,
                                    x, o_cmod, 2048, nullptr, nullptr, nullptr, nullptr);

    // 5) LN2 + modulate (bf16 only)
    ln_mod_kernel<<<MTOK / 8, 256>>>(p_x1, o_cmod, nullptr, nullptr, p_xm2b, 3072, 4096);

    // 6) MLP on tensor cores
    dim3 gF(FF / 128, MTOK / 128);     // (32, 64)
    mma_gemm<EPI_GELU><<<gF, 256, GEMM_SMEM>>>(p_xm2b, p_f1t, b_fc1, nullptr, p_hb, DD, FF, 1.f,
                                    nullptr, nullptr, 0, nullptr, nullptr, nullptr, nullptr);
    mma_gemm<EPI_GATE><<<gD, 256, GEMM_SMEM>>>(p_hb, p_f2t, b_fc2, o_xout, nullptr, FF, DD, 1.f,
                                    p_x1, o_cmod, 5120, nullptr, nullptr, nullptr, nullptr);
}

// round 12
// speedup vs baseline: 1.1142x; 1.0013x over previous
#include <cuda_runtime.h>
#include <cuda_bf16.h>
#include <math.h>
#include <cstdint>

// Problem dims (fixed by the dataset)
#define BB 8
#define SS 1024
#define DD 1024
#define FF 4096
#define MTOK (BB*SS)       // 8192
#define CMOD_N (6*DD)      // 6144

#define QSCALE 0.022542110013890053f   // log2(e) / 64

// -------- scratch (device globals; no allocation allowed) --------
__device__ float g_x1 [MTOK * DD];

__device__ __nv_bfloat16 g_qb  [MTOK * DD];
__device__ __nv_bfloat16 g_kb  [MTOK * DD];
__device__ __nv_bfloat16 g_vb  [MTOK * DD];
__device__ __nv_bfloat16 g_xmod_b[MTOK * DD];
__device__ __nv_bfloat16 g_xm2_b [MTOK * DD];
__device__ __nv_bfloat16 g_y_b   [MTOK * DD];
__device__ __nv_bfloat16 g_h_b   [(size_t)MTOK * FF];
__device__ __nv_bfloat16 g_wqkvt[3 * DD * DD];
__device__ __nv_bfloat16 g_wat  [DD * DD];
__device__ __nv_bfloat16 g_wfc1t[(size_t)FF * DD];
__device__ __nv_bfloat16 g_wfc2t[(size_t)DD * FF];

// ===================== PTX helpers (baseline ISA only — no tcgen05) =====================
__device__ __forceinline__ uint32_t smem_u32(const void* p) {
    uint32_t a;
    asm("{ .reg .u64 t; cvta.to.shared.u64 t, %1; cvt.u32.u64 %0, t; }" : "=r"(a) : "l"(p));
    return a;
}
__device__ __forceinline__ void cp_async16(uint32_t dst, const void* src) {
    asm volatile("cp.async.cg.shared.global [%0], [%1], 16;" :: "r"(dst), "l"(src));
}
#define CP_COMMIT() asm volatile("cp.async.commit_group;" ::: "memory")
#define CP_WAIT(n)  asm volatile("cp.async.wait_group %0;" :: "n"(n) : "memory")

__device__ __forceinline__ void ldm4(uint32_t* r, uint32_t addr) {
    asm volatile("ldmatrix.sync.aligned.m8n8.x4.shared.b16 {%0,%1,%2,%3}, [%4];"
        : "=r"(r[0]), "=r"(r[1]), "=r"(r[2]), "=r"(r[3]) : "r"(addr));
}
__device__ __forceinline__ void ldm4t(uint32_t* r, uint32_t addr) {
    asm volatile("ldmatrix.sync.aligned.m8n8.x4.trans.shared.b16 {%0,%1,%2,%3}, [%4];"
        : "=r"(r[0]), "=r"(r[1]), "=r"(r[2]), "=r"(r[3]) : "r"(addr));
}
__device__ __forceinline__ void mma16816(float* c, const uint32_t* a, const uint32_t* b) {
    asm volatile(
        "mma.sync.aligned.m16n8k16.row.col.f32.bf16.bf16.f32 "
        "{%0,%1,%2,%3}, {%4,%5,%6,%7}, {%8,%9}, {%0,%1,%2,%3};"
        : "+f"(c[0]), "+f"(c[1]), "+f"(c[2]), "+f"(c[3])
        : "r"(a[0]), "r"(a[1]), "r"(a[2]), "r"(a[3]), "r"(b[0]), "r"(b[1]));
}
__device__ __forceinline__ uint32_t pack_bf16x2(float lo, float hi) {
    uint32_t r;
    asm("cvt.rn.bf16x2.f32 %0, %1, %2;" : "=r"(r) : "f"(hi), "f"(lo));  // first operand -> upper half
    return r;
}
__device__ __forceinline__ float fast_exp2(float x) {
    float r;
    asm("ex2.approx.ftz.f32 %0, %1;" : "=f"(r) : "f"(x));
    return r;
}
__device__ __forceinline__ void stcs_f2(float* p, float2 v) {
    asm volatile("st.global.cs.v2.f32 [%0], {%1, %2};" :: "l"(p), "f"(v.x), "f"(v.y));
}
__device__ __forceinline__ void stcs_f4(float* p, float4 v) {
    asm volatile("st.global.cs.v4.f32 [%0], {%1, %2, %3, %4};"
        :: "l"(p), "f"(v.x), "f"(v.y), "f"(v.z), "f"(v.w));
}

// ===================== mma.sync GEMM: C[M x N] = A[M x K](bf16) @ Wt[N x K]^T =====================
// BM=128, BN=128. 256 threads (8 warps, warp tile 32x64) — the measured-best config.
// 6-stage cp.async (3 pairs of BK=32 chunks); one barrier per 64 K-elems.
enum { EPI_QKV3 = 0, EPI_GATE = 1, EPI_GELU = 2 };

#define CHUNK_BYTES 16384       // A 8KB + B 8KB per BK=32 chunk
#define PAIR_BYTES  32768
#define B_OFF 8192
#define GEMM_SMEM (3 * PAIR_BYTES)   // 96 KB

template <int EPI>
__global__ void __launch_bounds__(256) mma_gemm(
    const __nv_bfloat16* __restrict__ A, const __nv_bfloat16* __restrict__ Wt,
    const float* __restrict__ bias,
    float* __restrict__ outf, __nv_bfloat16* __restrict__ outb,
    int K, int N, float scale,
    const float* __restrict__ add_src, const float* __restrict__ cmod, int gate_off,
    __nv_bfloat16* __restrict__ outb2, __nv_bfloat16* __restrict__ outb3,
    const float* __restrict__ bias2, const float* __restrict__ bias3)
{
    extern __shared__ __align__(128) char smbuf[];   // 96 KB
    const uint32_t smb = smem_u32(smbuf);

    const int tid = threadIdx.x;
    const int lane = tid & 31, wid = tid >> 5;
    const int wm = wid & 3, wn = wid >> 2;      // 4 warps M x 2 warps N
    const int m0 = blockIdx.y * 128;
    const int n0 = blockIdx.x * 128;

    const int uA0 = tid, uA1 = tid + 256;
    const int rA0u = uA0 >> 2, gA0u = uA0 & 3;
    const int rA1u = uA1 >> 2, gA1u = uA1 & 3;
    const uint32_t dstA0 = (uint32_t)rA0u * 64u + (uint32_t)((gA0u ^ ((rA0u >> 1) & 3)) << 4);
    const uint32_t dstA1 = (uint32_t)rA1u * 64u + (uint32_t)((gA1u ^ ((rA1u >> 1) & 3)) << 4);
    const __nv_bfloat16* srcA0 = A + (size_t)(m0 + rA0u) * K + gA0u * 8;
    const __nv_bfloat16* srcA1 = A + (size_t)(m0 + rA1u) * K + gA1u * 8;
    const __nv_bfloat16* srcB0 = Wt + (size_t)(n0 + rA0u) * K + gA0u * 8;
    const __nv_bfloat16* srcB1 = Wt + (size_t)(n0 + rA1u) * K + gA1u * 8;

    const int npair = K >> 6;   // K / 64

    uint32_t aoff[2][2];
    {
        int r = wm * 32 + (lane & 15);
        int sw = (r >> 1) & 3;
        #pragma unroll
        for (int mt = 0; mt < 2; mt++)
            #pragma unroll
            for (int ks = 0; ks < 2; ks++)
                aoff[mt][ks] = (uint32_t)(r + mt * 16) * 64u +
                               (uint32_t)(((ks * 2 + (lane >> 4)) ^ sw) << 4);
    }
    uint32_t boff[4][2];
    {
        int n = wn * 64 + ((lane >> 4) & 1) * 8 + (lane & 7);
        int gpar = (lane >> 3) & 1;
        int sw = (n >> 1) & 3;
        #pragma unroll
        for (int np = 0; np < 4; np++)
            #pragma unroll
            for (int ks = 0; ks < 2; ks++)
                boff[np][ks] = (uint32_t)B_OFF + (uint32_t)(n + np * 16) * 64u +
                               (uint32_t)(((ks * 2 + gpar) ^ sw) << 4);
    }

    // prologue: pairs 0,1 (chunks 0..3), one commit group per pair
    #pragma unroll
    for (int s = 0; s < 2; s++) {
        uint32_t base = smb + (uint32_t)s * PAIR_BYTES;
        #pragma unroll
        for (int h = 0; h < 2; h++) {
            uint32_t cb = base + (uint32_t)h * CHUNK_BYTES;
            int ch = 2 * s + h;
            cp_async16(cb + dstA0,         srcA0 + ch * 32);
            cp_async16(cb + dstA1,         srcA1 + ch * 32);
            cp_async16(cb + B_OFF + dstA0, srcB0 + ch * 32);
            cp_async16(cb + B_OFF + dstA1, srcB1 + ch * 32);
        }
        CP_COMMIT();
    }

    float c[2][8][4];
    #pragma unroll
    for (int mt = 0; mt < 2; mt++)
        #pragma unroll
        for (int nt = 0; nt < 8; nt++)
            #pragma unroll
            for (int e = 0; e < 4; e++) c[mt][nt][e] = 0.f;

    for (int p = 0; p < npair; p++) {
        CP_WAIT(1);
        __syncthreads();
        if (p + 2 < npair) {
            uint32_t base = smb + (uint32_t)((p + 2) % 3) * PAIR_BYTES;
            #pragma unroll
            for (int h = 0; h < 2; h++) {
                uint32_t cb = base + (uint32_t)h * CHUNK_BYTES;
                int ch = 2 * (p + 2) + h;
                cp_async16(cb + dstA0,         srcA0 + ch * 32);
                cp_async16(cb + dstA1,         srcA1 + ch * 32);
                cp_async16(cb + B_OFF + dstA0, srcB0 + ch * 32);
                cp_async16(cb + B_OFF + dstA1, srcB1 + ch * 32);
            }
        }
        CP_COMMIT();

        const uint32_t sp = smb + (uint32_t)(p % 3) * PAIR_BYTES;
        #pragma unroll
        for (int h = 0; h < 2; h++) {
            const uint32_t st = sp + (uint32_t)h * CHUNK_BYTES;
            #pragma unroll
            for (int ks = 0; ks < 2; ks++) {
                uint32_t a[2][4];
                ldm4(a[0], st + aoff[0][ks]);
                ldm4(a[1], st + aoff[1][ks]);
                uint32_t b[8][2];
                #pragma unroll
                for (int np = 0; np < 4; np++) {
                    uint32_t r[4];
                    ldm4(r, st + boff[np][ks]);
                    b[2 * np][0] = r[0]; b[2 * np][1] = r[1];
                    b[2 * np + 1][0] = r[2]; b[2 * np + 1][1] = r[3];
                }
                #pragma unroll
                for (int mt = 0; mt < 2; mt++)
                    #pragma unroll
                    for (int nt = 0; nt < 8; nt++)
                        mma16816(c[mt][nt], a[mt], b[nt]);
            }
        }
    }

    // ---- epilogue ----
    __nv_bfloat16* qdst = nullptr;
    const float* bsel = bias;
    float scl = scale;
    if (EPI == EPI_QKV3) {
        int buf = n0 >> 10;
        qdst = (buf == 0) ? outb : (buf == 1) ? outb2 : outb3;
        bsel = (buf == 0) ? bias : (buf == 1) ? bias2 : bias3;
        scl  = (buf == 0) ? scale : 1.f;
    }
    const int lcol0 = n0 & 1023;

    #pragma unroll
    for (int mt = 0; mt < 2; mt++) {
        #pragma unroll
        for (int half = 0; half < 2; half++) {
            const int grow = m0 + wm * 32 + mt * 16 + (lane >> 2) + half * 8;
            const int b = grow >> 10;
            #pragma unroll
            for (int nt = 0; nt < 8; nt++) {
                const int coff = wn * 64 + nt * 8 + (lane & 3) * 2;
                if (EPI == EPI_QKV3) {
                    const int lcol = lcol0 + coff;
                    float v0 = (c[mt][nt][half * 2 + 0] + bsel[lcol]) * scl;
                    float v1 = (c[mt][nt][half * 2 + 1] + bsel[lcol + 1]) * scl;
                    __nv_bfloat162 pr;
                    pr.x = __float2bfloat16(v0);
                    pr.y = __float2bfloat16(v1);
                    *(__nv_bfloat162*)&qdst[(size_t)grow * DD + lcol] = pr;
                } else if (EPI == EPI_GATE) {
                    const int gcol = n0 + coff;
                    float v0 = c[mt][nt][half * 2 + 0] + bias[gcol];
                    float v1 = c[mt][nt][half * 2 + 1] + bias[gcol + 1];
                    const float* gp = cmod + b * CMOD_N + gate_off + gcol;
                    const float* ap = add_src + (size_t)grow * N + gcol;
                    float2 o = { ap[0] + gp[0] * v0, ap[1] + gp[1] * v1 };
                    if (gate_off == 5120)   // final x_out: write-only -> streaming store
                        stcs_f2(&outf[(size_t)grow * N + gcol], o);
                    else
                        *(float2*)&outf[(size_t)grow * N + gcol] = o;
                } else {   // EPI_GELU -> bf16
                    const int gcol = n0 + coff;
                    float v0 = c[mt][nt][half * 2 + 0] + bias[gcol];
                    float v1 = c[mt][nt][half * 2 + 1] + bias[gcol + 1];
                    float g0 = 0.5f * v0 * (1.f + erff(v0 * 0.70710678118654752f));
                    float g1 = 0.5f * v1 * (1.f + erff(v1 * 0.70710678118654752f));
                    __nv_bfloat162 pr;
                    pr.x = __float2bfloat16(g0);
                    pr.y = __float2bfloat16(g1);
                    *(__nv_bfloat162*)&outb[(size_t)grow * N + gcol] = pr;
                }
            }
        }
    }
}

// ===================== Flash attention on mma.sync (bf16 in/out, fixed-base exp2 softmax) =====================
// Br=128, Bc=64, Dh=64. 128 threads = 4 warps, each owning 32 q-rows (mq=2).
// __launch_bounds__(128, 3): cap regs at 170 so 3 CTAs fit per SM's register file
// (at 173 regs only 2 fit — we were 3 registers over the occupancy cliff).
__global__ void __launch_bounds__(128, 3) flash_mma(
    const __nv_bfloat16* __restrict__ Q, const __nv_bfloat16* __restrict__ K,
    const __nv_bfloat16* __restrict__ V, __nv_bfloat16* __restrict__ Y)
{
    extern __shared__ __align__(128) char smbuf[];   // Q 16KB + 3 x (K 8KB + V 8KB) = 64KB
    const uint32_t Qb  = smem_u32(smbuf);
    const uint32_t KVb = Qb + 16384;

    const int tid = threadIdx.x, lane = tid & 31, w = tid >> 5;
    const int qt = blockIdx.x, h = blockIdx.y, b = blockIdx.z;
    const size_t gbase = ((size_t)b * SS) * DD + h * 64;
    const int t0q = qt * 128;

    // --- Q load (16KB = 1024 x 16B units, 8/thread) ---
    #pragma unroll
    for (int i = 0; i < 8; i++) {
        int u = tid + i * 128;
        int r = u >> 3, g = u & 7;
        cp_async16(Qb + r * 128 + ((g ^ (r & 7)) << 4),
                   Q + gbase + (size_t)(t0q + r) * DD + g * 8);
    }
    // --- KV tile loader: per operand 512 units, 4/thread ---
    int kvr[4], kvg[4];
    uint32_t kvd[4];
    #pragma unroll
    for (int i = 0; i < 4; i++) {
        int u = tid + i * 128;
        kvr[i] = u >> 3; kvg[i] = u & 7;
        kvd[i] = (uint32_t)kvr[i] * 128u + (uint32_t)((kvg[i] ^ (kvr[i] & 7)) << 4);
    }

    #pragma unroll
    for (int s = 0; s < 2; s++) {   // tiles 0,1 -> stages 0,1 (tile 0 shares group with Q)
        uint32_t base = KVb + (uint32_t)s * 16384u;
        #pragma unroll
        for (int i = 0; i < 4; i++) {
            cp_async16(base + kvd[i],        K + gbase + (size_t)(s * 64 + kvr[i]) * DD + kvg[i] * 8);
            cp_async16(base + 8192 + kvd[i], V + gbase + (size_t)(s * 64 + kvr[i]) * DD + kvg[i] * 8);
        }
        CP_COMMIT();
    }

    uint32_t qa[2][4][4];
    float O[2][8][4];
    #pragma unroll
    for (int mq = 0; mq < 2; mq++)
        #pragma unroll
        for (int nb = 0; nb < 8; nb++)
            #pragma unroll
            for (int e = 0; e < 4; e++) O[mq][nb][e] = 0.f;
    float lp[2][2] = { {0.f, 0.f}, {0.f, 0.f} };

    for (int t = 0; t < 16; t++) {
        CP_WAIT(1);
        __syncthreads();   // data visibility for tile t AND orders compute(t-1) before prefetch below
        if (t + 2 < 16) {
            uint32_t base = KVb + (uint32_t)((t + 2) % 3) * 16384u;
            const int t0k = (t + 2) * 64;
            #pragma unroll
            for (int i = 0; i < 4; i++) {
                cp_async16(base + kvd[i],        K + gbase + (size_t)(t0k + kvr[i]) * DD + kvg[i] * 8);
                cp_async16(base + 8192 + kvd[i], V + gbase + (size_t)(t0k + kvr[i]) * DD + kvg[i] * 8);
            }
        }
        CP_COMMIT();

        if (t == 0) {
            #pragma unroll
            for (int mq = 0; mq < 2; mq++)
                #pragma unroll
                for (int kc = 0; kc < 4; kc++) {
                    int r = w * 32 + mq * 16 + (lane & 15);
                    int g = (kc * 2 + (lane >> 4)) ^ (r & 7);
                    ldm4(qa[mq][kc], Qb + r * 128 + (g << 4));
                }
        }
        const uint32_t Kb = KVb + (uint32_t)(t % 3) * 16384u;
        const uint32_t Vb = Kb + 8192u;

        // ---- S = Q @ K^T (K fragments shared across both q-row blocks) ----
        float sc[2][8][4];
        #pragma unroll
        for (int mq = 0; mq < 2; mq++)
            #pragma unroll
            for (int nb = 0; nb < 8; nb++)
                #pragma unroll
                for (int e = 0; e < 4; e++) sc[mq][nb][e] = 0.f;
        #pragma unroll
        for (int kc = 0; kc < 4; kc++) {
            #pragma unroll
            for (int ng = 0; ng < 4; ng++) {
                int n = ng * 16 + ((lane >> 4) & 1) * 8 + (lane & 7);
                int g = (kc * 2 + ((lane >> 3) & 1)) ^ (n & 7);
                uint32_t kb[4];
                ldm4(kb, Kb + n * 128 + (g << 4));
                #pragma unroll
                for (int mq = 0; mq < 2; mq++) {
                    mma16816(sc[mq][2 * ng],     qa[mq][kc], &kb[0]);
                    mma16816(sc[mq][2 * ng + 1], qa[mq][kc], &kb[2]);
                }
            }
        }

        // ---- fixed-base softmax: P = exp2(S), partial row sums only ----
        uint32_t pa[2][4][4];
        #pragma unroll
        for (int mq = 0; mq < 2; mq++)
            #pragma unroll
            for (int ng = 0; ng < 4; ng++) {
                float e00 = fast_exp2(sc[mq][2 * ng][0]),     e01 = fast_exp2(sc[mq][2 * ng][1]);
                float e02 = fast_exp2(sc[mq][2 * ng][2]),     e03 = fast_exp2(sc[mq][2 * ng][3]);
                float e10 = fast_exp2(sc[mq][2 * ng + 1][0]), e11 = fast_exp2(sc[mq][2 * ng + 1][1]);
                float e12 = fast_exp2(sc[mq][2 * ng + 1][2]), e13 = fast_exp2(sc[mq][2 * ng + 1][3]);
                lp[mq][0] += e00 + e01 + e10 + e11;
                lp[mq][1] += e02 + e03 + e12 + e13;
                pa[mq][ng][0] = pack_bf16x2(e00, e01);
                pa[mq][ng][1] = pack_bf16x2(e02, e03);
                pa[mq][ng][2] = pack_bf16x2(e10, e11);
                pa[mq][ng][3] = pack_bf16x2(e12, e13);
            }

        // ---- O += P @ V (V fragments shared across both q-row blocks) ----
        #pragma unroll
        for (int kc = 0; kc < 4; kc++) {
            #pragma unroll
            for (int ng = 0; ng < 4; ng++) {
                int r = kc * 16 + (lane & 15);
                int g = (ng * 2 + (lane >> 4)) ^ (r & 7);
                uint32_t vb[4];
                ldm4t(vb, Vb + r * 128 + (g << 4));
                #pragma unroll
                for (int mq = 0; mq < 2; mq++) {
                    mma16816(O[mq][2 * ng],     pa[mq][kc], &vb[0]);
                    mma16816(O[mq][2 * ng + 1], pa[mq][kc], &vb[2]);
                }
            }
        }
        // no trailing barrier: next iteration's top barrier orders compute(t) vs prefetch(t+3)
    }

    // ---- single end-of-loop l reduction + store ----
    #pragma unroll
    for (int mq = 0; mq < 2; mq++) {
        float l0 = lp[mq][0], l1 = lp[mq][1];
        l0 += __shfl_xor_sync(0xffffffffu, l0, 1);
        l0 += __shfl_xor_sync(0xffffffffu, l0, 2);
        l1 += __shfl_xor_sync(0xffffffffu, l1, 1);
        l1 += __shfl_xor_sync(0xffffffffu, l1, 2);
        float inv0 = 1.f / l0, inv1 = 1.f / l1;
        const int r0 = t0q + w * 32 + mq * 16 + (lane >> 2);
        #pragma unroll
        for (int nb = 0; nb < 8; nb++) {
            const int d = nb * 8 + (lane & 3) * 2;
            __nv_bfloat162 p0, p1;
            p0.x = __float2bfloat16(O[mq][nb][0] * inv0);
            p0.y = __float2bfloat16(O[mq][nb][1] * inv0);
            p1.x = __float2bfloat16(O[mq][nb][2] * inv1);
            p1.y = __float2bfloat16(O[mq][nb][3] * inv1);
            *(__nv_bfloat162*)&Y[gbase + (size_t)r0 * DD + d]       = p0;
            *(__nv_bfloat162*)&Y[gbase + (size_t)(r0 + 8) * DD + d] = p1;
        }
    }
}

// ===================== merged prologue: mod-GEMM (blocks 0..191) + all transposes (192..12479) =====================
__global__ void __launch_bounds__(256) prologue_kernel(
    const float* __restrict__ c, const float* __restrict__ w_mod,
    const float* __restrict__ b_mod, float* __restrict__ cmod,
    float* __restrict__ o_shift, float* __restrict__ o_scale, float* __restrict__ o_cact,
    const float* __restrict__ wq, const float* __restrict__ wk, const float* __restrict__ wv,
    const float* __restrict__ wattn, const float* __restrict__ wfc1, const float* __restrict__ wfc2,
    __nv_bfloat16* __restrict__ qkvt, __nv_bfloat16* __restrict__ wat,
    __nv_bfloat16* __restrict__ f1t, __nv_bfloat16* __restrict__ f2t)
{
    __shared__ __align__(16) char smu[40960];    // union: mod 40KB | transpose 4.2KB
    const int bid = blockIdx.x;
    const int tid = threadIdx.x;

    if (bid < 192) {
        // ---- cmod = silu(c) @ w_mod + b_mod ----
        float* sc = (float*)smu;                               // 32 KB
        float (*red)[32][8] = (float(*)[32][8])(smu + 32768);  // 8 KB
        for (int i = tid; i < BB * DD; i += 256) {
            float v = c[i];
            float sv = v / (1.f + expf(-v));
            sc[i] = sv;
            if (bid == 0) o_cact[i] = sv;
        }
        __syncthreads();

        int jl = tid & 31, ks = tid >> 5;
        int j = bid * 32 + jl;
        float acc[BB];
        #pragma unroll
        for (int b = 0; b < BB; b++) acc[b] = 0.f;

        int d0 = ks * 128;
        #pragma unroll 4
        for (int dd = 0; dd < 128; dd++) {
            int d = d0 + dd;
            float w = w_mod[(size_t)d * CMOD_N + j];
            #pragma unroll
            for (int b = 0; b < BB; b++) acc[b] = fmaf(sc[b * DD + d], w, acc[b]);
        }
        #pragma unroll
        for (int b = 0; b < BB; b++) red[ks][jl][b] = acc[b];
        __syncthreads();

        int b = ks;
        float s = 0.f;
        #pragma unroll
        for (int kk = 0; kk < 8; kk++) s += red[kk][jl][b];
        float v = s + b_mod[j];
        cmod[b * CMOD_N + j] = v;
        if (j < 1024)            o_shift[b * DD + j] = v;
        else if (j < 2048)       o_scale[b * DD + (j - 1024)] = v;
        return;
    }

    // ---- weight transposes ----
    float (*t)[33] = (float(*)[33])smu;
    int id = bid - 192;
    const float* W; __nv_bfloat16* Wt;
    int n0, k0, Nsrc, Kdst;
    if (id < 3072) {               // qkv: 96 n-tiles x 32 k-tiles
        int tx2 = id % 96, ty2 = id / 96;
        n0 = tx2 * 32; k0 = ty2 * 32;
        int buf = n0 >> 10;
        W = (buf == 0) ? wq : (buf == 1) ? wk : wv;
        Wt = qkvt;  Nsrc = DD; Kdst = DD;
        int nl0 = n0 & 1023;
        int txi = tid & 31, tyi = tid >> 5;
        #pragma unroll
        for (int r = tyi; r < 32; r += 8)
            t[r][txi] = W[(size_t)(k0 + r) * Nsrc + nl0 + txi];
        __syncthreads();
        #pragma unroll
        for (int r = tyi; r < 32; r += 8)
            Wt[(size_t)(n0 + r) * Kdst + k0 + txi] = __float2bfloat16(t[txi][r]);
        return;
    } else if (id < 4096) {        // w_attn: 32 x 32
        int lid2 = id - 3072;
        n0 = (lid2 % 32) * 32; k0 = (lid2 / 32) * 32;
        W = wattn; Wt = wat; Nsrc = DD; Kdst = DD;
    } else if (id < 8192) {        // fc1: [K=1024, N=4096] -> f1t[4096,1024]: 128 x 32
        int lid2 = id - 4096;
        n0 = (lid2 % 128) * 32; k0 = (lid2 / 128) * 32;
        W = wfc1; Wt = f1t; Nsrc = FF; Kdst = DD;
    } else {                       // fc2: [K=4096, N=1024] -> f2t[1024,4096]: 32 x 128
        int lid2 = id - 8192;
        n0 = (lid2 % 32) * 32; k0 = (lid2 / 32) * 32;
        W = wfc2; Wt = f2t; Nsrc = DD; Kdst = FF;
    }
    int txi = tid & 31, tyi = tid >> 5;
    #pragma unroll
    for (int r = tyi; r < 32; r += 8)
        t[r][txi] = W[(size_t)(k0 + r) * Nsrc + n0 + txi];
    __syncthreads();
    #pragma unroll
    for (int r = tyi; r < 32; r += 8)
        Wt[(size_t)(n0 + r) * Kdst + k0 + txi] = __float2bfloat16(t[txi][r]);
}

// ---------------- LayerNorm + modulate (warp-per-row; no block barriers, no smem) ----------------
__global__ void __launch_bounds__(256) ln_mod_kernel(
    const float* __restrict__ x, const float* __restrict__ cmod,
    float* __restrict__ xnorm, float* __restrict__ xmod, __nv_bfloat16* __restrict__ xmod_b,
    int shift_off, int scale_off)
{
    const int row = blockIdx.x * 8 + (threadIdx.x >> 5);
    const int lane = threadIdx.x & 31;
    const int b = row >> 10;
    const float4* xr = (const float4*)(x + (size_t)row * DD);

    float4 v[8];
    float s = 0.f;
    #pragma unroll
    for (int i = 0; i < 8; i++) {
        v[i] = xr[lane + i * 32];
        s += v[i].x + v[i].y + v[i].z + v[i].w;
    }
    #pragma unroll
    for (int o = 16; o > 0; o >>= 1) s += __shfl_xor_sync(0xffffffffu, s, o);
    const float mu = s * (1.f / DD);

    float s2 = 0.f;
    #pragma unroll
    for (int i = 0; i < 8; i++) {
        float d0 = v[i].x - mu, d1 = v[i].y - mu, d2 = v[i].z - mu, d3 = v[i].w - mu;
        s2 += d0 * d0 + d1 * d1 + d2 * d2 + d3 * d3;
    }
    #pragma unroll
    for (int o = 16; o > 0; o >>= 1) s2 += __shfl_xor_sync(0xffffffffu, s2, o);
    const float rstd = rsqrtf(s2 * (1.f / DD) + 1e-6f);

    const float4* shp = (const float4*)(cmod + b * CMOD_N + shift_off);
    const float4* slp = (const float4*)(cmod + b * CMOD_N + scale_off);
    #pragma unroll
    for (int i = 0; i < 8; i++) {
        const int idx = lane + i * 32;
        const float4 sh = shp[idx], sl = slp[idx];
        float4 xn = { (v[i].x - mu) * rstd, (v[i].y - mu) * rstd,
                      (v[i].z - mu) * rstd, (v[i].w - mu) * rstd };
        float4 xm = { xn.x * (1.f + sl.x) + sh.x, xn.y * (1.f + sl.y) + sh.y,
                      xn.z * (1.f + sl.z) + sh.z, xn.w * (1.f + sl.w) + sh.w };
        if (xnorm) stcs_f4(xnorm + (size_t)row * DD + idx * 4, xn);
        if (xmod)  stcs_f4(xmod  + (size_t)row * DD + idx * 4, xm);
        uint2 p = { pack_bf16x2(xm.x, xm.y), pack_bf16x2(xm.z, xm.w) };
        ((uint2*)(xmod_b + (size_t)row * DD))[idx] = p;
    }
}

// ---------------- launch ----------------
extern "C" void kernel_launch(void* const* d_in, const int* in_sizes, int n_in,
                              void* d_out, int out_size)
{
    const float* x      = (const float*)d_in[0];
    const float* c      = (const float*)d_in[1];
    const float* w_mod  = (const float*)d_in[2];
    const float* b_mod  = (const float*)d_in[3];
    const float* w_q    = (const float*)d_in[4];
    const float* b_q    = (const float*)d_in[5];
    const float* w_k    = (const float*)d_in[6];
    const float* b_k    = (const float*)d_in[7];
    const float* w_v    = (const float*)d_in[8];
    const float* b_v    = (const float*)d_in[9];
    const float* w_attn = (const float*)d_in[10];
    const float* b_attn = (const float*)d_in[11];
    const float* w_fc1  = (const float*)d_in[12];
    const float* b_fc1  = (const float*)d_in[13];
    const float* w_fc2  = (const float*)d_in[14];
    const float* b_fc2  = (const float*)d_in[15];

    float* out = (float*)d_out;
    float* o_xout  = out;                    // [8,1024,1024]
    float* o_xnorm = out + 8388608;          // [8,1024,1024]
    float* o_xmod  = out + 16777216;         // [8,1024,1024]
    float* o_shift = out + 25165824;         // [8,1024]
    float* o_scale = out + 25174016;         // [8,1024]
    float* o_cmod  = out + 25182208;         // [8,6144]
    float* o_cact  = out + 25231360;         // [8,1024]

    float *p_x1;
    __nv_bfloat16 *p_qb, *p_kb, *p_vb, *p_xmb, *p_xm2b, *p_yb, *p_hb;
    __nv_bfloat16 *p_wqkvt, *p_wat, *p_f1t, *p_f2t;
    cudaGetSymbolAddress((void**)&p_x1,    g_x1);
    cudaGetSymbolAddress((void**)&p_qb,    g_qb);
    cudaGetSymbolAddress((void**)&p_kb,    g_kb);
    cudaGetSymbolAddress((void**)&p_vb,    g_vb);
    cudaGetSymbolAddress((void**)&p_xmb,   g_xmod_b);
    cudaGetSymbolAddress((void**)&p_xm2b,  g_xm2_b);
    cudaGetSymbolAddress((void**)&p_yb,    g_y_b);
    cudaGetSymbolAddress((void**)&p_hb,    g_h_b);
    cudaGetSymbolAddress((void**)&p_wqkvt, g_wqkvt);
    cudaGetSymbolAddress((void**)&p_wat,   g_wat);
    cudaGetSymbolAddress((void**)&p_f1t,   g_wfc1t);
    cudaGetSymbolAddress((void**)&p_f2t,   g_wfc2t);

    cudaFuncSetAttribute(flash_mma, cudaFuncAttributeMaxDynamicSharedMemorySize, 65536);
    cudaFuncSetAttribute(mma_gemm<EPI_QKV3>, cudaFuncAttributeMaxDynamicSharedMemorySize, GEMM_SMEM);
    cudaFuncSetAttribute(mma_gemm<EPI_GATE>, cudaFuncAttributeMaxDynamicSharedMemorySize, GEMM_SMEM);
    cudaFuncSetAttribute(mma_gemm<EPI_GELU>, cudaFuncAttributeMaxDynamicSharedMemorySize, GEMM_SMEM);

    // 0) merged prologue: mod-GEMM + all weight transposes, concurrent
    prologue_kernel<<<192 + 12288, 256>>>(
        c, w_mod, b_mod, o_cmod, o_shift, o_scale, o_cact,
        w_q, w_k, w_v, w_attn, w_fc1, w_fc2,
        p_wqkvt, p_wat, p_f1t, p_f2t);

    // 1) LN1 + modulate
    ln_mod_kernel<<<MTOK / 8, 256>>>(x, o_cmod, o_xnorm, o_xmod, p_xmb, 0, 1024);

    // 2) fused QKV projection -> bf16 (q scaled by log2(e)/64 for exp2 softmax)
    dim3 gQKV(3 * DD / 128, MTOK / 128);   // (24, 64)
    mma_gemm<EPI_QKV3><<<gQKV, 256, GEMM_SMEM>>>(p_xmb, p_wqkvt, b_q, nullptr, p_qb, DD, DD, QSCALE,
                                      nullptr, nullptr, 0, p_kb, p_vb, b_k, b_v);

    // 3) attention on tensor cores (Br=128, mq=2; 3 CTAs/SM)
    flash_mma<<<dim3(SS / 128, 16, BB), 128, 65536>>>(p_qb, p_kb, p_vb, p_yb);

    // 4) attn projection + residual with gate_msa
    dim3 gD(DD / 128, MTOK / 128);     // (8, 64)
    mma_gemm<EPI_GATE><<<gD, 256, GEMM_SMEM>>>(p_yb, p_wat, b_attn, p_x1, nullptr, DD, DD, 1.f,
                                    x, o_cmod, 2048, nullptr, nullptr, nullptr, nullptr);

    // 5) LN2 + modulate (bf16 only)
    ln_mod_kernel<<<MTOK / 8, 256>>>(p_x1, o_cmod, nullptr, nullptr, p_xm2b, 3072, 4096);

    // 6) MLP on tensor cores
    dim3 gF(FF / 128, MTOK / 128);     // (32, 64)
    mma_gemm<EPI_GELU><<<gF, 256, GEMM_SMEM>>>(p_xm2b, p_f1t, b_fc1, nullptr, p_hb, DD, FF, 1.f,
                                    nullptr, nullptr, 0, nullptr, nullptr, nullptr, nullptr);
    mma_gemm<EPI_GATE><<<gD, 256, GEMM_SMEM>>>(p_hb, p_f2t, b_fc2, o_xout, nullptr, FF, DD, 1.f,
                                    p_x1, o_cmod, 5120, nullptr, nullptr, nullptr, nullptr);
}

// round 13
// speedup vs baseline: 1.1274x; 1.0119x over previous
#include <cuda_runtime.h>
#include <cuda_bf16.h>
#include <math.h>
#include <cstdint>

// Problem dims (fixed by the dataset)
#define BB 8
#define SS 1024
#define DD 1024
#define FF 4096
#define MTOK (BB*SS)       // 8192
#define CMOD_N (6*DD)      // 6144

#define QSCALE 0.022542110013890053f   // log2(e) / 64

// -------- scratch (device globals; no allocation allowed) --------
__device__ float g_x1 [MTOK * DD];

__device__ __nv_bfloat16 g_qb  [MTOK * DD];
__device__ __nv_bfloat16 g_kb  [MTOK * DD];
__device__ __nv_bfloat16 g_vb  [MTOK * DD];
__device__ __nv_bfloat16 g_xmod_b[MTOK * DD];
__device__ __nv_bfloat16 g_xm2_b [MTOK * DD];
__device__ __nv_bfloat16 g_y_b   [MTOK * DD];
__device__ __nv_bfloat16 g_h_b   [(size_t)MTOK * FF];
__device__ __nv_bfloat16 g_wqkvt[3 * DD * DD];
__device__ __nv_bfloat16 g_wat  [DD * DD];
__device__ __nv_bfloat16 g_wfc1t[(size_t)FF * DD];
__device__ __nv_bfloat16 g_wfc2t[(size_t)DD * FF];

// ===================== PTX helpers (baseline ISA only — no tcgen05) =====================
__device__ __forceinline__ uint32_t smem_u32(const void* p) {
    uint32_t a;
    asm("{ .reg .u64 t; cvta.to.shared.u64 t, %1; cvt.u32.u64 %0, t; }" : "=r"(a) : "l"(p));
    return a;
}
__device__ __forceinline__ void cp_async16(uint32_t dst, const void* src) {
    asm volatile("cp.async.cg.shared.global [%0], [%1], 16;" :: "r"(dst), "l"(src));
}
#define CP_COMMIT() asm volatile("cp.async.commit_group;" ::: "memory")
#define CP_WAIT(n)  asm volatile("cp.async.wait_group %0;" :: "n"(n) : "memory")

__device__ __forceinline__ void ldm4(uint32_t* r, uint32_t addr) {
    asm volatile("ldmatrix.sync.aligned.m8n8.x4.shared.b16 {%0,%1,%2,%3}, [%4];"
        : "=r"(r[0]), "=r"(r[1]), "=r"(r[2]), "=r"(r[3]) : "r"(addr));
}
__device__ __forceinline__ void ldm4t(uint32_t* r, uint32_t addr) {
    asm volatile("ldmatrix.sync.aligned.m8n8.x4.trans.shared.b16 {%0,%1,%2,%3}, [%4];"
        : "=r"(r[0]), "=r"(r[1]), "=r"(r[2]), "=r"(r[3]) : "r"(addr));
}
__device__ __forceinline__ void mma16816(float* c, const uint32_t* a, const uint32_t* b) {
    asm volatile(
        "mma.sync.aligned.m16n8k16.row.col.f32.bf16.bf16.f32 "
        "{%0,%1,%2,%3}, {%4,%5,%6,%7}, {%8,%9}, {%0,%1,%2,%3};"
        : "+f"(c[0]), "+f"(c[1]), "+f"(c[2]), "+f"(c[3])
        : "r"(a[0]), "r"(a[1]), "r"(a[2]), "r"(a[3]), "r"(b[0]), "r"(b[1]));
}
__device__ __forceinline__ uint32_t pack_bf16x2(float lo, float hi) {
    uint32_t r;
    asm("cvt.rn.bf16x2.f32 %0, %1, %2;" : "=r"(r) : "f"(hi), "f"(lo));  // first operand -> upper half
    return r;
}
__device__ __forceinline__ float fast_exp2(float x) {
    float r;
    asm("ex2.approx.ftz.f32 %0, %1;" : "=f"(r) : "f"(x));
    return r;
}
__device__ __forceinline__ void stcs_f2(float* p, float2 v) {
    asm volatile("st.global.cs.v2.f32 [%0], {%1, %2};" :: "l"(p), "f"(v.x), "f"(v.y));
}
__device__ __forceinline__ void stcs_f4(float* p, float4 v) {
    asm volatile("st.global.cs.v4.f32 [%0], {%1, %2, %3, %4};"
        :: "l"(p), "f"(v.x), "f"(v.y), "f"(v.z), "f"(v.w));
}

// ===================== mma.sync GEMM: C[M x N] = A[M x K](bf16) @ Wt[N x K]^T =====================
// BM=128, BN=128. 256 threads (8 warps, warp tile 32x64).
// 6-stage cp.async (3 pairs of BK=32 chunks); one barrier per 64 K-elems.
// Inner loop interleaves B-fragment ldmatrix with MMAs (2-deep register ring, no extra regs)
// so LDSM latency is covered by same-warp HMMA instead of bursting load/compute phases.
enum { EPI_QKV3 = 0, EPI_GATE = 1, EPI_GELU = 2 };

#define CHUNK_BYTES 16384       // A 8KB + B 8KB per BK=32 chunk
#define PAIR_BYTES  32768
#define B_OFF 8192
#define GEMM_SMEM (3 * PAIR_BYTES)   // 96 KB

template <int EPI>
__global__ void __launch_bounds__(256) mma_gemm(
    const __nv_bfloat16* __restrict__ A, const __nv_bfloat16* __restrict__ Wt,
    const float* __restrict__ bias,
    float* __restrict__ outf, __nv_bfloat16* __restrict__ outb,
    int K, int N, float scale,
    const float* __restrict__ add_src, const float* __restrict__ cmod, int gate_off,
    __nv_bfloat16* __restrict__ outb2, __nv_bfloat16* __restrict__ outb3,
    const float* __restrict__ bias2, const float* __restrict__ bias3)
{
    extern __shared__ __align__(128) char smbuf[];   // 96 KB
    const uint32_t smb = smem_u32(smbuf);

    const int tid = threadIdx.x;
    const int lane = tid & 31, wid = tid >> 5;
    const int wm = wid & 3, wn = wid >> 2;      // 4 warps M x 2 warps N
    const int m0 = blockIdx.y * 128;
    const int n0 = blockIdx.x * 128;

    const int uA0 = tid, uA1 = tid + 256;
    const int rA0u = uA0 >> 2, gA0u = uA0 & 3;
    const int rA1u = uA1 >> 2, gA1u = uA1 & 3;
    const uint32_t dstA0 = (uint32_t)rA0u * 64u + (uint32_t)((gA0u ^ ((rA0u >> 1) & 3)) << 4);
    const uint32_t dstA1 = (uint32_t)rA1u * 64u + (uint32_t)((gA1u ^ ((rA1u >> 1) & 3)) << 4);
    const __nv_bfloat16* srcA0 = A + (size_t)(m0 + rA0u) * K + gA0u * 8;
    const __nv_bfloat16* srcA1 = A + (size_t)(m0 + rA1u) * K + gA1u * 8;
    const __nv_bfloat16* srcB0 = Wt + (size_t)(n0 + rA0u) * K + gA0u * 8;
    const __nv_bfloat16* srcB1 = Wt + (size_t)(n0 + rA1u) * K + gA1u * 8;

    const int npair = K >> 6;   // K / 64

    uint32_t aoff[2][2];
    {
        int r = wm * 32 + (lane & 15);
        int sw = (r >> 1) & 3;
        #pragma unroll
        for (int mt = 0; mt < 2; mt++)
            #pragma unroll
            for (int ks = 0; ks < 2; ks++)
                aoff[mt][ks] = (uint32_t)(r + mt * 16) * 64u +
                               (uint32_t)(((ks * 2 + (lane >> 4)) ^ sw) << 4);
    }
    uint32_t boff[4][2];
    {
        int n = wn * 64 + ((lane >> 4) & 1) * 8 + (lane & 7);
        int gpar = (lane >> 3) & 1;
        int sw = (n >> 1) & 3;
        #pragma unroll
        for (int np = 0; np < 4; np++)
            #pragma unroll
            for (int ks = 0; ks < 2; ks++)
                boff[np][ks] = (uint32_t)B_OFF + (uint32_t)(n + np * 16) * 64u +
                               (uint32_t)(((ks * 2 + gpar) ^ sw) << 4);
    }

    // prologue: pairs 0,1 (chunks 0..3), one commit group per pair
    #pragma unroll
    for (int s = 0; s < 2; s++) {
        uint32_t base = smb + (uint32_t)s * PAIR_BYTES;
        #pragma unroll
        for (int h = 0; h < 2; h++) {
            uint32_t cb = base + (uint32_t)h * CHUNK_BYTES;
            int ch = 2 * s + h;
            cp_async16(cb + dstA0,         srcA0 + ch * 32);
            cp_async16(cb + dstA1,         srcA1 + ch * 32);
            cp_async16(cb + B_OFF + dstA0, srcB0 + ch * 32);
            cp_async16(cb + B_OFF + dstA1, srcB1 + ch * 32);
        }
        CP_COMMIT();
    }

    float c[2][8][4];
    #pragma unroll
    for (int mt = 0; mt < 2; mt++)
        #pragma unroll
        for (int nt = 0; nt < 8; nt++)
            #pragma unroll
            for (int e = 0; e < 4; e++) c[mt][nt][e] = 0.f;

    for (int p = 0; p < npair; p++) {
        CP_WAIT(1);
        __syncthreads();
        if (p + 2 < npair) {
            uint32_t base = smb + (uint32_t)((p + 2) % 3) * PAIR_BYTES;
            #pragma unroll
            for (int h = 0; h < 2; h++) {
                uint32_t cb = base + (uint32_t)h * CHUNK_BYTES;
                int ch = 2 * (p + 2) + h;
                cp_async16(cb + dstA0,         srcA0 + ch * 32);
                cp_async16(cb + dstA1,         srcA1 + ch * 32);
                cp_async16(cb + B_OFF + dstA0, srcB0 + ch * 32);
                cp_async16(cb + B_OFF + dstA1, srcB1 + ch * 32);
            }
        }
        CP_COMMIT();

        const uint32_t sp = smb + (uint32_t)(p % 3) * PAIR_BYTES;
        #pragma unroll
        for (int h = 0; h < 2; h++) {
            const uint32_t st = sp + (uint32_t)h * CHUNK_BYTES;
            #pragma unroll
            for (int ks = 0; ks < 2; ks++) {
                uint32_t a[2][4];
                ldm4(a[0], st + aoff[0][ks]);
                ldm4(a[1], st + aoff[1][ks]);
                // 2-deep B-fragment ring: issue next ldmatrix before current MMAs
                uint32_t bc[2][4];
                ldm4(bc[0], st + boff[0][ks]);
                #pragma unroll
                for (int np = 0; np < 4; np++) {
                    if (np < 3)
                        ldm4(bc[(np + 1) & 1], st + boff[np + 1][ks]);
                    const uint32_t* br = bc[np & 1];
                    mma16816(c[0][2 * np],     a[0], &br[0]);
                    mma16816(c[1][2 * np],     a[1], &br[0]);
                    mma16816(c[0][2 * np + 1], a[0], &br[2]);
                    mma16816(c[1][2 * np + 1], a[1], &br[2]);
                }
            }
        }
    }

    // ---- epilogue ----
    __nv_bfloat16* qdst = nullptr;
    const float* bsel = bias;
    float scl = scale;
    if (EPI == EPI_QKV3) {
        int buf = n0 >> 10;
        qdst = (buf == 0) ? outb : (buf == 1) ? outb2 : outb3;
        bsel = (buf == 0) ? bias : (buf == 1) ? bias2 : bias3;
        scl  = (buf == 0) ? scale : 1.f;
    }
    const int lcol0 = n0 & 1023;

    #pragma unroll
    for (int mt = 0; mt < 2; mt++) {
        #pragma unroll
        for (int half = 0; half < 2; half++) {
            const int grow = m0 + wm * 32 + mt * 16 + (lane >> 2) + half * 8;
            const int b = grow >> 10;
            #pragma unroll
            for (int nt = 0; nt < 8; nt++) {
                const int coff = wn * 64 + nt * 8 + (lane & 3) * 2;
                if (EPI == EPI_QKV3) {
                    const int lcol = lcol0 + coff;
                    float v0 = (c[mt][nt][half * 2 + 0] + bsel[lcol]) * scl;
                    float v1 = (c[mt][nt][half * 2 + 1] + bsel[lcol + 1]) * scl;
                    __nv_bfloat162 pr;
                    pr.x = __float2bfloat16(v0);
                    pr.y = __float2bfloat16(v1);
                    *(__nv_bfloat162*)&qdst[(size_t)grow * DD + lcol] = pr;
                } else if (EPI == EPI_GATE) {
                    const int gcol = n0 + coff;
                    float v0 = c[mt][nt][half * 2 + 0] + bias[gcol];
                    float v1 = c[mt][nt][half * 2 + 1] + bias[gcol + 1];
                    const float* gp = cmod + b * CMOD_N + gate_off + gcol;
                    const float* ap = add_src + (size_t)grow * N + gcol;
                    float2 o = { ap[0] + gp[0] * v0, ap[1] + gp[1] * v1 };
                    if (gate_off == 5120)   // final x_out: write-only -> streaming store
                        stcs_f2(&outf[(size_t)grow * N + gcol], o);
                    else
                        *(float2*)&outf[(size_t)grow * N + gcol] = o;
                } else {   // EPI_GELU -> bf16
                    const int gcol = n0 + coff;
                    float v0 = c[mt][nt][half * 2 + 0] + bias[gcol];
                    float v1 = c[mt][nt][half * 2 + 1] + bias[gcol + 1];
                    float g0 = 0.5f * v0 * (1.f + erff(v0 * 0.70710678118654752f));
                    float g1 = 0.5f * v1 * (1.f + erff(v1 * 0.70710678118654752f));
                    __nv_bfloat162 pr;
                    pr.x = __float2bfloat16(g0);
                    pr.y = __float2bfloat16(g1);
                    *(__nv_bfloat162*)&outb[(size_t)grow * N + gcol] = pr;
                }
            }
        }
    }
}

// ===================== Flash attention on mma.sync (bf16 in/out, fixed-base exp2 softmax) =====================
// Br=128, Bc=64, Dh=64. 128 threads = 4 warps, each owning 32 q-rows (mq=2).
// __launch_bounds__(128, 3): 3 CTAs/SM (regs capped at 170).
__global__ void __launch_bounds__(128, 3) flash_mma(
    const __nv_bfloat16* __restrict__ Q, const __nv_bfloat16* __restrict__ K,
    const __nv_bfloat16* __restrict__ V, __nv_bfloat16* __restrict__ Y)
{
    extern __shared__ __align__(128) char smbuf[];   // Q 16KB + 3 x (K 8KB + V 8KB) = 64KB
    const uint32_t Qb  = smem_u32(smbuf);
    const uint32_t KVb = Qb + 16384;

    const int tid = threadIdx.x, lane = tid & 31, w = tid >> 5;
    const int qt = blockIdx.x, h = blockIdx.y, b = blockIdx.z;
    const size_t gbase = ((size_t)b * SS) * DD + h * 64;
    const int t0q = qt * 128;

    // --- Q load (16KB = 1024 x 16B units, 8/thread) ---
    #pragma unroll
    for (int i = 0; i < 8; i++) {
        int u = tid + i * 128;
        int r = u >> 3, g = u & 7;
        cp_async16(Qb + r * 128 + ((g ^ (r & 7)) << 4),
                   Q + gbase + (size_t)(t0q + r) * DD + g * 8);
    }
    // --- KV tile loader: per operand 512 units, 4/thread ---
    int kvr[4], kvg[4];
    uint32_t kvd[4];
    #pragma unroll
    for (int i = 0; i < 4; i++) {
        int u = tid + i * 128;
        kvr[i] = u >> 3; kvg[i] = u & 7;
        kvd[i] = (uint32_t)kvr[i] * 128u + (uint32_t)((kvg[i] ^ (kvr[i] & 7)) << 4);
    }

    #pragma unroll
    for (int s = 0; s < 2; s++) {   // tiles 0,1 -> stages 0,1 (tile 0 shares group with Q)
        uint32_t base = KVb + (uint32_t)s * 16384u;
        #pragma unroll
        for (int i = 0; i < 4; i++) {
            cp_async16(base + kvd[i],        K + gbase + (size_t)(s * 64 + kvr[i]) * DD + kvg[i] * 8);
            cp_async16(base + 8192 + kvd[i], V + gbase + (size_t)(s * 64 + kvr[i]) * DD + kvg[i] * 8);
        }
        CP_COMMIT();
    }

    uint32_t qa[2][4][4];
    float O[2][8][4];
    #pragma unroll
    for (int mq = 0; mq < 2; mq++)
        #pragma unroll
        for (int nb = 0; nb < 8; nb++)
            #pragma unroll
            for (int e = 0; e < 4; e++) O[mq][nb][e] = 0.f;
    float lp[2][2] = { {0.f, 0.f}, {0.f, 0.f} };

    for (int t = 0; t < 16; t++) {
        CP_WAIT(1);
        __syncthreads();   // data visibility for tile t AND orders compute(t-1) before prefetch below
        if (t + 2 < 16) {
            uint32_t base = KVb + (uint32_t)((t + 2) % 3) * 16384u;
            const int t0k = (t + 2) * 64;
            #pragma unroll
            for (int i = 0; i < 4; i++) {
                cp_async16(base + kvd[i],        K + gbase + (size_t)(t0k + kvr[i]) * DD + kvg[i] * 8);
                cp_async16(base + 8192 + kvd[i], V + gbase + (size_t)(t0k + kvr[i]) * DD + kvg[i] * 8);
            }
        }
        CP_COMMIT();

        if (t == 0) {
            #pragma unroll
            for (int mq = 0; mq < 2; mq++)
                #pragma unroll
                for (int kc = 0; kc < 4; kc++) {
                    int r = w * 32 + mq * 16 + (lane & 15);
                    int g = (kc * 2 + (lane >> 4)) ^ (r & 7);
                    ldm4(qa[mq][kc], Qb + r * 128 + (g << 4));
                }
        }
        const uint32_t Kb = KVb + (uint32_t)(t % 3) * 16384u;
        const uint32_t Vb = Kb + 8192u;

        // ---- S = Q @ K^T (K fragments shared across both q-row blocks) ----
        float sc[2][8][4];
        #pragma unroll
        for (int mq = 0; mq < 2; mq++)
            #pragma unroll
            for (int nb = 0; nb < 8; nb++)
                #pragma unroll
                for (int e = 0; e < 4; e++) sc[mq][nb][e] = 0.f;
        #pragma unroll
        for (int kc = 0; kc < 4; kc++) {
            #pragma unroll
            for (int ng = 0; ng < 4; ng++) {
                int n = ng * 16 + ((lane >> 4) & 1) * 8 + (lane & 7);
                int g = (kc * 2 + ((lane >> 3) & 1)) ^ (n & 7);
                uint32_t kb[4];
                ldm4(kb, Kb + n * 128 + (g << 4));
                #pragma unroll
                for (int mq = 0; mq < 2; mq++) {
                    mma16816(sc[mq][2 * ng],     qa[mq][kc], &kb[0]);
                    mma16816(sc[mq][2 * ng + 1], qa[mq][kc], &kb[2]);
                }
            }
        }

        // ---- fixed-base softmax: P = exp2(S), partial row sums only ----
        uint32_t pa[2][4][4];
        #pragma unroll
        for (int mq = 0; mq < 2; mq++)
            #pragma unroll
            for (int ng = 0; ng < 4; ng++) {
                float e00 = fast_exp2(sc[mq][2 * ng][0]),     e01 = fast_exp2(sc[mq][2 * ng][1]);
                float e02 = fast_exp2(sc[mq][2 * ng][2]),     e03 = fast_exp2(sc[mq][2 * ng][3]);
                float e10 = fast_exp2(sc[mq][2 * ng + 1][0]), e11 = fast_exp2(sc[mq][2 * ng + 1][1]);
                float e12 = fast_exp2(sc[mq][2 * ng + 1][2]), e13 = fast_exp2(sc[mq][2 * ng + 1][3]);
                lp[mq][0] += e00 + e01 + e10 + e11;
                lp[mq][1] += e02 + e03 + e12 + e13;
                pa[mq][ng][0] = pack_bf16x2(e00, e01);
                pa[mq][ng][1] = pack_bf16x2(e02, e03);
                pa[mq][ng][2] = pack_bf16x2(e10, e11);
                pa[mq][ng][3] = pack_bf16x2(e12, e13);
            }

        // ---- O += P @ V (V fragments shared across both q-row blocks) ----
        #pragma unroll
        for (int kc = 0; kc < 4; kc++) {
            #pragma unroll
            for (int ng = 0; ng < 4; ng++) {
                int r = kc * 16 + (lane & 15);
                int g = (ng * 2 + (lane >> 4)) ^ (r & 7);
                uint32_t vb[4];
                ldm4t(vb, Vb + r * 128 + (g << 4));
                #pragma unroll
                for (int mq = 0; mq < 2; mq++) {
                    mma16816(O[mq][2 * ng],     pa[mq][kc], &vb[0]);
                    mma16816(O[mq][2 * ng + 1], pa[mq][kc], &vb[2]);
                }
            }
        }
        // no trailing barrier: next iteration's top barrier orders compute(t) vs prefetch(t+3)
    }

    // ---- single end-of-loop l reduction + store ----
    #pragma unroll
    for (int mq = 0; mq < 2; mq++) {
        float l0 = lp[mq][0], l1 = lp[mq][1];
        l0 += __shfl_xor_sync(0xffffffffu, l0, 1);
        l0 += __shfl_xor_sync(0xffffffffu, l0, 2);
        l1 += __shfl_xor_sync(0xffffffffu, l1, 1);
        l1 += __shfl_xor_sync(0xffffffffu, l1, 2);
        float inv0 = 1.f / l0, inv1 = 1.f / l1;
        const int r0 = t0q + w * 32 + mq * 16 + (lane >> 2);
        #pragma unroll
        for (int nb = 0; nb < 8; nb++) {
            const int d = nb * 8 + (lane & 3) * 2;
            __nv_bfloat162 p0, p1;
            p0.x = __float2bfloat16(O[mq][nb][0] * inv0);
            p0.y = __float2bfloat16(O[mq][nb][1] * inv0);
            p1.x = __float2bfloat16(O[mq][nb][2] * inv1);
            p1.y = __float2bfloat16(O[mq][nb][3] * inv1);
            *(__nv_bfloat162*)&Y[gbase + (size_t)r0 * DD + d]       = p0;
            *(__nv_bfloat162*)&Y[gbase + (size_t)(r0 + 8) * DD + d] = p1;
        }
    }
}

// ===================== merged prologue: mod-GEMM (blocks 0..191) + all transposes (192..12479) =====================
__global__ void __launch_bounds__(256) prologue_kernel(
    const float* __restrict__ c, const float* __restrict__ w_mod,
    const float* __restrict__ b_mod, float* __restrict__ cmod,
    float* __restrict__ o_shift, float* __restrict__ o_scale, float* __restrict__ o_cact,
    const float* __restrict__ wq, const float* __restrict__ wk, const float* __restrict__ wv,
    const float* __restrict__ wattn, const float* __restrict__ wfc1, const float* __restrict__ wfc2,
    __nv_bfloat16* __restrict__ qkvt, __nv_bfloat16* __restrict__ wat,
    __nv_bfloat16* __restrict__ f1t, __nv_bfloat16* __restrict__ f2t)
{
    __shared__ __align__(16) char smu[40960];    // union: mod 40KB | transpose 4.2KB
    const int bid = blockIdx.x;
    const int tid = threadIdx.x;

    if (bid < 192) {
        // ---- cmod = silu(c) @ w_mod + b_mod ----
        float* sc = (float*)smu;                               // 32 KB
        float (*red)[32][8] = (float(*)[32][8])(smu + 32768);  // 8 KB
        for (int i = tid; i < BB * DD; i += 256) {
            float v = c[i];
            float sv = v / (1.f + expf(-v));
            sc[i] = sv;
            if (bid == 0) o_cact[i] = sv;
        }
        __syncthreads();

        int jl = tid & 31, ks = tid >> 5;
        int j = bid * 32 + jl;
        float acc[BB];
        #pragma unroll
        for (int b = 0; b < BB; b++) acc[b] = 0.f;

        int d0 = ks * 128;
        #pragma unroll 4
        for (int dd = 0; dd < 128; dd++) {
            int d = d0 + dd;
            float w = w_mod[(size_t)d * CMOD_N + j];
            #pragma unroll
            for (int b = 0; b < BB; b++) acc[b] = fmaf(sc[b * DD + d], w, acc[b]);
        }
        #pragma unroll
        for (int b = 0; b < BB; b++) red[ks][jl][b] = acc[b];
        __syncthreads();

        int b = ks;
        float s = 0.f;
        #pragma unroll
        for (int kk = 0; kk < 8; kk++) s += red[kk][jl][b];
        float v = s + b_mod[j];
        cmod[b * CMOD_N + j] = v;
        if (j < 1024)            o_shift[b * DD + j] = v;
        else if (j < 2048)       o_scale[b * DD + (j - 1024)] = v;
        return;
    }

    // ---- weight transposes ----
    float (*t)[33] = (float(*)[33])smu;
    int id = bid - 192;
    const float* W; __nv_bfloat16* Wt;
    int n0, k0, Nsrc, Kdst;
    if (id < 3072) {               // qkv: 96 n-tiles x 32 k-tiles
        int tx2 = id % 96, ty2 = id / 96;
        n0 = tx2 * 32; k0 = ty2 * 32;
        int buf = n0 >> 10;
        W = (buf == 0) ? wq : (buf == 1) ? wk : wv;
        Wt = qkvt;  Nsrc = DD; Kdst = DD;
        int nl0 = n0 & 1023;
        int txi = tid & 31, tyi = tid >> 5;
        #pragma unroll
        for (int r = tyi; r < 32; r += 8)
            t[r][txi] = W[(size_t)(k0 + r) * Nsrc + nl0 + txi];
        __syncthreads();
        #pragma unroll
        for (int r = tyi; r < 32; r += 8)
            Wt[(size_t)(n0 + r) * Kdst + k0 + txi] = __float2bfloat16(t[txi][r]);
        return;
    } else if (id < 4096) {        // w_attn: 32 x 32
        int lid2 = id - 3072;
        n0 = (lid2 % 32) * 32; k0 = (lid2 / 32) * 32;
        W = wattn; Wt = wat; Nsrc = DD; Kdst = DD;
    } else if (id < 8192) {        // fc1: [K=1024, N=4096] -> f1t[4096,1024]: 128 x 32
        int lid2 = id - 4096;
        n0 = (lid2 % 128) * 32; k0 = (lid2 / 128) * 32;
        W = wfc1; Wt = f1t; Nsrc = FF; Kdst = DD;
    } else {                       // fc2: [K=4096, N=1024] -> f2t[1024,4096]: 32 x 128
        int lid2 = id - 8192;
        n0 = (lid2 % 32) * 32; k0 = (lid2 / 32) * 32;
        W = wfc2; Wt = f2t; Nsrc = DD; Kdst = FF;
    }
    int txi = tid & 31, tyi = tid >> 5;
    #pragma unroll
    for (int r = tyi; r < 32; r += 8)
        t[r][txi] = W[(size_t)(k0 + r) * Nsrc + n0 + txi];
    __syncthreads();
    #pragma unroll
    for (int r = tyi; r < 32; r += 8)
        Wt[(size_t)(n0 + r) * Kdst + k0 + txi] = __float2bfloat16(t[txi][r]);
}

// ---------------- LayerNorm + modulate (warp-per-row; no block barriers, no smem) ----------------
__global__ void __launch_bounds__(256) ln_mod_kernel(
    const float* __restrict__ x, const float* __restrict__ cmod,
    float* __restrict__ xnorm, float* __restrict__ xmod, __nv_bfloat16* __restrict__ xmod_b,
    int shift_off, int scale_off)
{
    const int row = blockIdx.x * 8 + (threadIdx.x >> 5);
    const int lane = threadIdx.x & 31;
    const int b = row >> 10;
    const float4* xr = (const float4*)(x + (size_t)row * DD);

    float4 v[8];
    float s = 0.f;
    #pragma unroll
    for (int i = 0; i < 8; i++) {
        v[i] = xr[lane + i * 32];
        s += v[i].x + v[i].y + v[i].z + v[i].w;
    }
    #pragma unroll
    for (int o = 16; o > 0; o >>= 1) s += __shfl_xor_sync(0xffffffffu, s, o);
    const float mu = s * (1.f / DD);

    float s2 = 0.f;
    #pragma unroll
    for (int i = 0; i < 8; i++) {
        float d0 = v[i].x - mu, d1 = v[i].y - mu, d2 = v[i].z - mu, d3 = v[i].w - mu;
        s2 += d0 * d0 + d1 * d1 + d2 * d2 + d3 * d3;
    }
    #pragma unroll
    for (int o = 16; o > 0; o >>= 1) s2 += __shfl_xor_sync(0xffffffffu, s2, o);
    const float rstd = rsqrtf(s2 * (1.f / DD) + 1e-6f);

    const float4* shp = (const float4*)(cmod + b * CMOD_N + shift_off);
    const float4* slp = (const float4*)(cmod + b * CMOD_N + scale_off);
    #pragma unroll
    for (int i = 0; i < 8; i++) {
        const int idx = lane + i * 32;
        const float4 sh = shp[idx], sl = slp[idx];
        float4 xn = { (v[i].x - mu) * rstd, (v[i].y - mu) * rstd,
                      (v[i].z - mu) * rstd, (v[i].w - mu) * rstd };
        float4 xm = { xn.x * (1.f + sl.x) + sh.x, xn.y * (1.f + sl.y) + sh.y,
                      xn.z * (1.f + sl.z) + sh.z, xn.w * (1.f + sl.w) + sh.w };
        if (xnorm) stcs_f4(xnorm + (size_t)row * DD + idx * 4, xn);
        if (xmod)  stcs_f4(xmod  + (size_t)row * DD + idx * 4, xm);
        uint2 p = { pack_bf16x2(xm.x, xm.y), pack_bf16x2(xm.z, xm.w) };
        ((uint2*)(xmod_b + (size_t)row * DD))[idx] = p;
    }
}

// ---------------- launch ----------------
extern "C" void kernel_launch(void* const* d_in, const int* in_sizes, int n_in,
                              void* d_out, int out_size)
{
    const float* x      = (const float*)d_in[0];
    const float* c      = (const float*)d_in[1];
    const float* w_mod  = (const float*)d_in[2];
    const float* b_mod  = (const float*)d_in[3];
    const float* w_q    = (const float*)d_in[4];
    const float* b_q    = (const float*)d_in[5];
    const float* w_k    = (const float*)d_in[6];
    const float* b_k    = (const float*)d_in[7];
    const float* w_v    = (const float*)d_in[8];
    const float* b_v    = (const float*)d_in[9];
    const float* w_attn = (const float*)d_in[10];
    const float* b_attn = (const float*)d_in[11];
    const float* w_fc1  = (const float*)d_in[12];
    const float* b_fc1  = (const float*)d_in[13];
    const float* w_fc2  = (const float*)d_in[14];
    const float* b_fc2  = (const float*)d_in[15];

    float* out = (float*)d_out;
    float* o_xout  = out;                    // [8,1024,1024]
    float* o_xnorm = out + 8388608;          // [8,1024,1024]
    float* o_xmod  = out + 16777216;         // [8,1024,1024]
    float* o_shift = out + 25165824;         // [8,1024]
    float* o_scale = out + 25174016;         // [8,1024]
    float* o_cmod  = out + 25182208;         // [8,6144]
    float* o_cact  = out + 25231360;         // [8,1024]

    float *p_x1;
    __nv_bfloat16 *p_qb, *p_kb, *p_vb, *p_xmb, *p_xm2b, *p_yb, *p_hb;
    __nv_bfloat16 *p_wqkvt, *p_wat, *p_f1t, *p_f2t;
    cudaGetSymbolAddress((void**)&p_x1,    g_x1);
    cudaGetSymbolAddress((void**)&p_qb,    g_qb);
    cudaGetSymbolAddress((void**)&p_kb,    g_kb);
    cudaGetSymbolAddress((void**)&p_vb,    g_vb);
    cudaGetSymbolAddress((void**)&p_xmb,   g_xmod_b);
    cudaGetSymbolAddress((void**)&p_xm2b,  g_xm2_b);
    cudaGetSymbolAddress((void**)&p_yb,    g_y_b);
    cudaGetSymbolAddress((void**)&p_hb,    g_h_b);
    cudaGetSymbolAddress((void**)&p_wqkvt, g_wqkvt);
    cudaGetSymbolAddress((void**)&p_wat,   g_wat);
    cudaGetSymbolAddress((void**)&p_f1t,   g_wfc1t);
    cudaGetSymbolAddress((void**)&p_f2t,   g_wfc2t);

    cudaFuncSetAttribute(flash_mma, cudaFuncAttributeMaxDynamicSharedMemorySize, 65536);
    cudaFuncSetAttribute(mma_gemm<EPI_QKV3>, cudaFuncAttributeMaxDynamicSharedMemorySize, GEMM_SMEM);
    cudaFuncSetAttribute(mma_gemm<EPI_GATE>, cudaFuncAttributeMaxDynamicSharedMemorySize, GEMM_SMEM);
    cudaFuncSetAttribute(mma_gemm<EPI_GELU>, cudaFuncAttributeMaxDynamicSharedMemorySize, GEMM_SMEM);

    // 0) merged prologue: mod-GEMM + all weight transposes, concurrent
    prologue_kernel<<<192 + 12288, 256>>>(
        c, w_mod, b_mod, o_cmod, o_shift, o_scale, o_cact,
        w_q, w_k, w_v, w_attn, w_fc1, w_fc2,
        p_wqkvt, p_wat, p_f1t, p_f2t);

    // 1) LN1 + modulate
    ln_mod_kernel<<<MTOK / 8, 256>>>(x, o_cmod, o_xnorm, o_xmod, p_xmb, 0, 1024);

    // 2) fused QKV projection -> bf16 (q scaled by log2(e)/64 for exp2 softmax)
    dim3 gQKV(3 * DD / 128, MTOK / 128);   // (24, 64)
    mma_gemm<EPI_QKV3><<<gQKV, 256, GEMM_SMEM>>>(p_xmb, p_wqkvt, b_q, nullptr, p_qb, DD, DD, QSCALE,
                                      nullptr, nullptr, 0, p_kb, p_vb, b_k, b_v);

    // 3) attention on tensor cores (Br=128, mq=2; 3 CTAs/SM)
    flash_mma<<<dim3(SS / 128, 16, BB), 128, 65536>>>(p_qb, p_kb, p_vb, p_yb);

    // 4) attn projection + residual with gate_msa
    dim3 gD(DD / 128, MTOK / 128);     // (8, 64)
    mma_gemm<EPI_GATE><<<gD, 256, GEMM_SMEM>>>(p_yb, p_wat, b_attn, p_x1, nullptr, DD, DD, 1.f,
                                    x, o_cmod, 2048, nullptr, nullptr, nullptr, nullptr);

    // 5) LN2 + modulate (bf16 only)
    ln_mod_kernel<<<MTOK / 8, 256>>>(p_x1, o_cmod, nullptr, nullptr, p_xm2b, 3072, 4096);

    // 6) MLP on tensor cores
    dim3 gF(FF / 128, MTOK / 128);     // (32, 64)
    mma_gemm<EPI_GELU><<<gF, 256, GEMM_SMEM>>>(p_xm2b, p_f1t, b_fc1, nullptr, p_hb, DD, FF, 1.f,
                                    nullptr, nullptr, 0, nullptr, nullptr, nullptr, nullptr);
    mma_gemm<EPI_GATE><<<gD, 256, GEMM_SMEM>>>(p_hb, p_f2t, b_fc2, o_xout, nullptr, FF, DD, 1.f,
                                    p_x1, o_cmod, 5120, nullptr, nullptr, nullptr, nullptr);
}

// round 14
// speedup vs baseline: 1.1318x; 1.0039x over previous
#include <cuda_runtime.h>
#include <cuda_bf16.h>
#include <math.h>
#include <cstdint>

// Problem dims (fixed by the dataset)
#define BB 8
#define SS 1024
#define DD 1024
#define FF 4096
#define MTOK (BB*SS)       // 8192
#define CMOD_N (6*DD)      // 6144

#define QSCALE 0.022542110013890053f   // log2(e) / 64

// -------- scratch (device globals; no allocation allowed) --------
__device__ float g_x1 [MTOK * DD];

__device__ __nv_bfloat16 g_qb  [MTOK * DD];
__device__ __nv_bfloat16 g_kb  [MTOK * DD];
__device__ __nv_bfloat16 g_vb  [MTOK * DD];
__device__ __nv_bfloat16 g_xmod_b[MTOK * DD];
__device__ __nv_bfloat16 g_xm2_b [MTOK * DD];
__device__ __nv_bfloat16 g_y_b   [MTOK * DD];
__device__ __nv_bfloat16 g_h_b   [(size_t)MTOK * FF];
__device__ __nv_bfloat16 g_wqkvt[3 * DD * DD];
__device__ __nv_bfloat16 g_wat  [DD * DD];
__device__ __nv_bfloat16 g_wfc1t[(size_t)FF * DD];
__device__ __nv_bfloat16 g_wfc2t[(size_t)DD * FF];

// ===================== PTX helpers (baseline ISA only — no tcgen05) =====================
__device__ __forceinline__ uint32_t smem_u32(const void* p) {
    uint32_t a;
    asm("{ .reg .u64 t; cvta.to.shared.u64 t, %1; cvt.u32.u64 %0, t; }" : "=r"(a) : "l"(p));
    return a;
}
__device__ __forceinline__ void cp_async16(uint32_t dst, const void* src) {
    asm volatile("cp.async.cg.shared.global [%0], [%1], 16;" :: "r"(dst), "l"(src));
}
#define CP_COMMIT() asm volatile("cp.async.commit_group;" ::: "memory")
#define CP_WAIT(n)  asm volatile("cp.async.wait_group %0;" :: "n"(n) : "memory")

__device__ __forceinline__ void ldm4(uint32_t* r, uint32_t addr) {
    asm volatile("ldmatrix.sync.aligned.m8n8.x4.shared.b16 {%0,%1,%2,%3}, [%4];"
        : "=r"(r[0]), "=r"(r[1]), "=r"(r[2]), "=r"(r[3]) : "r"(addr));
}
__device__ __forceinline__ void ldm4t(uint32_t* r, uint32_t addr) {
    asm volatile("ldmatrix.sync.aligned.m8n8.x4.trans.shared.b16 {%0,%1,%2,%3}, [%4];"
        : "=r"(r[0]), "=r"(r[1]), "=r"(r[2]), "=r"(r[3]) : "r"(addr));
}
__device__ __forceinline__ void mma16816(float* c, const uint32_t* a, const uint32_t* b) {
    asm volatile(
        "mma.sync.aligned.m16n8k16.row.col.f32.bf16.bf16.f32 "
        "{%0,%1,%2,%3}, {%4,%5,%6,%7}, {%8,%9}, {%0,%1,%2,%3};"
        : "+f"(c[0]), "+f"(c[1]), "+f"(c[2]), "+f"(c[3])
        : "r"(a[0]), "r"(a[1]), "r"(a[2]), "r"(a[3]), "r"(b[0]), "r"(b[1]));
}
__device__ __forceinline__ uint32_t pack_bf16x2(float lo, float hi) {
    uint32_t r;
    asm("cvt.rn.bf16x2.f32 %0, %1, %2;" : "=r"(r) : "f"(hi), "f"(lo));  // first operand -> upper half
    return r;
}
__device__ __forceinline__ float fast_exp2(float x) {
    float r;
    asm("ex2.approx.ftz.f32 %0, %1;" : "=f"(r) : "f"(x));
    return r;
}
__device__ __forceinline__ void stcs_f2(float* p, float2 v) {
    asm volatile("st.global.cs.v2.f32 [%0], {%1, %2};" :: "l"(p), "f"(v.x), "f"(v.y));
}
__device__ __forceinline__ void stcs_f4(float* p, float4 v) {
    asm volatile("st.global.cs.v4.f32 [%0], {%1, %2, %3, %4};"
        :: "l"(p), "f"(v.x), "f"(v.y), "f"(v.z), "f"(v.w));
}

// ===================== mma.sync GEMM: C[M x N] = A[M x K](bf16) @ Wt[N x K]^T =====================
// BM=128, BN=128. 256 threads (8 warps, warp tile 32x64).
// 6-stage cp.async (3 pairs of BK=32 chunks); one barrier per 64 K-elems.
// Inner loop interleaves B-fragment ldmatrix with MMAs (2-deep register ring).
enum { EPI_QKV3 = 0, EPI_GATE = 1, EPI_GELU = 2 };

#define CHUNK_BYTES 16384       // A 8KB + B 8KB per BK=32 chunk
#define PAIR_BYTES  32768
#define B_OFF 8192
#define GEMM_SMEM (3 * PAIR_BYTES)   // 96 KB

template <int EPI>
__global__ void __launch_bounds__(256) mma_gemm(
    const __nv_bfloat16* __restrict__ A, const __nv_bfloat16* __restrict__ Wt,
    const float* __restrict__ bias,
    float* __restrict__ outf, __nv_bfloat16* __restrict__ outb,
    int K, int N, float scale,
    const float* __restrict__ add_src, const float* __restrict__ cmod, int gate_off,
    __nv_bfloat16* __restrict__ outb2, __nv_bfloat16* __restrict__ outb3,
    const float* __restrict__ bias2, const float* __restrict__ bias3)
{
    extern __shared__ __align__(128) char smbuf[];   // 96 KB
    const uint32_t smb = smem_u32(smbuf);

    const int tid = threadIdx.x;
    const int lane = tid & 31, wid = tid >> 5;
    const int wm = wid & 3, wn = wid >> 2;      // 4 warps M x 2 warps N
    const int m0 = blockIdx.y * 128;
    const int n0 = blockIdx.x * 128;

    const int uA0 = tid, uA1 = tid + 256;
    const int rA0u = uA0 >> 2, gA0u = uA0 & 3;
    const int rA1u = uA1 >> 2, gA1u = uA1 & 3;
    const uint32_t dstA0 = (uint32_t)rA0u * 64u + (uint32_t)((gA0u ^ ((rA0u >> 1) & 3)) << 4);
    const uint32_t dstA1 = (uint32_t)rA1u * 64u + (uint32_t)((gA1u ^ ((rA1u >> 1) & 3)) << 4);
    const __nv_bfloat16* srcA0 = A + (size_t)(m0 + rA0u) * K + gA0u * 8;
    const __nv_bfloat16* srcA1 = A + (size_t)(m0 + rA1u) * K + gA1u * 8;
    const __nv_bfloat16* srcB0 = Wt + (size_t)(n0 + rA0u) * K + gA0u * 8;
    const __nv_bfloat16* srcB1 = Wt + (size_t)(n0 + rA1u) * K + gA1u * 8;

    const int npair = K >> 6;   // K / 64

    uint32_t aoff[2][2];
    {
        int r = wm * 32 + (lane & 15);
        int sw = (r >> 1) & 3;
        #pragma unroll
        for (int mt = 0; mt < 2; mt++)
            #pragma unroll
            for (int ks = 0; ks < 2; ks++)
                aoff[mt][ks] = (uint32_t)(r + mt * 16) * 64u +
                               (uint32_t)(((ks * 2 + (lane >> 4)) ^ sw) << 4);
    }
    uint32_t boff[4][2];
    {
        int n = wn * 64 + ((lane >> 4) & 1) * 8 + (lane & 7);
        int gpar = (lane >> 3) & 1;
        int sw = (n >> 1) & 3;
        #pragma unroll
        for (int np = 0; np < 4; np++)
            #pragma unroll
            for (int ks = 0; ks < 2; ks++)
                boff[np][ks] = (uint32_t)B_OFF + (uint32_t)(n + np * 16) * 64u +
                               (uint32_t)(((ks * 2 + gpar) ^ sw) << 4);
    }

    // prologue: pairs 0,1 (chunks 0..3), one commit group per pair
    #pragma unroll
    for (int s = 0; s < 2; s++) {
        uint32_t base = smb + (uint32_t)s * PAIR_BYTES;
        #pragma unroll
        for (int h = 0; h < 2; h++) {
            uint32_t cb = base + (uint32_t)h * CHUNK_BYTES;
            int ch = 2 * s + h;
            cp_async16(cb + dstA0,         srcA0 + ch * 32);
            cp_async16(cb + dstA1,         srcA1 + ch * 32);
            cp_async16(cb + B_OFF + dstA0, srcB0 + ch * 32);
            cp_async16(cb + B_OFF + dstA1, srcB1 + ch * 32);
        }
        CP_COMMIT();
    }

    float c[2][8][4];
    #pragma unroll
    for (int mt = 0; mt < 2; mt++)
        #pragma unroll
        for (int nt = 0; nt < 8; nt++)
            #pragma unroll
            for (int e = 0; e < 4; e++) c[mt][nt][e] = 0.f;

    for (int p = 0; p < npair; p++) {
        CP_WAIT(1);
        __syncthreads();
        if (p + 2 < npair) {
            uint32_t base = smb + (uint32_t)((p + 2) % 3) * PAIR_BYTES;
            #pragma unroll
            for (int h = 0; h < 2; h++) {
                uint32_t cb = base + (uint32_t)h * CHUNK_BYTES;
                int ch = 2 * (p + 2) + h;
                cp_async16(cb + dstA0,         srcA0 + ch * 32);
                cp_async16(cb + dstA1,         srcA1 + ch * 32);
                cp_async16(cb + B_OFF + dstA0, srcB0 + ch * 32);
                cp_async16(cb + B_OFF + dstA1, srcB1 + ch * 32);
            }
        }
        CP_COMMIT();

        const uint32_t sp = smb + (uint32_t)(p % 3) * PAIR_BYTES;
        #pragma unroll
        for (int h = 0; h < 2; h++) {
            const uint32_t st = sp + (uint32_t)h * CHUNK_BYTES;
            #pragma unroll
            for (int ks = 0; ks < 2; ks++) {
                uint32_t a[2][4];
                ldm4(a[0], st + aoff[0][ks]);
                ldm4(a[1], st + aoff[1][ks]);
                // 2-deep B-fragment ring: issue next ldmatrix before current MMAs
                uint32_t bc[2][4];
                ldm4(bc[0], st + boff[0][ks]);
                #pragma unroll
                for (int np = 0; np < 4; np++) {
                    if (np < 3)
                        ldm4(bc[(np + 1) & 1], st + boff[np + 1][ks]);
                    const uint32_t* br = bc[np & 1];
                    mma16816(c[0][2 * np],     a[0], &br[0]);
                    mma16816(c[1][2 * np],     a[1], &br[0]);
                    mma16816(c[0][2 * np + 1], a[0], &br[2]);
                    mma16816(c[1][2 * np + 1], a[1], &br[2]);
                }
            }
        }
    }

    // ---- epilogue ----
    __nv_bfloat16* qdst = nullptr;
    const float* bsel = bias;
    float scl = scale;
    if (EPI == EPI_QKV3) {
        int buf = n0 >> 10;
        qdst = (buf == 0) ? outb : (buf == 1) ? outb2 : outb3;
        bsel = (buf == 0) ? bias : (buf == 1) ? bias2 : bias3;
        scl  = (buf == 0) ? scale : 1.f;
    }
    const int lcol0 = n0 & 1023;

    #pragma unroll
    for (int mt = 0; mt < 2; mt++) {
        #pragma unroll
        for (int half = 0; half < 2; half++) {
            const int grow = m0 + wm * 32 + mt * 16 + (lane >> 2) + half * 8;
            const int b = grow >> 10;
            #pragma unroll
            for (int nt = 0; nt < 8; nt++) {
                const int coff = wn * 64 + nt * 8 + (lane & 3) * 2;
                if (EPI == EPI_QKV3) {
                    const int lcol = lcol0 + coff;
                    float v0 = (c[mt][nt][half * 2 + 0] + bsel[lcol]) * scl;
                    float v1 = (c[mt][nt][half * 2 + 1] + bsel[lcol + 1]) * scl;
                    __nv_bfloat162 pr;
                    pr.x = __float2bfloat16(v0);
                    pr.y = __float2bfloat16(v1);
                    *(__nv_bfloat162*)&qdst[(size_t)grow * DD + lcol] = pr;
                } else if (EPI == EPI_GATE) {
                    const int gcol = n0 + coff;
                    float v0 = c[mt][nt][half * 2 + 0] + bias[gcol];
                    float v1 = c[mt][nt][half * 2 + 1] + bias[gcol + 1];
                    const float* gp = cmod + b * CMOD_N + gate_off + gcol;
                    const float* ap = add_src + (size_t)grow * N + gcol;
                    float2 o = { ap[0] + gp[0] * v0, ap[1] + gp[1] * v1 };
                    if (gate_off == 5120)   // final x_out: write-only -> streaming store
                        stcs_f2(&outf[(size_t)grow * N + gcol], o);
                    else
                        *(float2*)&outf[(size_t)grow * N + gcol] = o;
                } else {   // EPI_GELU -> bf16
                    const int gcol = n0 + coff;
                    float v0 = c[mt][nt][half * 2 + 0] + bias[gcol];
                    float v1 = c[mt][nt][half * 2 + 1] + bias[gcol + 1];
                    float g0 = 0.5f * v0 * (1.f + erff(v0 * 0.70710678118654752f));
                    float g1 = 0.5f * v1 * (1.f + erff(v1 * 0.70710678118654752f));
                    __nv_bfloat162 pr;
                    pr.x = __float2bfloat16(g0);
                    pr.y = __float2bfloat16(g1);
                    *(__nv_bfloat162*)&outb[(size_t)grow * N + gcol] = pr;
                }
            }
        }
    }
}

// ===================== Flash attention on mma.sync (bf16 in/out, fixed-base exp2 softmax) =====================
// Br=128, Bc=64, Dh=64. 128 threads = 4 warps, each owning 32 q-rows (mq=2).
// __launch_bounds__(128, 3): 3 CTAs/SM. K and V inner loops use the same 2-deep
// ldmatrix/MMA interleave ring that recovered latency exposure in the GEMM (R13).
__global__ void __launch_bounds__(128, 3) flash_mma(
    const __nv_bfloat16* __restrict__ Q, const __nv_bfloat16* __restrict__ K,
    const __nv_bfloat16* __restrict__ V, __nv_bfloat16* __restrict__ Y)
{
    extern __shared__ __align__(128) char smbuf[];   // Q 16KB + 3 x (K 8KB + V 8KB) = 64KB
    const uint32_t Qb  = smem_u32(smbuf);
    const uint32_t KVb = Qb + 16384;

    const int tid = threadIdx.x, lane = tid & 31, w = tid >> 5;
    const int qt = blockIdx.x, h = blockIdx.y, b = blockIdx.z;
    const size_t gbase = ((size_t)b * SS) * DD + h * 64;
    const int t0q = qt * 128;

    // --- Q load (16KB = 1024 x 16B units, 8/thread) ---
    #pragma unroll
    for (int i = 0; i < 8; i++) {
        int u = tid + i * 128;
        int r = u >> 3, g = u & 7;
        cp_async16(Qb + r * 128 + ((g ^ (r & 7)) << 4),
                   Q + gbase + (size_t)(t0q + r) * DD + g * 8);
    }
    // --- KV tile loader: per operand 512 units, 4/thread ---
    int kvr[4], kvg[4];
    uint32_t kvd[4];
    #pragma unroll
    for (int i = 0; i < 4; i++) {
        int u = tid + i * 128;
        kvr[i] = u >> 3; kvg[i] = u & 7;
        kvd[i] = (uint32_t)kvr[i] * 128u + (uint32_t)((kvg[i] ^ (kvr[i] & 7)) << 4);
    }

    #pragma unroll
    for (int s = 0; s < 2; s++) {   // tiles 0,1 -> stages 0,1 (tile 0 shares group with Q)
        uint32_t base = KVb + (uint32_t)s * 16384u;
        #pragma unroll
        for (int i = 0; i < 4; i++) {
            cp_async16(base + kvd[i],        K + gbase + (size_t)(s * 64 + kvr[i]) * DD + kvg[i] * 8);
            cp_async16(base + 8192 + kvd[i], V + gbase + (size_t)(s * 64 + kvr[i]) * DD + kvg[i] * 8);
        }
        CP_COMMIT();
    }

    uint32_t qa[2][4][4];
    float O[2][8][4];
    #pragma unroll
    for (int mq = 0; mq < 2; mq++)
        #pragma unroll
        for (int nb = 0; nb < 8; nb++)
            #pragma unroll
            for (int e = 0; e < 4; e++) O[mq][nb][e] = 0.f;
    float lp[2][2] = { {0.f, 0.f}, {0.f, 0.f} };

    for (int t = 0; t < 16; t++) {
        CP_WAIT(1);
        __syncthreads();   // data visibility for tile t AND orders compute(t-1) before prefetch below
        if (t + 2 < 16) {
            uint32_t base = KVb + (uint32_t)((t + 2) % 3) * 16384u;
            const int t0k = (t + 2) * 64;
            #pragma unroll
            for (int i = 0; i < 4; i++) {
                cp_async16(base + kvd[i],        K + gbase + (size_t)(t0k + kvr[i]) * DD + kvg[i] * 8);
                cp_async16(base + 8192 + kvd[i], V + gbase + (size_t)(t0k + kvr[i]) * DD + kvg[i] * 8);
            }
        }
        CP_COMMIT();

        if (t == 0) {
            #pragma unroll
            for (int mq = 0; mq < 2; mq++)
                #pragma unroll
                for (int kc = 0; kc < 4; kc++) {
                    int r = w * 32 + mq * 16 + (lane & 15);
                    int g = (kc * 2 + (lane >> 4)) ^ (r & 7);
                    ldm4(qa[mq][kc], Qb + r * 128 + (g << 4));
                }
        }
        const uint32_t Kb = KVb + (uint32_t)(t % 3) * 16384u;
        const uint32_t Vb = Kb + 8192u;

        // ---- S = Q @ K^T: 2-deep K-fragment ring over the 16 (kc,ng) loads ----
        float sc[2][8][4];
        #pragma unroll
        for (int mq = 0; mq < 2; mq++)
            #pragma unroll
            for (int nb = 0; nb < 8; nb++)
                #pragma unroll
                for (int e = 0; e < 4; e++) sc[mq][nb][e] = 0.f;
        {
            const int nbase = ((lane >> 4) & 1) * 8 + (lane & 7);
            const int gpar = (lane >> 3) & 1;
            uint32_t kf[2][4];
            // load (kc=0, ng=0)
            {
                int n = nbase;
                int g = (0 + gpar) ^ (n & 7);
                ldm4(kf[0], Kb + n * 128 + (g << 4));
            }
            #pragma unroll
            for (int kc = 0; kc < 4; kc++) {
                #pragma unroll
                for (int ng = 0; ng < 4; ng++) {
                    const int idx = kc * 4 + ng;
                    if (idx < 15) {
                        const int nkc = (idx + 1) >> 2, nng = (idx + 1) & 3;
                        int n = nng * 16 + nbase;
                        int g = (nkc * 2 + gpar) ^ (n & 7);
                        ldm4(kf[(idx + 1) & 1], Kb + n * 128 + (g << 4));
                    }
                    const uint32_t* kb = kf[idx & 1];
                    #pragma unroll
                    for (int mq = 0; mq < 2; mq++) {
                        mma16816(sc[mq][2 * ng],     qa[mq][kc], &kb[0]);
                        mma16816(sc[mq][2 * ng + 1], qa[mq][kc], &kb[2]);
                    }
                }
            }
        }

        // ---- fixed-base softmax: P = exp2(S), partial row sums only ----
        uint32_t pa[2][4][4];
        #pragma unroll
        for (int mq = 0; mq < 2; mq++)
            #pragma unroll
            for (int ng = 0; ng < 4; ng++) {
                float e00 = fast_exp2(sc[mq][2 * ng][0]),     e01 = fast_exp2(sc[mq][2 * ng][1]);
                float e02 = fast_exp2(sc[mq][2 * ng][2]),     e03 = fast_exp2(sc[mq][2 * ng][3]);
                float e10 = fast_exp2(sc[mq][2 * ng + 1][0]), e11 = fast_exp2(sc[mq][2 * ng + 1][1]);
                float e12 = fast_exp2(sc[mq][2 * ng + 1][2]), e13 = fast_exp2(sc[mq][2 * ng + 1][3]);
                lp[mq][0] += e00 + e01 + e10 + e11;
                lp[mq][1] += e02 + e03 + e12 + e13;
                pa[mq][ng][0] = pack_bf16x2(e00, e01);
                pa[mq][ng][1] = pack_bf16x2(e02, e03);
                pa[mq][ng][2] = pack_bf16x2(e10, e11);
                pa[mq][ng][3] = pack_bf16x2(e12, e13);
            }

        // ---- O += P @ V: 2-deep V-fragment ring over the 16 (kc,ng) loads ----
        {
            const int rbase = lane & 15;
            const int gsel = lane >> 4;
            uint32_t vf[2][4];
            {
                int r = rbase;
                int g = (0 * 2 + gsel) ^ (r & 7);
                ldm4t(vf[0], Vb + r * 128 + (g << 4));
            }
            #pragma unroll
            for (int kc = 0; kc < 4; kc++) {
                #pragma unroll
                for (int ng = 0; ng < 4; ng++) {
                    const int idx = kc * 4 + ng;
                    if (idx < 15) {
                        const int nkc = (idx + 1) >> 2, nng = (idx + 1) & 3;
                        int r = nkc * 16 + rbase;
                        int g = (nng * 2 + gsel) ^ (r & 7);
                        ldm4t(vf[(idx + 1) & 1], Vb + r * 128 + (g << 4));
                    }
                    const uint32_t* vb = vf[idx & 1];
                    #pragma unroll
                    for (int mq = 0; mq < 2; mq++) {
                        mma16816(O[mq][2 * ng],     pa[mq][kc], &vb[0]);
                        mma16816(O[mq][2 * ng + 1], pa[mq][kc], &vb[2]);
                    }
                }
            }
        }
        // no trailing barrier: next iteration's top barrier orders compute(t) vs prefetch(t+3)
    }

    // ---- single end-of-loop l reduction + store ----
    #pragma unroll
    for (int mq = 0; mq < 2; mq++) {
        float l0 = lp[mq][0], l1 = lp[mq][1];
        l0 += __shfl_xor_sync(0xffffffffu, l0, 1);
        l0 += __shfl_xor_sync(0xffffffffu, l0, 2);
        l1 += __shfl_xor_sync(0xffffffffu, l1, 1);
        l1 += __shfl_xor_sync(0xffffffffu, l1, 2);
        float inv0 = 1.f / l0, inv1 = 1.f / l1;
        const int r0 = t0q + w * 32 + mq * 16 + (lane >> 2);
        #pragma unroll
        for (int nb = 0; nb < 8; nb++) {
            const int d = nb * 8 + (lane & 3) * 2;
            __nv_bfloat162 p0, p1;
            p0.x = __float2bfloat16(O[mq][nb][0] * inv0);
            p0.y = __float2bfloat16(O[mq][nb][1] * inv0);
            p1.x = __float2bfloat16(O[mq][nb][2] * inv1);
            p1.y = __float2bfloat16(O[mq][nb][3] * inv1);
            *(__nv_bfloat162*)&Y[gbase + (size_t)r0 * DD + d]       = p0;
            *(__nv_bfloat162*)&Y[gbase + (size_t)(r0 + 8) * DD + d] = p1;
        }
    }
}

// ===================== merged prologue: mod-GEMM (blocks 0..191) + all transposes (192..12479) =====================
__global__ void __launch_bounds__(256) prologue_kernel(
    const float* __restrict__ c, const float* __restrict__ w_mod,
    const float* __restrict__ b_mod, float* __restrict__ cmod,
    float* __restrict__ o_shift, float* __restrict__ o_scale, float* __restrict__ o_cact,
    const float* __restrict__ wq, const float* __restrict__ wk, const float* __restrict__ wv,
    const float* __restrict__ wattn, const float* __restrict__ wfc1, const float* __restrict__ wfc2,
    __nv_bfloat16* __restrict__ qkvt, __nv_bfloat16* __restrict__ wat,
    __nv_bfloat16* __restrict__ f1t, __nv_bfloat16* __restrict__ f2t)
{
    __shared__ __align__(16) char smu[40960];    // union: mod 40KB | transpose 4.2KB
    const int bid = blockIdx.x;
    const int tid = threadIdx.x;

    if (bid < 192) {
        // ---- cmod = silu(c) @ w_mod + b_mod ----
        float* sc = (float*)smu;                               // 32 KB
        float (*red)[32][8] = (float(*)[32][8])(smu + 32768);  // 8 KB
        for (int i = tid; i < BB * DD; i += 256) {
            float v = c[i];
            float sv = v / (1.f + expf(-v));
            sc[i] = sv;
            if (bid == 0) o_cact[i] = sv;
        }
        __syncthreads();

        int jl = tid & 31, ks = tid >> 5;
        int j = bid * 32 + jl;
        float acc[BB];
        #pragma unroll
        for (int b = 0; b < BB; b++) acc[b] = 0.f;

        int d0 = ks * 128;
        #pragma unroll 4
        for (int dd = 0; dd < 128; dd++) {
            int d = d0 + dd;
            float w = w_mod[(size_t)d * CMOD_N + j];
            #pragma unroll
            for (int b = 0; b < BB; b++) acc[b] = fmaf(sc[b * DD + d], w, acc[b]);
        }
        #pragma unroll
        for (int b = 0; b < BB; b++) red[ks][jl][b] = acc[b];
        __syncthreads();

        int b = ks;
        float s = 0.f;
        #pragma unroll
        for (int kk = 0; kk < 8; kk++) s += red[kk][jl][b];
        float v = s + b_mod[j];
        cmod[b * CMOD_N + j] = v;
        if (j < 1024)            o_shift[b * DD + j] = v;
        else if (j < 2048)       o_scale[b * DD + (j - 1024)] = v;
        return;
    }

    // ---- weight transposes ----
    float (*t)[33] = (float(*)[33])smu;
    int id = bid - 192;
    const float* W; __nv_bfloat16* Wt;
    int n0, k0, Nsrc, Kdst;
    if (id < 3072) {               // qkv: 96 n-tiles x 32 k-tiles
        int tx2 = id % 96, ty2 = id / 96;
        n0 = tx2 * 32; k0 = ty2 * 32;
        int buf = n0 >> 10;
        W = (buf == 0) ? wq : (buf == 1) ? wk : wv;
        Wt = qkvt;  Nsrc = DD; Kdst = DD;
        int nl0 = n0 & 1023;
        int txi = tid & 31, tyi = tid >> 5;
        #pragma unroll
        for (int r = tyi; r < 32; r += 8)
            t[r][txi] = W[(size_t)(k0 + r) * Nsrc + nl0 + txi];
        __syncthreads();
        #pragma unroll
        for (int r = tyi; r < 32; r += 8)
            Wt[(size_t)(n0 + r) * Kdst + k0 + txi] = __float2bfloat16(t[txi][r]);
        return;
    } else if (id < 4096) {        // w_attn: 32 x 32
        int lid2 = id - 3072;
        n0 = (lid2 % 32) * 32; k0 = (lid2 / 32) * 32;
        W = wattn; Wt = wat; Nsrc = DD; Kdst = DD;
    } else if (id < 8192) {        // fc1: [K=1024, N=4096] -> f1t[4096,1024]: 128 x 32
        int lid2 = id - 4096;
        n0 = (lid2 % 128) * 32; k0 = (lid2 / 128) * 32;
        W = wfc1; Wt = f1t; Nsrc = FF; Kdst = DD;
    } else {                       // fc2: [K=4096, N=1024] -> f2t[1024,4096]: 32 x 128
        int lid2 = id - 8192;
        n0 = (lid2 % 32) * 32; k0 = (lid2 / 32) * 32;
        W = wfc2; Wt = f2t; Nsrc = DD; Kdst = FF;
    }
    int txi = tid & 31, tyi = tid >> 5;
    #pragma unroll
    for (int r = tyi; r < 32; r += 8)
        t[r][txi] = W[(size_t)(k0 + r) * Nsrc + n0 + txi];
    __syncthreads();
    #pragma unroll
    for (int r = tyi; r < 32; r += 8)
        Wt[(size_t)(n0 + r) * Kdst + k0 + txi] = __float2bfloat16(t[txi][r]);
}

// ---------------- LayerNorm + modulate (warp-per-row; no block barriers, no smem) ----------------
__global__ void __launch_bounds__(256) ln_mod_kernel(
    const float* __restrict__ x, const float* __restrict__ cmod,
    float* __restrict__ xnorm, float* __restrict__ xmod, __nv_bfloat16* __restrict__ xmod_b,
    int shift_off, int scale_off)
{
    const int row = blockIdx.x * 8 + (threadIdx.x >> 5);
    const int lane = threadIdx.x & 31;
    const int b = row >> 10;
    const float4* xr = (const float4*)(x + (size_t)row * DD);

    float4 v[8];
    float s = 0.f;
    #pragma unroll
    for (int i = 0; i < 8; i++) {
        v[i] = xr[lane + i * 32];
        s += v[i].x + v[i].y + v[i].z + v[i].w;
    }
    #pragma unroll
    for (int o = 16; o > 0; o >>= 1) s += __shfl_xor_sync(0xffffffffu, s, o);
    const float mu = s * (1.f / DD);

    float s2 = 0.f;
    #pragma unroll
    for (int i = 0; i < 8; i++) {
        float d0 = v[i].x - mu, d1 = v[i].y - mu, d2 = v[i].z - mu, d3 = v[i].w - mu;
        s2 += d0 * d0 + d1 * d1 + d2 * d2 + d3 * d3;
    }
    #pragma unroll
    for (int o = 16; o > 0; o >>= 1) s2 += __shfl_xor_sync(0xffffffffu, s2, o);
    const float rstd = rsqrtf(s2 * (1.f / DD) + 1e-6f);

    const float4* shp = (const float4*)(cmod + b * CMOD_N + shift_off);
    const float4* slp = (const float4*)(cmod + b * CMOD_N + scale_off);
    #pragma unroll
    for (int i = 0; i < 8; i++) {
        const int idx = lane + i * 32;
        const float4 sh = shp[idx], sl = slp[idx];
        float4 xn = { (v[i].x - mu) * rstd, (v[i].y - mu) * rstd,
                      (v[i].z - mu) * rstd, (v[i].w - mu) * rstd };
        float4 xm = { xn.x * (1.f + sl.x) + sh.x, xn.y * (1.f + sl.y) + sh.y,
                      xn.z * (1.f + sl.z) + sh.z, xn.w * (1.f + sl.w) + sh.w };
        if (xnorm) stcs_f4(xnorm + (size_t)row * DD + idx * 4, xn);
        if (xmod)  stcs_f4(xmod  + (size_t)row * DD + idx * 4, xm);
        uint2 p = { pack_bf16x2(xm.x, xm.y), pack_bf16x2(xm.z, xm.w) };
        ((uint2*)(xmod_b + (size_t)row * DD))[idx] = p;
    }
}

// ---------------- launch ----------------
extern "C" void kernel_launch(void* const* d_in, const int* in_sizes, int n_in,
                              void* d_out, int out_size)
{
    const float* x      = (const float*)d_in[0];
    const float* c      = (const float*)d_in[1];
    const float* w_mod  = (const float*)d_in[2];
    const float* b_mod  = (const float*)d_in[3];
    const float* w_q    = (const float*)d_in[4];
    const float* b_q    = (const float*)d_in[5];
    const float* w_k    = (const float*)d_in[6];
    const float* b_k    = (const float*)d_in[7];
    const float* w_v    = (const float*)d_in[8];
    const float* b_v    = (const float*)d_in[9];
    const float* w_attn = (const float*)d_in[10];
    const float* b_attn = (const float*)d_in[11];
    const float* w_fc1  = (const float*)d_in[12];
    const float* b_fc1  = (const float*)d_in[13];
    const float* w_fc2  = (const float*)d_in[14];
    const float* b_fc2  = (const float*)d_in[15];

    float* out = (float*)d_out;
    float* o_xout  = out;                    // [8,1024,1024]
    float* o_xnorm = out + 8388608;          // [8,1024,1024]
    float* o_xmod  = out + 16777216;         // [8,1024,1024]
    float* o_shift = out + 25165824;         // [8,1024]
    float* o_scale = out + 25174016;         // [8,1024]
    float* o_cmod  = out + 25182208;         // [8,6144]
    float* o_cact  = out + 25231360;         // [8,1024]

    float *p_x1;
    __nv_bfloat16 *p_qb, *p_kb, *p_vb, *p_xmb, *p_xm2b, *p_yb, *p_hb;
    __nv_bfloat16 *p_wqkvt, *p_wat, *p_f1t, *p_f2t;
    cudaGetSymbolAddress((void**)&p_x1,    g_x1);
    cudaGetSymbolAddress((void**)&p_qb,    g_qb);
    cudaGetSymbolAddress((void**)&p_kb,    g_kb);
    cudaGetSymbolAddress((void**)&p_vb,    g_vb);
    cudaGetSymbolAddress((void**)&p_xmb,   g_xmod_b);
    cudaGetSymbolAddress((void**)&p_xm2b,  g_xm2_b);
    cudaGetSymbolAddress((void**)&p_yb,    g_y_b);
    cudaGetSymbolAddress((void**)&p_hb,    g_h_b);
    cudaGetSymbolAddress((void**)&p_wqkvt, g_wqkvt);
    cudaGetSymbolAddress((void**)&p_wat,   g_wat);
    cudaGetSymbolAddress((void**)&p_f1t,   g_wfc1t);
    cudaGetSymbolAddress((void**)&p_f2t,   g_wfc2t);

    cudaFuncSetAttribute(flash_mma, cudaFuncAttributeMaxDynamicSharedMemorySize, 65536);
    cudaFuncSetAttribute(mma_gemm<EPI_QKV3>, cudaFuncAttributeMaxDynamicSharedMemorySize, GEMM_SMEM);
    cudaFuncSetAttribute(mma_gemm<EPI_GATE>, cudaFuncAttributeMaxDynamicSharedMemorySize, GEMM_SMEM);
    cudaFuncSetAttribute(mma_gemm<EPI_GELU>, cudaFuncAttributeMaxDynamicSharedMemorySize, GEMM_SMEM);

    // 0) merged prologue: mod-GEMM + all weight transposes, concurrent
    prologue_kernel<<<192 + 12288, 256>>>(
        c, w_mod, b_mod, o_cmod, o_shift, o_scale, o_cact,
        w_q, w_k, w_v, w_attn, w_fc1, w_fc2,
        p_wqkvt, p_wat, p_f1t, p_f2t);

    // 1) LN1 + modulate
    ln_mod_kernel<<<MTOK / 8, 256>>>(x, o_cmod, o_xnorm, o_xmod, p_xmb, 0, 1024);

    // 2) fused QKV projection -> bf16 (q scaled by log2(e)/64 for exp2 softmax)
    dim3 gQKV(3 * DD / 128, MTOK / 128);   // (24, 64)
    mma_gemm<EPI_QKV3><<<gQKV, 256, GEMM_SMEM>>>(p_xmb, p_wqkvt, b_q, nullptr, p_qb, DD, DD, QSCALE,
                                      nullptr, nullptr, 0, p_kb, p_vb, b_k, b_v);

    // 3) attention on tensor cores (Br=128, mq=2; 3 CTAs/SM; interleaved LDSM rings)
    flash_mma<<<dim3(SS / 128, 16, BB), 128, 65536>>>(p_qb, p_kb, p_vb, p_yb);

    // 4) attn projection + residual with gate_msa
    dim3 gD(DD / 128, MTOK / 128);     // (8, 64)
    mma_gemm<EPI_GATE><<<gD, 256, GEMM_SMEM>>>(p_yb, p_wat, b_attn, p_x1, nullptr, DD, DD, 1.f,
                                    x, o_cmod, 2048, nullptr, nullptr, nullptr, nullptr);

    // 5) LN2 + modulate (bf16 only)
    ln_mod_kernel<<<MTOK / 8, 256>>>(p_x1, o_cmod, nullptr, nullptr, p_xm2b, 3072, 4096);

    // 6) MLP on tensor cores
    dim3 gF(FF / 128, MTOK / 128);     // (32, 64)
    mma_gemm<EPI_GELU><<<gF, 256, GEMM_SMEM>>>(p_xm2b, p_f1t, b_fc1, nullptr, p_hb, DD, FF, 1.f,
                                    nullptr, nullptr, 0, nullptr, nullptr, nullptr, nullptr);
    mma_gemm<EPI_GATE><<<gD, 256, GEMM_SMEM>>>(p_hb, p_f2t, b_fc2, o_xout, nullptr, FF, DD, 1.f,
                                    p_x1, o_cmod, 5120, nullptr, nullptr, nullptr, nullptr);
}

// round 15
// speedup vs baseline: 1.1358x; 1.0035x over previous
#include <cuda_runtime.h>
#include <cuda_bf16.h>
#include <math.h>
#include <cstdint>

// Problem dims (fixed by the dataset)
#define BB 8
#define SS 1024
#define DD 1024
#define FF 4096
#define MTOK (BB*SS)       // 8192
#define CMOD_N (6*DD)      // 6144

#define QSCALE 0.022542110013890053f   // log2(e) / 64

// -------- scratch (device globals; no allocation allowed) --------
__device__ float g_x1 [MTOK * DD];

__device__ __nv_bfloat16 g_qb  [MTOK * DD];
__device__ __nv_bfloat16 g_kb  [MTOK * DD];
__device__ __nv_bfloat16 g_vb  [MTOK * DD];
__device__ __nv_bfloat16 g_xmod_b[MTOK * DD];
__device__ __nv_bfloat16 g_xm2_b [MTOK * DD];
__device__ __nv_bfloat16 g_y_b   [MTOK * DD];
__device__ __nv_bfloat16 g_h_b   [(size_t)MTOK * FF];
__device__ __nv_bfloat16 g_wqkvt[3 * DD * DD];
__device__ __nv_bfloat16 g_wat  [DD * DD];
__device__ __nv_bfloat16 g_wfc1t[(size_t)FF * DD];
__device__ __nv_bfloat16 g_wfc2t[(size_t)DD * FF];

// ===================== PTX helpers (baseline ISA only — no tcgen05) =====================
__device__ __forceinline__ uint32_t smem_u32(const void* p) {
    uint32_t a;
    asm("{ .reg .u64 t; cvta.to.shared.u64 t, %1; cvt.u32.u64 %0, t; }" : "=r"(a) : "l"(p));
    return a;
}
__device__ __forceinline__ void cp_async16(uint32_t dst, const void* src) {
    asm volatile("cp.async.cg.shared.global [%0], [%1], 16;" :: "r"(dst), "l"(src));
}
#define CP_COMMIT() asm volatile("cp.async.commit_group;" ::: "memory")
#define CP_WAIT(n)  asm volatile("cp.async.wait_group %0;" :: "n"(n) : "memory")

__device__ __forceinline__ void ldm4(uint32_t* r, uint32_t addr) {
    asm volatile("ldmatrix.sync.aligned.m8n8.x4.shared.b16 {%0,%1,%2,%3}, [%4];"
        : "=r"(r[0]), "=r"(r[1]), "=r"(r[2]), "=r"(r[3]) : "r"(addr));
}
__device__ __forceinline__ void ldm4t(uint32_t* r, uint32_t addr) {
    asm volatile("ldmatrix.sync.aligned.m8n8.x4.trans.shared.b16 {%0,%1,%2,%3}, [%4];"
        : "=r"(r[0]), "=r"(r[1]), "=r"(r[2]), "=r"(r[3]) : "r"(addr));
}
__device__ __forceinline__ void mma16816(float* c, const uint32_t* a, const uint32_t* b) {
    asm volatile(
        "mma.sync.aligned.m16n8k16.row.col.f32.bf16.bf16.f32 "
        "{%0,%1,%2,%3}, {%4,%5,%6,%7}, {%8,%9}, {%0,%1,%2,%3};"
        : "+f"(c[0]), "+f"(c[1]), "+f"(c[2]), "+f"(c[3])
        : "r"(a[0]), "r"(a[1]), "r"(a[2]), "r"(a[3]), "r"(b[0]), "r"(b[1]));
}
__device__ __forceinline__ uint32_t pack_bf16x2(float lo, float hi) {
    uint32_t r;
    asm("cvt.rn.bf16x2.f32 %0, %1, %2;" : "=r"(r) : "f"(hi), "f"(lo));  // first operand -> upper half
    return r;
}
__device__ __forceinline__ float fast_exp2(float x) {
    float r;
    asm("ex2.approx.ftz.f32 %0, %1;" : "=f"(r) : "f"(x));
    return r;
}
__device__ __forceinline__ void stcs_f2(float* p, float2 v) {
    asm volatile("st.global.cs.v2.f32 [%0], {%1, %2};" :: "l"(p), "f"(v.x), "f"(v.y));
}
__device__ __forceinline__ void stcs_f4(float* p, float4 v) {
    asm volatile("st.global.cs.v4.f32 [%0], {%1, %2, %3, %4};"
        :: "l"(p), "f"(v.x), "f"(v.y), "f"(v.z), "f"(v.w));
}

// ===================== mma.sync GEMM: C[M x N] = A[M x K](bf16) @ Wt[N x K]^T =====================
// BM=128, BN=128. 256 threads (8 warps, warp tile 32x64).
// 6-stage cp.async (3 pairs of BK=32 chunks); one barrier per 64 K-elems.
// Per h-chunk: all 4 A-fragments hoisted up front; single 8-deep B-ring spanning both ks
// (accumulation order unchanged: (ks, np) major order preserved).
enum { EPI_QKV3 = 0, EPI_GATE = 1, EPI_GELU = 2 };

#define CHUNK_BYTES 16384       // A 8KB + B 8KB per BK=32 chunk
#define PAIR_BYTES  32768
#define B_OFF 8192
#define GEMM_SMEM (3 * PAIR_BYTES)   // 96 KB

template <int EPI>
__global__ void __launch_bounds__(256) mma_gemm(
    const __nv_bfloat16* __restrict__ A, const __nv_bfloat16* __restrict__ Wt,
    const float* __restrict__ bias,
    float* __restrict__ outf, __nv_bfloat16* __restrict__ outb,
    int K, int N, float scale,
    const float* __restrict__ add_src, const float* __restrict__ cmod, int gate_off,
    __nv_bfloat16* __restrict__ outb2, __nv_bfloat16* __restrict__ outb3,
    const float* __restrict__ bias2, const float* __restrict__ bias3)
{
    extern __shared__ __align__(128) char smbuf[];   // 96 KB
    const uint32_t smb = smem_u32(smbuf);

    const int tid = threadIdx.x;
    const int lane = tid & 31, wid = tid >> 5;
    const int wm = wid & 3, wn = wid >> 2;      // 4 warps M x 2 warps N
    const int m0 = blockIdx.y * 128;
    const int n0 = blockIdx.x * 128;

    const int uA0 = tid, uA1 = tid + 256;
    const int rA0u = uA0 >> 2, gA0u = uA0 & 3;
    const int rA1u = uA1 >> 2, gA1u = uA1 & 3;
    const uint32_t dstA0 = (uint32_t)rA0u * 64u + (uint32_t)((gA0u ^ ((rA0u >> 1) & 3)) << 4);
    const uint32_t dstA1 = (uint32_t)rA1u * 64u + (uint32_t)((gA1u ^ ((rA1u >> 1) & 3)) << 4);
    const __nv_bfloat16* srcA0 = A + (size_t)(m0 + rA0u) * K + gA0u * 8;
    const __nv_bfloat16* srcA1 = A + (size_t)(m0 + rA1u) * K + gA1u * 8;
    const __nv_bfloat16* srcB0 = Wt + (size_t)(n0 + rA0u) * K + gA0u * 8;
    const __nv_bfloat16* srcB1 = Wt + (size_t)(n0 + rA1u) * K + gA1u * 8;

    const int npair = K >> 6;   // K / 64

    uint32_t aoff[2][2];   // [mt][ks]
    {
        int r = wm * 32 + (lane & 15);
        int sw = (r >> 1) & 3;
        #pragma unroll
        for (int mt = 0; mt < 2; mt++)
            #pragma unroll
            for (int ks = 0; ks < 2; ks++)
                aoff[mt][ks] = (uint32_t)(r + mt * 16) * 64u +
                               (uint32_t)(((ks * 2 + (lane >> 4)) ^ sw) << 4);
    }
    uint32_t boff[2][4];   // [ks][np]
    {
        int n = wn * 64 + ((lane >> 4) & 1) * 8 + (lane & 7);
        int gpar = (lane >> 3) & 1;
        int sw = (n >> 1) & 3;
        #pragma unroll
        for (int np = 0; np < 4; np++)
            #pragma unroll
            for (int ks = 0; ks < 2; ks++)
                boff[ks][np] = (uint32_t)B_OFF + (uint32_t)(n + np * 16) * 64u +
                               (uint32_t)(((ks * 2 + gpar) ^ sw) << 4);
    }

    // prologue: pairs 0,1 (chunks 0..3), one commit group per pair
    #pragma unroll
    for (int s = 0; s < 2; s++) {
        uint32_t base = smb + (uint32_t)s * PAIR_BYTES;
        #pragma unroll
        for (int h = 0; h < 2; h++) {
            uint32_t cb = base + (uint32_t)h * CHUNK_BYTES;
            int ch = 2 * s + h;
            cp_async16(cb + dstA0,         srcA0 + ch * 32);
            cp_async16(cb + dstA1,         srcA1 + ch * 32);
            cp_async16(cb + B_OFF + dstA0, srcB0 + ch * 32);
            cp_async16(cb + B_OFF + dstA1, srcB1 + ch * 32);
        }
        CP_COMMIT();
    }

    float c[2][8][4];
    #pragma unroll
    for (int mt = 0; mt < 2; mt++)
        #pragma unroll
        for (int nt = 0; nt < 8; nt++)
            #pragma unroll
            for (int e = 0; e < 4; e++) c[mt][nt][e] = 0.f;

    for (int p = 0; p < npair; p++) {
        CP_WAIT(1);
        __syncthreads();
        if (p + 2 < npair) {
            uint32_t base = smb + (uint32_t)((p + 2) % 3) * PAIR_BYTES;
            #pragma unroll
            for (int h = 0; h < 2; h++) {
                uint32_t cb = base + (uint32_t)h * CHUNK_BYTES;
                int ch = 2 * (p + 2) + h;
                cp_async16(cb + dstA0,         srcA0 + ch * 32);
                cp_async16(cb + dstA1,         srcA1 + ch * 32);
                cp_async16(cb + B_OFF + dstA0, srcB0 + ch * 32);
                cp_async16(cb + B_OFF + dstA1, srcB1 + ch * 32);
            }
        }
        CP_COMMIT();

        const uint32_t sp = smb + (uint32_t)(p % 3) * PAIR_BYTES;
        #pragma unroll
        for (int h = 0; h < 2; h++) {
            const uint32_t st = sp + (uint32_t)h * CHUNK_BYTES;
            // hoist all 4 A-fragments for this chunk (2 mt x 2 ks)
            uint32_t a[2][2][4];   // [ks][mt]
            ldm4(a[0][0], st + aoff[0][0]);
            ldm4(a[0][1], st + aoff[1][0]);
            ldm4(a[1][0], st + aoff[0][1]);
            ldm4(a[1][1], st + aoff[1][1]);
            // 2-deep B-fragment ring spanning both ks (8 iterations)
            uint32_t bc[2][4];
            ldm4(bc[0], st + boff[0][0]);
            #pragma unroll
            for (int ks = 0; ks < 2; ks++) {
                #pragma unroll
                for (int np = 0; np < 4; np++) {
                    const int idx = ks * 4 + np;
                    if (idx < 7) {
                        const int nks = (idx + 1) >> 2, nnp = (idx + 1) & 3;
                        ldm4(bc[(idx + 1) & 1], st + boff[nks][nnp]);
                    }
                    const uint32_t* br = bc[idx & 1];
                    mma16816(c[0][2 * np],     a[ks][0], &br[0]);
                    mma16816(c[1][2 * np],     a[ks][1], &br[0]);
                    mma16816(c[0][2 * np + 1], a[ks][0], &br[2]);
                    mma16816(c[1][2 * np + 1], a[ks][1], &br[2]);
                }
            }
        }
    }

    // ---- epilogue ----
    __nv_bfloat16* qdst = nullptr;
    const float* bsel = bias;
    float scl = scale;
    if (EPI == EPI_QKV3) {
        int buf = n0 >> 10;
        qdst = (buf == 0) ? outb : (buf == 1) ? outb2 : outb3;
        bsel = (buf == 0) ? bias : (buf == 1) ? bias2 : bias3;
        scl  = (buf == 0) ? scale : 1.f;
    }
    const int lcol0 = n0 & 1023;

    #pragma unroll
    for (int mt = 0; mt < 2; mt++) {
        #pragma unroll
        for (int half = 0; half < 2; half++) {
            const int grow = m0 + wm * 32 + mt * 16 + (lane >> 2) + half * 8;
            const int b = grow >> 10;
            #pragma unroll
            for (int nt = 0; nt < 8; nt++) {
                const int coff = wn * 64 + nt * 8 + (lane & 3) * 2;
                if (EPI == EPI_QKV3) {
                    const int lcol = lcol0 + coff;
                    float v0 = (c[mt][nt][half * 2 + 0] + bsel[lcol]) * scl;
                    float v1 = (c[mt][nt][half * 2 + 1] + bsel[lcol + 1]) * scl;
                    __nv_bfloat162 pr;
                    pr.x = __float2bfloat16(v0);
                    pr.y = __float2bfloat16(v1);
                    *(__nv_bfloat162*)&qdst[(size_t)grow * DD + lcol] = pr;
                } else if (EPI == EPI_GATE) {
                    const int gcol = n0 + coff;
                    float v0 = c[mt][nt][half * 2 + 0] + bias[gcol];
                    float v1 = c[mt][nt][half * 2 + 1] + bias[gcol + 1];
                    const float* gp = cmod + b * CMOD_N + gate_off + gcol;
                    const float* ap = add_src + (size_t)grow * N + gcol;
                    float2 o = { ap[0] + gp[0] * v0, ap[1] + gp[1] * v1 };
                    if (gate_off == 5120)   // final x_out: write-only -> streaming store
                        stcs_f2(&outf[(size_t)grow * N + gcol], o);
                    else
                        *(float2*)&outf[(size_t)grow * N + gcol] = o;
                } else {   // EPI_GELU -> bf16
                    const int gcol = n0 + coff;
                    float v0 = c[mt][nt][half * 2 + 0] + bias[gcol];
                    float v1 = c[mt][nt][half * 2 + 1] + bias[gcol + 1];
                    float g0 = 0.5f * v0 * (1.f + erff(v0 * 0.70710678118654752f));
                    float g1 = 0.5f * v1 * (1.f + erff(v1 * 0.70710678118654752f));
                    __nv_bfloat162 pr;
                    pr.x = __float2bfloat16(g0);
                    pr.y = __float2bfloat16(g1);
                    *(__nv_bfloat162*)&outb[(size_t)grow * N + gcol] = pr;
                }
            }
        }
    }
}

// ===================== Flash attention on mma.sync (bf16 in/out, fixed-base exp2 softmax) =====================
// Br=128, Bc=64, Dh=64. 128 threads = 4 warps, each owning 32 q-rows (mq=2).
// __launch_bounds__(128, 3): 3 CTAs/SM. K and V inner loops use 2-deep ldmatrix/MMA rings.
__global__ void __launch_bounds__(128, 3) flash_mma(
    const __nv_bfloat16* __restrict__ Q, const __nv_bfloat16* __restrict__ K,
    const __nv_bfloat16* __restrict__ V, __nv_bfloat16* __restrict__ Y)
{
    extern __shared__ __align__(128) char smbuf[];   // Q 16KB + 3 x (K 8KB + V 8KB) = 64KB
    const uint32_t Qb  = smem_u32(smbuf);
    const uint32_t KVb = Qb + 16384;

    const int tid = threadIdx.x, lane = tid & 31, w = tid >> 5;
    const int qt = blockIdx.x, h = blockIdx.y, b = blockIdx.z;
    const size_t gbase = ((size_t)b * SS) * DD + h * 64;
    const int t0q = qt * 128;

    // --- Q load (16KB = 1024 x 16B units, 8/thread) ---
    #pragma unroll
    for (int i = 0; i < 8; i++) {
        int u = tid + i * 128;
        int r = u >> 3, g = u & 7;
        cp_async16(Qb + r * 128 + ((g ^ (r & 7)) << 4),
                   Q + gbase + (size_t)(t0q + r) * DD + g * 8);
    }
    // --- KV tile loader: per operand 512 units, 4/thread ---
    int kvr[4], kvg[4];
    uint32_t kvd[4];
    #pragma unroll
    for (int i = 0; i < 4; i++) {
        int u = tid + i * 128;
        kvr[i] = u >> 3; kvg[i] = u & 7;
        kvd[i] = (uint32_t)kvr[i] * 128u + (uint32_t)((kvg[i] ^ (kvr[i] & 7)) << 4);
    }

    #pragma unroll
    for (int s = 0; s < 2; s++) {   // tiles 0,1 -> stages 0,1 (tile 0 shares group with Q)
        uint32_t base = KVb + (uint32_t)s * 16384u;
        #pragma unroll
        for (int i = 0; i < 4; i++) {
            cp_async16(base + kvd[i],        K + gbase + (size_t)(s * 64 + kvr[i]) * DD + kvg[i] * 8);
            cp_async16(base + 8192 + kvd[i], V + gbase + (size_t)(s * 64 + kvr[i]) * DD + kvg[i] * 8);
        }
        CP_COMMIT();
    }

    uint32_t qa[2][4][4];
    float O[2][8][4];
    #pragma unroll
    for (int mq = 0; mq < 2; mq++)
        #pragma unroll
        for (int nb = 0; nb < 8; nb++)
            #pragma unroll
            for (int e = 0; e < 4; e++) O[mq][nb][e] = 0.f;
    float lp[2][2] = { {0.f, 0.f}, {0.f, 0.f} };

    for (int t = 0; t < 16; t++) {
        CP_WAIT(1);
        __syncthreads();   // data visibility for tile t AND orders compute(t-1) before prefetch below
        if (t + 2 < 16) {
            uint32_t base = KVb + (uint32_t)((t + 2) % 3) * 16384u;
            const int t0k = (t + 2) * 64;
            #pragma unroll
            for (int i = 0; i < 4; i++) {
                cp_async16(base + kvd[i],        K + gbase + (size_t)(t0k + kvr[i]) * DD + kvg[i] * 8);
                cp_async16(base + 8192 + kvd[i], V + gbase + (size_t)(t0k + kvr[i]) * DD + kvg[i] * 8);
            }
        }
        CP_COMMIT();

        if (t == 0) {
            #pragma unroll
            for (int mq = 0; mq < 2; mq++)
                #pragma unroll
                for (int kc = 0; kc < 4; kc++) {
                    int r = w * 32 + mq * 16 + (lane & 15);
                    int g = (kc * 2 + (lane >> 4)) ^ (r & 7);
                    ldm4(qa[mq][kc], Qb + r * 128 + (g << 4));
                }
        }
        const uint32_t Kb = KVb + (uint32_t)(t % 3) * 16384u;
        const uint32_t Vb = Kb + 8192u;

        // ---- S = Q @ K^T: 2-deep K-fragment ring over the 16 (kc,ng) loads ----
        float sc[2][8][4];
        #pragma unroll
        for (int mq = 0; mq < 2; mq++)
            #pragma unroll
            for (int nb = 0; nb < 8; nb++)
                #pragma unroll
                for (int e = 0; e < 4; e++) sc[mq][nb][e] = 0.f;
        {
            const int nbase = ((lane >> 4) & 1) * 8 + (lane & 7);
            const int gpar = (lane >> 3) & 1;
            uint32_t kf[2][4];
            {
                int n = nbase;
                int g = (0 + gpar) ^ (n & 7);
                ldm4(kf[0], Kb + n * 128 + (g << 4));
            }
            #pragma unroll
            for (int kc = 0; kc < 4; kc++) {
                #pragma unroll
                for (int ng = 0; ng < 4; ng++) {
                    const int idx = kc * 4 + ng;
                    if (idx < 15) {
                        const int nkc = (idx + 1) >> 2, nng = (idx + 1) & 3;
                        int n = nng * 16 + nbase;
                        int g = (nkc * 2 + gpar) ^ (n & 7);
                        ldm4(kf[(idx + 1) & 1], Kb + n * 128 + (g << 4));
                    }
                    const uint32_t* kb = kf[idx & 1];
                    #pragma unroll
                    for (int mq = 0; mq < 2; mq++) {
                        mma16816(sc[mq][2 * ng],     qa[mq][kc], &kb[0]);
                        mma16816(sc[mq][2 * ng + 1], qa[mq][kc], &kb[2]);
                    }
                }
            }
        }

        // ---- fixed-base softmax: P = exp2(S), partial row sums only ----
        uint32_t pa[2][4][4];
        #pragma unroll
        for (int mq = 0; mq < 2; mq++)
            #pragma unroll
            for (int ng = 0; ng < 4; ng++) {
                float e00 = fast_exp2(sc[mq][2 * ng][0]),     e01 = fast_exp2(sc[mq][2 * ng][1]);
                float e02 = fast_exp2(sc[mq][2 * ng][2]),     e03 = fast_exp2(sc[mq][2 * ng][3]);
                float e10 = fast_exp2(sc[mq][2 * ng + 1][0]), e11 = fast_exp2(sc[mq][2 * ng + 1][1]);
                float e12 = fast_exp2(sc[mq][2 * ng + 1][2]), e13 = fast_exp2(sc[mq][2 * ng + 1][3]);
                lp[mq][0] += e00 + e01 + e10 + e11;
                lp[mq][1] += e02 + e03 + e12 + e13;
                pa[mq][ng][0] = pack_bf16x2(e00, e01);
                pa[mq][ng][1] = pack_bf16x2(e02, e03);
                pa[mq][ng][2] = pack_bf16x2(e10, e11);
                pa[mq][ng][3] = pack_bf16x2(e12, e13);
            }

        // ---- O += P @ V: 2-deep V-fragment ring over the 16 (kc,ng) loads ----
        {
            const int rbase = lane & 15;
            const int gsel = lane >> 4;
            uint32_t vf[2][4];
            {
                int r = rbase;
                int g = (0 * 2 + gsel) ^ (r & 7);
                ldm4t(vf[0], Vb + r * 128 + (g << 4));
            }
            #pragma unroll
            for (int kc = 0; kc < 4; kc++) {
                #pragma unroll
                for (int ng = 0; ng < 4; ng++) {
                    const int idx = kc * 4 + ng;
                    if (idx < 15) {
                        const int nkc = (idx + 1) >> 2, nng = (idx + 1) & 3;
                        int r = nkc * 16 + rbase;
                        int g = (nng * 2 + gsel) ^ (r & 7);
                        ldm4t(vf[(idx + 1) & 1], Vb + r * 128 + (g << 4));
                    }
                    const uint32_t* vb = vf[idx & 1];
                    #pragma unroll
                    for (int mq = 0; mq < 2; mq++) {
                        mma16816(O[mq][2 * ng],     pa[mq][kc], &vb[0]);
                        mma16816(O[mq][2 * ng + 1], pa[mq][kc], &vb[2]);
                    }
                }
            }
        }
        // no trailing barrier: next iteration's top barrier orders compute(t) vs prefetch(t+3)
    }

    // ---- single end-of-loop l reduction + store ----
    #pragma unroll
    for (int mq = 0; mq < 2; mq++) {
        float l0 = lp[mq][0], l1 = lp[mq][1];
        l0 += __shfl_xor_sync(0xffffffffu, l0, 1);
        l0 += __shfl_xor_sync(0xffffffffu, l0, 2);
        l1 += __shfl_xor_sync(0xffffffffu, l1, 1);
        l1 += __shfl_xor_sync(0xffffffffu, l1, 2);
        float inv0 = 1.f / l0, inv1 = 1.f / l1;
        const int r0 = t0q + w * 32 + mq * 16 + (lane >> 2);
        #pragma unroll
        for (int nb = 0; nb < 8; nb++) {
            const int d = nb * 8 + (lane & 3) * 2;
            __nv_bfloat162 p0, p1;
            p0.x = __float2bfloat16(O[mq][nb][0] * inv0);
            p0.y = __float2bfloat16(O[mq][nb][1] * inv0);
            p1.x = __float2bfloat16(O[mq][nb][2] * inv1);
            p1.y = __float2bfloat16(O[mq][nb][3] * inv1);
            *(__nv_bfloat162*)&Y[gbase + (size_t)r0 * DD + d]       = p0;
            *(__nv_bfloat162*)&Y[gbase + (size_t)(r0 + 8) * DD + d] = p1;
        }
    }
}

// ===================== merged prologue: mod-GEMM (blocks 0..191) + all transposes (192..12479) =====================
__global__ void __launch_bounds__(256) prologue_kernel(
    const float* __restrict__ c, const float* __restrict__ w_mod,
    const float* __restrict__ b_mod, float* __restrict__ cmod,
    float* __restrict__ o_shift, float* __restrict__ o_scale, float* __restrict__ o_cact,
    const float* __restrict__ wq, const float* __restrict__ wk, const float* __restrict__ wv,
    const float* __restrict__ wattn, const float* __restrict__ wfc1, const float* __restrict__ wfc2,
    __nv_bfloat16* __restrict__ qkvt, __nv_bfloat16* __restrict__ wat,
    __nv_bfloat16* __restrict__ f1t, __nv_bfloat16* __restrict__ f2t)
{
    __shared__ __align__(16) char smu[40960];    // union: mod 40KB | transpose 4.2KB
    const int bid = blockIdx.x;
    const int tid = threadIdx.x;

    if (bid < 192) {
        // ---- cmod = silu(c) @ w_mod + b_mod ----
        float* sc = (float*)smu;                               // 32 KB
        float (*red)[32][8] = (float(*)[32][8])(smu + 32768);  // 8 KB
        for (int i = tid; i < BB * DD; i += 256) {
            float v = c[i];
            float sv = v / (1.f + expf(-v));
            sc[i] = sv;
            if (bid == 0) o_cact[i] = sv;
        }
        __syncthreads();

        int jl = tid & 31, ks = tid >> 5;
        int j = bid * 32 + jl;
        float acc[BB];
        #pragma unroll
        for (int b = 0; b < BB; b++) acc[b] = 0.f;

        int d0 = ks * 128;
        #pragma unroll 4
        for (int dd = 0; dd < 128; dd++) {
            int d = d0 + dd;
            float w = w_mod[(size_t)d * CMOD_N + j];
            #pragma unroll
            for (int b = 0; b < BB; b++) acc[b] = fmaf(sc[b * DD + d], w, acc[b]);
        }
        #pragma unroll
        for (int b = 0; b < BB; b++) red[ks][jl][b] = acc[b];
        __syncthreads();

        int b = ks;
        float s = 0.f;
        #pragma unroll
        for (int kk = 0; kk < 8; kk++) s += red[kk][jl][b];
        float v = s + b_mod[j];
        cmod[b * CMOD_N + j] = v;
        if (j < 1024)            o_shift[b * DD + j] = v;
        else if (j < 2048)       o_scale[b * DD + (j - 1024)] = v;
        return;
    }

    // ---- weight transposes ----
    float (*t)[33] = (float(*)[33])smu;
    int id = bid - 192;
    const float* W; __nv_bfloat16* Wt;
    int n0, k0, Nsrc, Kdst;
    if (id < 3072) {               // qkv: 96 n-tiles x 32 k-tiles
        int tx2 = id % 96, ty2 = id / 96;
        n0 = tx2 * 32; k0 = ty2 * 32;
        int buf = n0 >> 10;
        W = (buf == 0) ? wq : (buf == 1) ? wk : wv;
        Wt = qkvt;  Nsrc = DD; Kdst = DD;
        int nl0 = n0 & 1023;
        int txi = tid & 31, tyi = tid >> 5;
        #pragma unroll
        for (int r = tyi; r < 32; r += 8)
            t[r][txi] = W[(size_t)(k0 + r) * Nsrc + nl0 + txi];
        __syncthreads();
        #pragma unroll
        for (int r = tyi; r < 32; r += 8)
            Wt[(size_t)(n0 + r) * Kdst + k0 + txi] = __float2bfloat16(t[txi][r]);
        return;
    } else if (id < 4096) {        // w_attn: 32 x 32
        int lid2 = id - 3072;
        n0 = (lid2 % 32) * 32; k0 = (lid2 / 32) * 32;
        W = wattn; Wt = wat; Nsrc = DD; Kdst = DD;
    } else if (id < 8192) {        // fc1: [K=1024, N=4096] -> f1t[4096,1024]: 128 x 32
        int lid2 = id - 4096;
        n0 = (lid2 % 128) * 32; k0 = (lid2 / 128) * 32;
        W = wfc1; Wt = f1t; Nsrc = FF; Kdst = DD;
    } else {                       // fc2: [K=4096, N=1024] -> f2t[1024,4096]: 32 x 128
        int lid2 = id - 8192;
        n0 = (lid2 % 32) * 32; k0 = (lid2 / 32) * 32;
        W = wfc2; Wt = f2t; Nsrc = DD; Kdst = FF;
    }
    int txi = tid & 31, tyi = tid >> 5;
    #pragma unroll
    for (int r = tyi; r < 32; r += 8)
        t[r][txi] = W[(size_t)(k0 + r) * Nsrc + n0 + txi];
    __syncthreads();
    #pragma unroll
    for (int r = tyi; r < 32; r += 8)
        Wt[(size_t)(n0 + r) * Kdst + k0 + txi] = __float2bfloat16(t[txi][r]);
}

// ---------------- LayerNorm + modulate (warp-per-row; no block barriers, no smem) ----------------
__global__ void __launch_bounds__(256) ln_mod_kernel(
    const float* __restrict__ x, const float* __restrict__ cmod,
    float* __restrict__ xnorm, float* __restrict__ xmod, __nv_bfloat16* __restrict__ xmod_b,
    int shift_off, int scale_off)
{
    const int row = blockIdx.x * 8 + (threadIdx.x >> 5);
    const int lane = threadIdx.x & 31;
    const int b = row >> 10;
    const float4* xr = (const float4*)(x + (size_t)row * DD);

    float4 v[8];
    float s = 0.f;
    #pragma unroll
    for (int i = 0; i < 8; i++) {
        v[i] = xr[lane + i * 32];
        s += v[i].x + v[i].y + v[i].z + v[i].w;
    }
    #pragma unroll
    for (int o = 16; o > 0; o >>= 1) s += __shfl_xor_sync(0xffffffffu, s, o);
    const float mu = s * (1.f / DD);

    float s2 = 0.f;
    #pragma unroll
    for (int i = 0; i < 8; i++) {
        float d0 = v[i].x - mu, d1 = v[i].y - mu, d2 = v[i].z - mu, d3 = v[i].w - mu;
        s2 += d0 * d0 + d1 * d1 + d2 * d2 + d3 * d3;
    }
    #pragma unroll
    for (int o = 16; o > 0; o >>= 1) s2 += __shfl_xor_sync(0xffffffffu, s2, o);
    const float rstd = rsqrtf(s2 * (1.f / DD) + 1e-6f);

    const float4* shp = (const float4*)(cmod + b * CMOD_N + shift_off);
    const float4* slp = (const float4*)(cmod + b * CMOD_N + scale_off);
    #pragma unroll
    for (int i = 0; i < 8; i++) {
        const int idx = lane + i * 32;
        const float4 sh = shp[idx], sl = slp[idx];
        float4 xn = { (v[i].x - mu) * rstd, (v[i].y - mu) * rstd,
                      (v[i].z - mu) * rstd, (v[i].w - mu) * rstd };
        float4 xm = { xn.x * (1.f + sl.x) + sh.x, xn.y * (1.f + sl.y) + sh.y,
                      xn.z * (1.f + sl.z) + sh.z, xn.w * (1.f + sl.w) + sh.w };
        if (xnorm) stcs_f4(xnorm + (size_t)row * DD + idx * 4, xn);
        if (xmod)  stcs_f4(xmod  + (size_t)row * DD + idx * 4, xm);
        uint2 p = { pack_bf16x2(xm.x, xm.y), pack_bf16x2(xm.z, xm.w) };
        ((uint2*)(xmod_b + (size_t)row * DD))[idx] = p;
    }
}

// ---------------- launch ----------------
extern "C" void kernel_launch(void* const* d_in, const int* in_sizes, int n_in,
                              void* d_out, int out_size)
{
    const float* x      = (const float*)d_in[0];
    const float* c      = (const float*)d_in[1];
    const float* w_mod  = (const float*)d_in[2];
    const float* b_mod  = (const float*)d_in[3];
    const float* w_q    = (const float*)d_in[4];
    const float* b_q    = (const float*)d_in[5];
    const float* w_k    = (const float*)d_in[6];
    const float* b_k    = (const float*)d_in[7];
    const float* w_v    = (const float*)d_in[8];
    const float* b_v    = (const float*)d_in[9];
    const float* w_attn = (const float*)d_in[10];
    const float* b_attn = (const float*)d_in[11];
    const float* w_fc1  = (const float*)d_in[12];
    const float* b_fc1  = (const float*)d_in[13];
    const float* w_fc2  = (const float*)d_in[14];
    const float* b_fc2  = (const float*)d_in[15];

    float* out = (float*)d_out;
    float* o_xout  = out;                    // [8,1024,1024]
    float* o_xnorm = out + 8388608;          // [8,1024,1024]
    float* o_xmod  = out + 16777216;         // [8,1024,1024]
    float* o_shift = out + 25165824;         // [8,1024]
    float* o_scale = out + 25174016;         // [8,1024]
    float* o_cmod  = out + 25182208;         // [8,6144]
    float* o_cact  = out + 25231360;         // [8,1024]

    float *p_x1;
    __nv_bfloat16 *p_qb, *p_kb, *p_vb, *p_xmb, *p_xm2b, *p_yb, *p_hb;
    __nv_bfloat16 *p_wqkvt, *p_wat, *p_f1t, *p_f2t;
    cudaGetSymbolAddress((void**)&p_x1,    g_x1);
    cudaGetSymbolAddress((void**)&p_qb,    g_qb);
    cudaGetSymbolAddress((void**)&p_kb,    g_kb);
    cudaGetSymbolAddress((void**)&p_vb,    g_vb);
    cudaGetSymbolAddress((void**)&p_xmb,   g_xmod_b);
    cudaGetSymbolAddress((void**)&p_xm2b,  g_xm2_b);
    cudaGetSymbolAddress((void**)&p_yb,    g_y_b);
    cudaGetSymbolAddress((void**)&p_hb,    g_h_b);
    cudaGetSymbolAddress((void**)&p_wqkvt, g_wqkvt);
    cudaGetSymbolAddress((void**)&p_wat,   g_wat);
    cudaGetSymbolAddress((void**)&p_f1t,   g_wfc1t);
    cudaGetSymbolAddress((void**)&p_f2t,   g_wfc2t);

    cudaFuncSetAttribute(flash_mma, cudaFuncAttributeMaxDynamicSharedMemorySize, 65536);
    cudaFuncSetAttribute(mma_gemm<EPI_QKV3>, cudaFuncAttributeMaxDynamicSharedMemorySize, GEMM_SMEM);
    cudaFuncSetAttribute(mma_gemm<EPI_GATE>, cudaFuncAttributeMaxDynamicSharedMemorySize, GEMM_SMEM);
    cudaFuncSetAttribute(mma_gemm<EPI_GELU>, cudaFuncAttributeMaxDynamicSharedMemorySize, GEMM_SMEM);

    // 0) merged prologue: mod-GEMM + all weight transposes, concurrent
    prologue_kernel<<<192 + 12288, 256>>>(
        c, w_mod, b_mod, o_cmod, o_shift, o_scale, o_cact,
        w_q, w_k, w_v, w_attn, w_fc1, w_fc2,
        p_wqkvt, p_wat, p_f1t, p_f2t);

    // 1) LN1 + modulate
    ln_mod_kernel<<<MTOK / 8, 256>>>(x, o_cmod, o_xnorm, o_xmod, p_xmb, 0, 1024);

    // 2) fused QKV projection -> bf16 (q scaled by log2(e)/64 for exp2 softmax)
    dim3 gQKV(3 * DD / 128, MTOK / 128);   // (24, 64)
    mma_gemm<EPI_QKV3><<<gQKV, 256, GEMM_SMEM>>>(p_xmb, p_wqkvt, b_q, nullptr, p_qb, DD, DD, QSCALE,
                                      nullptr, nullptr, 0, p_kb, p_vb, b_k, b_v);

    // 3) attention on tensor cores (Br=128, mq=2; 3 CTAs/SM; interleaved LDSM rings)
    flash_mma<<<dim3(SS / 128, 16, BB), 128, 65536>>>(p_qb, p_kb, p_vb, p_yb);

    // 4) attn projection + residual with gate_msa
    dim3 gD(DD / 128, MTOK / 128);     // (8, 64)
    mma_gemm<EPI_GATE><<<gD, 256, GEMM_SMEM>>>(p_yb, p_wat, b_attn, p_x1, nullptr, DD, DD, 1.f,
                                    x, o_cmod, 2048, nullptr, nullptr, nullptr, nullptr);

    // 5) LN2 + modulate (bf16 only)
    ln_mod_kernel<<<MTOK / 8, 256>>>(p_x1, o_cmod, nullptr, nullptr, p_xm2b, 3072, 4096);

    // 6) MLP on tensor cores
    dim3 gF(FF / 128, MTOK / 128);     // (32, 64)
    mma_gemm<EPI_GELU><<<gF, 256, GEMM_SMEM>>>(p_xm2b, p_f1t, b_fc1, nullptr, p_hb, DD, FF, 1.f,
                                    nullptr, nullptr, 0, nullptr, nullptr, nullptr, nullptr);
    mma_gemm<EPI_GATE><<<gD, 256, GEMM_SMEM>>>(p_hb, p_f2t, b_fc2, o_xout, nullptr, FF, DD, 1.f,
                                    p_x1, o_cmod, 5120, nullptr, nullptr, nullptr, nullptr);
}